// round 5
// baseline (speedup 1.0000x reference)
#include <cuda_runtime.h>
#include <math.h>
#include <stdint.h>

// Problem constants
#define BD 4
#define ND 2048
#define CD 256
#define INNER 1024
#define ROWS (BD*ND)          // 8192
#define EPS 1e-5f
#define ATT_SCALE 0.125f      // 64^-0.5

// ---------------- scratch (device globals; allocation-free rule) -------------
__device__ float g_qn[ROWS*CD];
__device__ float g_kn[ROWS*CD];
__device__ float g_vn[ROWS*CD];
__device__ float g_qp[ROWS*INNER];
__device__ float g_kp[ROWS*INNER];
__device__ float g_vp[ROWS*INNER];
__device__ float g_vpt[ROWS*INNER];            // vp^T per batch [INNER, ND]
__device__ float g_attn[(long long)BD*ND*ND];  // 64 MB
__device__ float g_x[ROWS*INNER];
__device__ float g_wqt[INNER*CD];              // Wq^T [1024,256] (tf32)
__device__ float g_wkt[INNER*CD];
__device__ float g_wvt[INNER*CD];
__device__ float g_wot[CD*INNER];              // Wo^T [256,1024] (tf32)

// ---------------- helpers ----------------
__device__ __forceinline__ float warp_sum(float v) {
    #pragma unroll
    for (int o = 16; o; o >>= 1) v += __shfl_xor_sync(0xffffffffu, v, o);
    return v;
}
__device__ __forceinline__ float warp_max(float v) {
    #pragma unroll
    for (int o = 16; o; o >>= 1) v = fmaxf(v, __shfl_xor_sync(0xffffffffu, v, o));
    return v;
}
__device__ __forceinline__ float block_sum256(float v, float* shm) {
    v = warp_sum(v);
    int w = threadIdx.x >> 5;
    if ((threadIdx.x & 31) == 0) shm[w] = v;
    __syncthreads();
    if (threadIdx.x == 0) {
        float s = 0.f;
        #pragma unroll
        for (int i = 0; i < 8; i++) s += shm[i];
        shm[8] = s;
    }
    __syncthreads();
    float r = shm[8];
    __syncthreads();
    return r;
}
__device__ __forceinline__ float block_max256(float v, float* shm) {
    v = warp_max(v);
    int w = threadIdx.x >> 5;
    if ((threadIdx.x & 31) == 0) shm[w] = v;
    __syncthreads();
    if (threadIdx.x == 0) {
        float m = shm[0];
        #pragma unroll
        for (int i = 1; i < 8; i++) m = fmaxf(m, shm[i]);
        shm[8] = m;
    }
    __syncthreads();
    float r = shm[8];
    __syncthreads();
    return r;
}

__device__ __forceinline__ float f2tf(float f) {
    unsigned r;
    asm("cvt.rna.tf32.f32 %0, %1;" : "=r"(r) : "f"(f));
    return __uint_as_float(r);
}

__device__ __forceinline__ void mma_tf32(float* c, const unsigned* a, const unsigned* b) {
    asm volatile(
        "mma.sync.aligned.m16n8k8.row.col.f32.tf32.tf32.f32 "
        "{%0,%1,%2,%3}, {%4,%5,%6,%7}, {%8,%9}, {%0,%1,%2,%3};"
        : "+f"(c[0]), "+f"(c[1]), "+f"(c[2]), "+f"(c[3])
        : "r"(a[0]), "r"(a[1]), "r"(a[2]), "r"(a[3]), "r"(b[0]), "r"(b[1]));
}

// ---------------- LayerNorm (writes tf32-rounded) ---------------------------
__global__ void ln_kernel(const float* __restrict__ q, const float* __restrict__ k,
                          const float* __restrict__ v, const float* __restrict__ g,
                          const float* __restrict__ b) {
    __shared__ float shm[9];
    const float* src;
    float* dst;
    int which = blockIdx.y;
    long long off = (long long)blockIdx.x * CD;
    if (which == 0)      { src = q + off; dst = g_qn + off; }
    else if (which == 1) { src = k + off; dst = g_kn + off; }
    else                 { src = v + off; dst = g_vn + off; }
    int t = threadIdx.x;
    float x = src[t];
    float mean = block_sum256(x, shm) * (1.0f / CD);
    float d = x - mean;
    float var = block_sum256(d * d, shm) * (1.0f / CD);
    float inv = rsqrtf(var + EPS);
    dst[t] = f2tf(d * inv * g[t] + b[t]);
}

// ---------------- rounding transpose: dst[C,R] = tf32(src[R,C]^T) -----------
__global__ void transpose_kernel(const float* __restrict__ src, float* __restrict__ dst,
                                 int R, int C, long long sstride, long long dstride) {
    __shared__ float tile[32][33];
    src += (long long)blockIdx.z * sstride;
    dst += (long long)blockIdx.z * dstride;
    int tx = threadIdx.x, ty = threadIdx.y;
    int c0 = blockIdx.x * 32, r0 = blockIdx.y * 32;
    #pragma unroll
    for (int j = 0; j < 4; j++)
        tile[ty + 8 * j][tx] = f2tf(src[(long long)(r0 + ty + 8 * j) * C + c0 + tx]);
    __syncthreads();
    #pragma unroll
    for (int j = 0; j < 4; j++)
        dst[(long long)(c0 + ty + 8 * j) * R + r0 + tx] = tile[tx][ty + 8 * j];
}

// ---------------- tf32 tensor-core GEMM (NT only, pair-permuted smem) -------
// C[M,Ntot] = alpha * A[M,K] @ B[Ntot,K]^T (+ bias).
// A, B both row-major K-major, values pre-rounded to tf32.
// Block tile 128x128x32, 8 warps (4Mx2N), warp tile 32x64, mma m16n8k8.
// Smem layout: rows of 32 k-values stored as 4 groups of 8 with permutation
// p(k)=2*(k%4)+(k/4)  ->  (tg, tg+4) adjacent => 64-bit fragment LDS.
#define RS 40   // row stride in floats (conflict-free for LDS.64)

__device__ __forceinline__ void fill_pair(float* __restrict__ s, const float* __restrict__ g,
                                          long long row0, int ldk, int k0, int tid) {
    #pragma unroll
    for (int i = 0; i < 4; i++) {
        int idx = i * 256 + tid;
        int r  = idx >> 3;
        int c4 = (idx & 7) << 2;          // 0,4,...,28
        float4 v = *reinterpret_cast<const float4*>(g + (row0 + r) * (long long)ldk + k0 + c4);
        int grp = c4 >> 3;                // 0..3 (8-wide k group)
        int gam = (c4 >> 2) & 1;          // 0: k%8<4, 1: k%8>=4
        float* base = s + r * RS + grp * 8 + gam;
        base[0] = v.x; base[2] = v.y; base[4] = v.z; base[6] = v.w;
    }
}

template<bool HAS_BIAS, bool ROUND_OUT>
__global__ __launch_bounds__(256)
void mma_gemm(const float* __restrict__ A, const float* __restrict__ B,
              const float* __restrict__ bias, float* __restrict__ Cout,
              int Ntot, int K, float alpha,
              long long strideA, long long strideB, long long strideC) {
    __shared__ float As[128 * RS];
    __shared__ float Bs[128 * RS];

    A    += (long long)blockIdx.z * strideA;
    B    += (long long)blockIdx.z * strideB;
    Cout += (long long)blockIdx.z * strideC;

    const int tid  = threadIdx.x;
    const int lane = tid & 31;
    const int w    = tid >> 5;
    const int g    = lane >> 2;            // 0..7
    const int tg   = lane & 3;             // 0..3
    const int warpM = (w >> 1) * 32;
    const int warpN = (w & 1) * 64;
    const long long bm = (long long)blockIdx.y * 128;
    const long long bn = (long long)blockIdx.x * 128;

    float acc[2][8][4];
    #pragma unroll
    for (int i = 0; i < 2; i++)
        #pragma unroll
        for (int j = 0; j < 8; j++)
            #pragma unroll
            for (int q_ = 0; q_ < 4; q_++) acc[i][j][q_] = 0.f;

    for (int k0 = 0; k0 < K; k0 += 32) {
        fill_pair(As, A, bm, K, k0, tid);
        fill_pair(Bs, B, bn, K, k0, tid);
        __syncthreads();

        #pragma unroll
        for (int ks = 0; ks < 4; ks++) {
            const int kb2 = ks * 8 + 2 * tg;
            unsigned af[2][4];
            #pragma unroll
            for (int mt = 0; mt < 2; mt++) {
                int m = warpM + mt * 16;
                float2 x0 = *reinterpret_cast<const float2*>(&As[(m + g)     * RS + kb2]);
                float2 x1 = *reinterpret_cast<const float2*>(&As[(m + g + 8) * RS + kb2]);
                af[mt][0] = __float_as_uint(x0.x);
                af[mt][1] = __float_as_uint(x1.x);
                af[mt][2] = __float_as_uint(x0.y);
                af[mt][3] = __float_as_uint(x1.y);
            }
            unsigned bf[8][2];
            #pragma unroll
            for (int nt = 0; nt < 8; nt++) {
                int n = warpN + nt * 8 + g;
                float2 y = *reinterpret_cast<const float2*>(&Bs[n * RS + kb2]);
                bf[nt][0] = __float_as_uint(y.x);
                bf[nt][1] = __float_as_uint(y.y);
            }
            #pragma unroll
            for (int mt = 0; mt < 2; mt++)
                #pragma unroll
                for (int nt = 0; nt < 8; nt++)
                    mma_tf32(acc[mt][nt], af[mt], bf[nt]);
        }
        __syncthreads();
    }

    // ---- epilogue ----
    #pragma unroll
    for (int mt = 0; mt < 2; mt++) {
        #pragma unroll
        for (int nt = 0; nt < 8; nt++) {
            long long row0 = bm + warpM + mt * 16 + g;
            long long col  = bn + warpN + nt * 8 + tg * 2;
            float b0 = 0.f, b1 = 0.f;
            if (HAS_BIAS) { b0 = bias[col]; b1 = bias[col + 1]; }
            float o00 = acc[mt][nt][0] * alpha + b0;
            float o01 = acc[mt][nt][1] * alpha + b1;
            float o10 = acc[mt][nt][2] * alpha + b0;
            float o11 = acc[mt][nt][3] * alpha + b1;
            if (ROUND_OUT) {
                o00 = f2tf(o00); o01 = f2tf(o01); o10 = f2tf(o10); o11 = f2tf(o11);
            }
            *reinterpret_cast<float2*>(Cout + row0 * Ntot + col)       = make_float2(o00, o01);
            *reinterpret_cast<float2*>(Cout + (row0 + 8) * Ntot + col) = make_float2(o10, o11);
        }
    }
}

// ---------------- softmax over rows of g_attn (len 2048), writes tf32 -------
__global__ void softmax_kernel() {
    __shared__ float shm[9];
    float* row = g_attn + (long long)blockIdx.x * ND;
    int t = threadIdx.x;
    float vals[8];
    float m = -INFINITY;
    #pragma unroll
    for (int i = 0; i < 8; i++) {
        vals[i] = row[t + i * 256];
        m = fmaxf(m, vals[i]);
    }
    m = block_max256(m, shm);
    float s = 0.f;
    #pragma unroll
    for (int i = 0; i < 8; i++) {
        vals[i] = __expf(vals[i] - m);
        s += vals[i];
    }
    s = block_sum256(s, shm);
    float inv = 1.0f / s;
    #pragma unroll
    for (int i = 0; i < 8; i++) row[t + i * 256] = f2tf(vals[i] * inv);
}

// ---------------- launch ----------------------------------------------------
extern "C" void kernel_launch(void* const* d_in, const int* in_sizes, int n_in,
                              void* d_out, int out_size) {
    const float* q    = (const float*)d_in[0];
    const float* k    = (const float*)d_in[1];
    const float* v    = (const float*)d_in[2];
    const float* ln_g = (const float*)d_in[3];
    const float* ln_b = (const float*)d_in[4];
    const float* Wq   = (const float*)d_in[5];
    const float* bq   = (const float*)d_in[6];
    const float* Wk   = (const float*)d_in[7];
    const float* bk   = (const float*)d_in[8];
    const float* Wv   = (const float*)d_in[9];
    const float* bv   = (const float*)d_in[10];
    const float* Wo   = (const float*)d_in[11];
    const float* bo   = (const float*)d_in[12];
    float* out = (float*)d_out;

    float *qn, *kn, *vn, *qp, *kp, *vp, *vpt, *attn, *x, *wqt, *wkt, *wvt, *wot;
    cudaGetSymbolAddress((void**)&qn, g_qn);
    cudaGetSymbolAddress((void**)&kn, g_kn);
    cudaGetSymbolAddress((void**)&vn, g_vn);
    cudaGetSymbolAddress((void**)&qp, g_qp);
    cudaGetSymbolAddress((void**)&kp, g_kp);
    cudaGetSymbolAddress((void**)&vp, g_vp);
    cudaGetSymbolAddress((void**)&vpt, g_vpt);
    cudaGetSymbolAddress((void**)&attn, g_attn);
    cudaGetSymbolAddress((void**)&x, g_x);
    cudaGetSymbolAddress((void**)&wqt, g_wqt);
    cudaGetSymbolAddress((void**)&wkt, g_wkt);
    cudaGetSymbolAddress((void**)&wvt, g_wvt);
    cudaGetSymbolAddress((void**)&wot, g_wot);

    // 0. transpose+round weights: Wq/Wk/Wv [256,1024]->[1024,256]; Wo [1024,256]->[256,1024]
    transpose_kernel<<<dim3(INNER / 32, CD / 32, 1), dim3(32, 8)>>>(Wq, wqt, CD, INNER, 0, 0);
    transpose_kernel<<<dim3(INNER / 32, CD / 32, 1), dim3(32, 8)>>>(Wk, wkt, CD, INNER, 0, 0);
    transpose_kernel<<<dim3(INNER / 32, CD / 32, 1), dim3(32, 8)>>>(Wv, wvt, CD, INNER, 0, 0);
    transpose_kernel<<<dim3(CD / 32, INNER / 32, 1), dim3(32, 8)>>>(Wo, wot, INNER, CD, 0, 0);

    // 1. LayerNorm q,k,v (tf32-rounded out)
    ln_kernel<<<dim3(ROWS, 3), 256>>>(q, k, v, ln_g, ln_b);

    // 2. Projections: A[8192,256] @ Wt[1024,256]^T + bias
    {
        dim3 grid(INNER / 128, ROWS / 128, 1);
        mma_gemm<true, true ><<<grid, 256>>>(qn, wqt, bq, qp, INNER, CD, 1.0f, 0, 0, 0);
        mma_gemm<true, true ><<<grid, 256>>>(kn, wkt, bk, kp, INNER, CD, 1.0f, 0, 0, 0);
        mma_gemm<true, false><<<grid, 256>>>(vn, wvt, bv, vp, INNER, CD, 1.0f, 0, 0, 0);
    }

    // 3. Scores: per batch qp[2048,1024] @ kp[2048,1024]^T * SCALE
    {
        dim3 grid(ND / 128, ND / 128, BD);
        mma_gemm<false, false><<<grid, 256>>>(
            qp, kp, nullptr, attn, ND, INNER, ATT_SCALE,
            (long long)ND * INNER, (long long)ND * INNER, (long long)ND * ND);
    }

    // 4. Softmax rows (tf32-rounded out)
    softmax_kernel<<<BD * ND, 256>>>();

    // 5. transpose+round vp -> vpt per batch: [2048,1024] -> [1024,2048]
    transpose_kernel<<<dim3(INNER / 32, ND / 32, BD), dim3(32, 8)>>>(
        vp, vpt, ND, INNER, (long long)ND * INNER, (long long)ND * INNER);

    // 6. AV: per batch attn[2048,2048] @ vpt[1024,2048]^T  (rounded out)
    {
        dim3 grid(INNER / 128, ND / 128, BD);
        mma_gemm<false, true><<<grid, 256>>>(
            attn, vpt, nullptr, x, INNER, ND, 1.0f,
            (long long)ND * ND, (long long)ND * INNER, (long long)ND * INNER);
    }

    // 7. Output projection: x[8192,1024] @ wot[256,1024]^T + bias (fp32 out)
    {
        dim3 grid(CD / 128, ROWS / 128, 1);
        mma_gemm<true, false><<<grid, 256>>>(x, wot, bo, out, CD, INNER, 1.0f, 0, 0, 0);
    }
}

// round 6
// speedup vs baseline: 1.3123x; 1.3123x over previous
#include <cuda_runtime.h>
#include <math.h>
#include <stdint.h>

// Problem constants
#define BD 4
#define ND 2048
#define CD 256
#define INNER 1024
#define ROWS (BD*ND)          // 8192
#define EPS 1e-5f
#define ATT_SCALE 0.125f      // 64^-0.5

// ---------------- scratch (device globals; allocation-free rule) -------------
__device__ float g_qn[ROWS*CD];
__device__ float g_kn[ROWS*CD];
__device__ float g_vn[ROWS*CD];
__device__ float g_qp[ROWS*INNER];
__device__ float g_kp[ROWS*INNER];
__device__ float g_vp[ROWS*INNER];
__device__ float g_vpt[ROWS*INNER];            // vp^T per batch [INNER, ND] (tf32)
__device__ float g_attn[(long long)BD*ND*ND];  // 64 MB raw scaled scores
__device__ float g_x[ROWS*INNER];
__device__ float g_wqt[INNER*CD];              // Wq^T [1024,256] (tf32)
__device__ float g_wkt[INNER*CD];
__device__ float g_wvt[INNER*CD];
__device__ float g_wot[CD*INNER];              // Wo^T [256,1024] (tf32)
__device__ float g_sm_m[ROWS];                 // per-row score max
__device__ float g_sm_il[ROWS];                // per-row 1/sum(exp)

// ---------------- helpers ----------------
__device__ __forceinline__ float warp_sum(float v) {
    #pragma unroll
    for (int o = 16; o; o >>= 1) v += __shfl_xor_sync(0xffffffffu, v, o);
    return v;
}
__device__ __forceinline__ float warp_max(float v) {
    #pragma unroll
    for (int o = 16; o; o >>= 1) v = fmaxf(v, __shfl_xor_sync(0xffffffffu, v, o));
    return v;
}
__device__ __forceinline__ float block_sum256(float v, float* shm) {
    v = warp_sum(v);
    int w = threadIdx.x >> 5;
    if ((threadIdx.x & 31) == 0) shm[w] = v;
    __syncthreads();
    if (threadIdx.x == 0) {
        float s = 0.f;
        #pragma unroll
        for (int i = 0; i < 8; i++) s += shm[i];
        shm[8] = s;
    }
    __syncthreads();
    float r = shm[8];
    __syncthreads();
    return r;
}
__device__ __forceinline__ float block_max256(float v, float* shm) {
    v = warp_max(v);
    int w = threadIdx.x >> 5;
    if ((threadIdx.x & 31) == 0) shm[w] = v;
    __syncthreads();
    if (threadIdx.x == 0) {
        float m = shm[0];
        #pragma unroll
        for (int i = 1; i < 8; i++) m = fmaxf(m, shm[i]);
        shm[8] = m;
    }
    __syncthreads();
    float r = shm[8];
    __syncthreads();
    return r;
}

__device__ __forceinline__ float f2tf(float f) {
    unsigned r;
    asm("cvt.rna.tf32.f32 %0, %1;" : "=r"(r) : "f"(f));
    return __uint_as_float(r);
}

__device__ __forceinline__ void mma_tf32(float* c, const unsigned* a, const unsigned* b) {
    asm volatile(
        "mma.sync.aligned.m16n8k8.row.col.f32.tf32.tf32.f32 "
        "{%0,%1,%2,%3}, {%4,%5,%6,%7}, {%8,%9}, {%0,%1,%2,%3};"
        : "+f"(c[0]), "+f"(c[1]), "+f"(c[2]), "+f"(c[3])
        : "r"(a[0]), "r"(a[1]), "r"(a[2]), "r"(a[3]), "r"(b[0]), "r"(b[1]));
}

// ---------------- LayerNorm (writes tf32-rounded) ---------------------------
__global__ void ln_kernel(const float* __restrict__ q, const float* __restrict__ k,
                          const float* __restrict__ v, const float* __restrict__ g,
                          const float* __restrict__ b) {
    __shared__ float shm[9];
    const float* src;
    float* dst;
    int which = blockIdx.y;
    long long off = (long long)blockIdx.x * CD;
    if (which == 0)      { src = q + off; dst = g_qn + off; }
    else if (which == 1) { src = k + off; dst = g_kn + off; }
    else                 { src = v + off; dst = g_vn + off; }
    int t = threadIdx.x;
    float x = src[t];
    float mean = block_sum256(x, shm) * (1.0f / CD);
    float d = x - mean;
    float var = block_sum256(d * d, shm) * (1.0f / CD);
    float inv = rsqrtf(var + EPS);
    dst[t] = f2tf(d * inv * g[t] + b[t]);
}

// ---------------- rounding transpose: dst[C,R] = tf32(src[R,C]^T) -----------
__global__ void transpose_kernel(const float* __restrict__ src, float* __restrict__ dst,
                                 int R, int C, long long sstride, long long dstride) {
    __shared__ float tile[32][33];
    src += (long long)blockIdx.z * sstride;
    dst += (long long)blockIdx.z * dstride;
    int tx = threadIdx.x, ty = threadIdx.y;
    int c0 = blockIdx.x * 32, r0 = blockIdx.y * 32;
    #pragma unroll
    for (int j = 0; j < 4; j++)
        tile[ty + 8 * j][tx] = f2tf(src[(long long)(r0 + ty + 8 * j) * C + c0 + tx]);
    __syncthreads();
    #pragma unroll
    for (int j = 0; j < 4; j++)
        dst[(long long)(c0 + ty + 8 * j) * R + r0 + tx] = tile[tx][ty + 8 * j];
}

// ---------------- softmax row stats: max and 1/sumexp ------------------------
__global__ void softmax_stats_kernel() {
    __shared__ float shm[9];
    const float4* row = reinterpret_cast<const float4*>(g_attn + (long long)blockIdx.x * ND);
    int t = threadIdx.x;
    float4 v0 = row[t];
    float4 v1 = row[t + 256];
    float m = fmaxf(fmaxf(fmaxf(v0.x, v0.y), fmaxf(v0.z, v0.w)),
                    fmaxf(fmaxf(v1.x, v1.y), fmaxf(v1.z, v1.w)));
    m = block_max256(m, shm);
    float s = __expf(v0.x - m) + __expf(v0.y - m) + __expf(v0.z - m) + __expf(v0.w - m)
            + __expf(v1.x - m) + __expf(v1.y - m) + __expf(v1.z - m) + __expf(v1.w - m);
    s = block_sum256(s, shm);
    if (t == 0) {
        g_sm_m[blockIdx.x]  = m;
        g_sm_il[blockIdx.x] = 1.0f / s;
    }
}

// ---------------- tf32 tensor-core GEMM (NT form; R2-proven inner loop) -----
// C[M,Ntot] = alpha * A[M,K] @ B[Ntot,K]^T (+ bias). Inputs pre-rounded tf32,
// except SOFT_A: A holds raw scores; fill applies tf32(exp(a-m)*il) per row.
// Block tile 128x128x32, 8 warps (4Mx2N), warp tile 32x64, mma m16n8k8.
template<bool HAS_BIAS, bool ROUND_OUT, bool SOFT_A>
__global__ __launch_bounds__(256)
void mma_gemm(const float* __restrict__ A, const float* __restrict__ B,
              const float* __restrict__ bias, float* __restrict__ Cout,
              int Ntot, int K, float alpha,
              long long strideA, long long strideB, long long strideC) {
    constexpr int AS = 36;
    __shared__ float As[128 * AS];
    __shared__ float Bs[128 * AS];

    A    += (long long)blockIdx.z * strideA;
    B    += (long long)blockIdx.z * strideB;
    Cout += (long long)blockIdx.z * strideC;

    const int tid  = threadIdx.x;
    const int lane = tid & 31;
    const int w    = tid >> 5;
    const int g    = lane >> 2;
    const int tg   = lane & 3;
    const int warpM = (w >> 1) * 32;
    const int warpN = (w & 1) * 64;
    const long long bm = (long long)blockIdx.y * 128;
    const long long bn = (long long)blockIdx.x * 128;

    const int ar = tid >> 3;               // 0..31
    const int ac = (tid & 7) * 4;          // 0..28

    // per-row softmax stats for the 4 A-rows this thread fills
    float sm_m[4], sm_il[4];
    if (SOFT_A) {
        #pragma unroll
        for (int i = 0; i < 4; i++) {
            int r = ar + i * 32;
            sm_m[i]  = g_sm_m[blockIdx.z * ND + bm + r];
            sm_il[i] = g_sm_il[blockIdx.z * ND + bm + r];
        }
    }

    float acc[2][8][4];
    #pragma unroll
    for (int i = 0; i < 2; i++)
        #pragma unroll
        for (int j = 0; j < 8; j++)
            #pragma unroll
            for (int q_ = 0; q_ < 4; q_++) acc[i][j][q_] = 0.f;

    for (int k0 = 0; k0 < K; k0 += 32) {
        // ---- A tile (128x32) ----
        #pragma unroll
        for (int i = 0; i < 4; i++) {
            int r = ar + i * 32;
            float4 v = *reinterpret_cast<const float4*>(A + (bm + r) * K + k0 + ac);
            if (SOFT_A) {
                v.x = f2tf(__expf(v.x - sm_m[i]) * sm_il[i]);
                v.y = f2tf(__expf(v.y - sm_m[i]) * sm_il[i]);
                v.z = f2tf(__expf(v.z - sm_m[i]) * sm_il[i]);
                v.w = f2tf(__expf(v.w - sm_m[i]) * sm_il[i]);
            }
            *reinterpret_cast<float4*>(&As[r * AS + ac]) = v;
        }
        // ---- B tile (128x32) ----
        #pragma unroll
        for (int i = 0; i < 4; i++) {
            int r = ar + i * 32;
            float4 v = *reinterpret_cast<const float4*>(B + (bn + r) * K + k0 + ac);
            *reinterpret_cast<float4*>(&Bs[r * AS + ac]) = v;
        }
        __syncthreads();

        #pragma unroll
        for (int ks = 0; ks < 4; ks++) {
            const int kb = ks * 8;
            unsigned af[2][4];
            #pragma unroll
            for (int mt = 0; mt < 2; mt++) {
                int m = warpM + mt * 16;
                af[mt][0] = __float_as_uint(As[(m + g)     * AS + kb + tg]);
                af[mt][1] = __float_as_uint(As[(m + g + 8) * AS + kb + tg]);
                af[mt][2] = __float_as_uint(As[(m + g)     * AS + kb + tg + 4]);
                af[mt][3] = __float_as_uint(As[(m + g + 8) * AS + kb + tg + 4]);
            }
            unsigned bf[8][2];
            #pragma unroll
            for (int nt = 0; nt < 8; nt++) {
                int n = warpN + nt * 8 + g;
                bf[nt][0] = __float_as_uint(Bs[n * AS + kb + tg]);
                bf[nt][1] = __float_as_uint(Bs[n * AS + kb + tg + 4]);
            }
            #pragma unroll
            for (int mt = 0; mt < 2; mt++)
                #pragma unroll
                for (int nt = 0; nt < 8; nt++)
                    mma_tf32(acc[mt][nt], af[mt], bf[nt]);
        }
        __syncthreads();
    }

    // ---- epilogue ----
    #pragma unroll
    for (int mt = 0; mt < 2; mt++) {
        #pragma unroll
        for (int nt = 0; nt < 8; nt++) {
            long long row0 = bm + warpM + mt * 16 + g;
            long long col  = bn + warpN + nt * 8 + tg * 2;
            float b0 = 0.f, b1 = 0.f;
            if (HAS_BIAS) { b0 = bias[col]; b1 = bias[col + 1]; }
            float o00 = acc[mt][nt][0] * alpha + b0;
            float o01 = acc[mt][nt][1] * alpha + b1;
            float o10 = acc[mt][nt][2] * alpha + b0;
            float o11 = acc[mt][nt][3] * alpha + b1;
            if (ROUND_OUT) {
                o00 = f2tf(o00); o01 = f2tf(o01); o10 = f2tf(o10); o11 = f2tf(o11);
            }
            *reinterpret_cast<float2*>(Cout + row0 * Ntot + col)       = make_float2(o00, o01);
            *reinterpret_cast<float2*>(Cout + (row0 + 8) * Ntot + col) = make_float2(o10, o11);
        }
    }
}

// ---------------- launch ----------------------------------------------------
extern "C" void kernel_launch(void* const* d_in, const int* in_sizes, int n_in,
                              void* d_out, int out_size) {
    const float* q    = (const float*)d_in[0];
    const float* k    = (const float*)d_in[1];
    const float* v    = (const float*)d_in[2];
    const float* ln_g = (const float*)d_in[3];
    const float* ln_b = (const float*)d_in[4];
    const float* Wq   = (const float*)d_in[5];
    const float* bq   = (const float*)d_in[6];
    const float* Wk   = (const float*)d_in[7];
    const float* bk   = (const float*)d_in[8];
    const float* Wv   = (const float*)d_in[9];
    const float* bv   = (const float*)d_in[10];
    const float* Wo   = (const float*)d_in[11];
    const float* bo   = (const float*)d_in[12];
    float* out = (float*)d_out;

    float *qn, *kn, *vn, *qp, *kp, *vp, *vpt, *attn, *x, *wqt, *wkt, *wvt, *wot;
    cudaGetSymbolAddress((void**)&qn, g_qn);
    cudaGetSymbolAddress((void**)&kn, g_kn);
    cudaGetSymbolAddress((void**)&vn, g_vn);
    cudaGetSymbolAddress((void**)&qp, g_qp);
    cudaGetSymbolAddress((void**)&kp, g_kp);
    cudaGetSymbolAddress((void**)&vp, g_vp);
    cudaGetSymbolAddress((void**)&vpt, g_vpt);
    cudaGetSymbolAddress((void**)&attn, g_attn);
    cudaGetSymbolAddress((void**)&x, g_x);
    cudaGetSymbolAddress((void**)&wqt, g_wqt);
    cudaGetSymbolAddress((void**)&wkt, g_wkt);
    cudaGetSymbolAddress((void**)&wvt, g_wvt);
    cudaGetSymbolAddress((void**)&wot, g_wot);

    // 0. transpose+round weights
    transpose_kernel<<<dim3(INNER / 32, CD / 32, 1), dim3(32, 8)>>>(Wq, wqt, CD, INNER, 0, 0);
    transpose_kernel<<<dim3(INNER / 32, CD / 32, 1), dim3(32, 8)>>>(Wk, wkt, CD, INNER, 0, 0);
    transpose_kernel<<<dim3(INNER / 32, CD / 32, 1), dim3(32, 8)>>>(Wv, wvt, CD, INNER, 0, 0);
    transpose_kernel<<<dim3(CD / 32, INNER / 32, 1), dim3(32, 8)>>>(Wo, wot, INNER, CD, 0, 0);

    // 1. LayerNorm q,k,v (tf32-rounded out)
    ln_kernel<<<dim3(ROWS, 3), 256>>>(q, k, v, ln_g, ln_b);

    // 2. Projections: A[8192,256] @ Wt[1024,256]^T + bias
    {
        dim3 grid(INNER / 128, ROWS / 128, 1);
        mma_gemm<true, true,  false><<<grid, 256>>>(qn, wqt, bq, qp, INNER, CD, 1.0f, 0, 0, 0);
        mma_gemm<true, true,  false><<<grid, 256>>>(kn, wkt, bk, kp, INNER, CD, 1.0f, 0, 0, 0);
        mma_gemm<true, false, false><<<grid, 256>>>(vn, wvt, bv, vp, INNER, CD, 1.0f, 0, 0, 0);
    }

    // 3. Scores: per batch qp[2048,1024] @ kp[2048,1024]^T * SCALE (raw fp32 out)
    {
        dim3 grid(ND / 128, ND / 128, BD);
        mma_gemm<false, false, false><<<grid, 256>>>(
            qp, kp, nullptr, attn, ND, INNER, ATT_SCALE,
            (long long)ND * INNER, (long long)ND * INNER, (long long)ND * ND);
    }

    // 4. Softmax row stats (max, 1/sumexp)
    softmax_stats_kernel<<<BD * ND, 256>>>();

    // 5. transpose+round vp -> vpt per batch: [2048,1024] -> [1024,2048]
    transpose_kernel<<<dim3(INNER / 32, ND / 32, BD), dim3(32, 8)>>>(
        vp, vpt, ND, INNER, (long long)ND * INNER, (long long)ND * INNER);

    // 6. AV with fused softmax in A-fill: per batch exp(attn) @ vpt^T (rounded out)
    {
        dim3 grid(INNER / 128, ND / 128, BD);
        mma_gemm<false, true, true><<<grid, 256>>>(
            attn, vpt, nullptr, x, INNER, ND, 1.0f,
            (long long)ND * ND, (long long)ND * INNER, (long long)ND * INNER);
    }

    // 7. Output projection: x[8192,1024] @ wot[256,1024]^T + bias (fp32 out)
    {
        dim3 grid(CD / 128, ROWS / 128, 1);
        mma_gemm<true, false, false><<<grid, 256>>>(x, wot, bo, out, CD, INNER, 1.0f, 0, 0, 0);
    }
}

// round 7
// speedup vs baseline: 1.5640x; 1.1918x over previous
#include <cuda_runtime.h>
#include <math.h>
#include <stdint.h>

// Problem constants
#define BD 4
#define ND 2048
#define CD 256
#define INNER 1024
#define ROWS (BD*ND)          // 8192
#define EPS 1e-5f
#define ATT_SCALE 0.125f      // 64^-0.5

// ---------------- scratch (device globals; allocation-free rule) -------------
__device__ float g_qn[ROWS*CD];
__device__ float g_kn[ROWS*CD];
__device__ float g_vn[ROWS*CD];
__device__ float g_qp[ROWS*INNER];
__device__ float g_kp[ROWS*INNER];
__device__ float g_vp[ROWS*INNER];
__device__ float g_vpt[ROWS*INNER];            // vp^T per batch [INNER, ND] (tf32)
__device__ float g_attn[(long long)BD*ND*ND];  // 64 MB
__device__ float g_x[ROWS*INNER];
__device__ float g_wqt[INNER*CD];              // Wq^T [1024,256] (tf32)
__device__ float g_wkt[INNER*CD];
__device__ float g_wvt[INNER*CD];
__device__ float g_wot[CD*INNER];              // Wo^T [256,1024] (tf32)

// ---------------- helpers ----------------
__device__ __forceinline__ float warp_sum(float v) {
    #pragma unroll
    for (int o = 16; o; o >>= 1) v += __shfl_xor_sync(0xffffffffu, v, o);
    return v;
}
__device__ __forceinline__ float warp_max(float v) {
    #pragma unroll
    for (int o = 16; o; o >>= 1) v = fmaxf(v, __shfl_xor_sync(0xffffffffu, v, o));
    return v;
}
__device__ __forceinline__ float block_sum256(float v, float* shm) {
    v = warp_sum(v);
    int w = threadIdx.x >> 5;
    if ((threadIdx.x & 31) == 0) shm[w] = v;
    __syncthreads();
    if (threadIdx.x == 0) {
        float s = 0.f;
        #pragma unroll
        for (int i = 0; i < 8; i++) s += shm[i];
        shm[8] = s;
    }
    __syncthreads();
    float r = shm[8];
    __syncthreads();
    return r;
}
__device__ __forceinline__ float block_max256(float v, float* shm) {
    v = warp_max(v);
    int w = threadIdx.x >> 5;
    if ((threadIdx.x & 31) == 0) shm[w] = v;
    __syncthreads();
    if (threadIdx.x == 0) {
        float m = shm[0];
        #pragma unroll
        for (int i = 1; i < 8; i++) m = fmaxf(m, shm[i]);
        shm[8] = m;
    }
    __syncthreads();
    float r = shm[8];
    __syncthreads();
    return r;
}

__device__ __forceinline__ float f2tf(float f) {
    unsigned r;
    asm("cvt.rna.tf32.f32 %0, %1;" : "=r"(r) : "f"(f));
    return __uint_as_float(r);
}

__device__ __forceinline__ void mma_tf32(float* c, const unsigned* a, const unsigned* b) {
    asm volatile(
        "mma.sync.aligned.m16n8k8.row.col.f32.tf32.tf32.f32 "
        "{%0,%1,%2,%3}, {%4,%5,%6,%7}, {%8,%9}, {%0,%1,%2,%3};"
        : "+f"(c[0]), "+f"(c[1]), "+f"(c[2]), "+f"(c[3])
        : "r"(a[0]), "r"(a[1]), "r"(a[2]), "r"(a[3]), "r"(b[0]), "r"(b[1]));
}

__device__ __forceinline__ void cp16(float* smem_dst, const float* gmem_src) {
    unsigned s = (unsigned)__cvta_generic_to_shared(smem_dst);
    asm volatile("cp.async.cg.shared.global [%0], [%1], 16;" :: "r"(s), "l"(gmem_src));
}
__device__ __forceinline__ void cp_commit() {
    asm volatile("cp.async.commit_group;");
}
template<int NN>
__device__ __forceinline__ void cp_wait() {
    asm volatile("cp.async.wait_group %0;" :: "n"(NN));
}

// ---------------- LayerNorm (writes tf32-rounded) ---------------------------
__global__ void ln_kernel(const float* __restrict__ q, const float* __restrict__ k,
                          const float* __restrict__ v, const float* __restrict__ g,
                          const float* __restrict__ b) {
    __shared__ float shm[9];
    const float* src;
    float* dst;
    int which = blockIdx.y;
    long long off = (long long)blockIdx.x * CD;
    if (which == 0)      { src = q + off; dst = g_qn + off; }
    else if (which == 1) { src = k + off; dst = g_kn + off; }
    else                 { src = v + off; dst = g_vn + off; }
    int t = threadIdx.x;
    float x = src[t];
    float mean = block_sum256(x, shm) * (1.0f / CD);
    float d = x - mean;
    float var = block_sum256(d * d, shm) * (1.0f / CD);
    float inv = rsqrtf(var + EPS);
    dst[t] = f2tf(d * inv * g[t] + b[t]);
}

// ---------------- rounding transpose: dst[C,R] = tf32(src[R,C]^T) -----------
__global__ void transpose_kernel(const float* __restrict__ src, float* __restrict__ dst,
                                 int R, int C, long long sstride, long long dstride) {
    __shared__ float tile[32][33];
    src += (long long)blockIdx.z * sstride;
    dst += (long long)blockIdx.z * dstride;
    int tx = threadIdx.x, ty = threadIdx.y;
    int c0 = blockIdx.x * 32, r0 = blockIdx.y * 32;
    #pragma unroll
    for (int j = 0; j < 4; j++)
        tile[ty + 8 * j][tx] = f2tf(src[(long long)(r0 + ty + 8 * j) * C + c0 + tx]);
    __syncthreads();
    #pragma unroll
    for (int j = 0; j < 4; j++)
        dst[(long long)(c0 + ty + 8 * j) * R + r0 + tx] = tile[tx][ty + 8 * j];
}

// ---------------- softmax over rows of g_attn (len 2048), writes tf32 -------
__global__ void softmax_kernel() {
    __shared__ float shm[9];
    float* row = g_attn + (long long)blockIdx.x * ND;
    int t = threadIdx.x;
    float vals[8];
    float m = -INFINITY;
    #pragma unroll
    for (int i = 0; i < 8; i++) {
        vals[i] = row[t + i * 256];
        m = fmaxf(m, vals[i]);
    }
    m = block_max256(m, shm);
    float s = 0.f;
    #pragma unroll
    for (int i = 0; i < 8; i++) {
        vals[i] = __expf(vals[i] - m);
        s += vals[i];
    }
    s = block_sum256(s, shm);
    float inv = 1.0f / s;
    #pragma unroll
    for (int i = 0; i < 8; i++) row[t + i * 256] = f2tf(vals[i] * inv);
}

// ---------------- tf32 tensor-core GEMM (NT; 2-stage cp.async pipeline) -----
// C[M,Ntot] = alpha * A[M,K] @ B[Ntot,K]^T (+ bias). Inputs pre-rounded tf32.
// Block tile 128x128x32, 8 warps (4Mx2N), warp tile 32x64, mma m16n8k8.
#define AS 36
#define STG_FLOATS (128 * AS)    // one operand tile, 4608 floats
#define PIPE_SMEM (4 * STG_FLOATS * 4)  // 2 stages x (A+B) = 73728 bytes

template<bool HAS_BIAS, bool ROUND_OUT>
__global__ __launch_bounds__(256, 2)
void mma_gemm(const float* __restrict__ A, const float* __restrict__ B,
              const float* __restrict__ bias, float* __restrict__ Cout,
              int Ntot, int K, float alpha,
              long long strideA, long long strideB, long long strideC) {
    extern __shared__ float smem[];
    // layout: As0 | Bs0 | As1 | Bs1

    A    += (long long)blockIdx.z * strideA;
    B    += (long long)blockIdx.z * strideB;
    Cout += (long long)blockIdx.z * strideC;

    const int tid  = threadIdx.x;
    const int lane = tid & 31;
    const int w    = tid >> 5;
    const int g    = lane >> 2;
    const int tg   = lane & 3;
    const int warpM = (w >> 1) * 32;
    const int warpN = (w & 1) * 64;
    const long long bm = (long long)blockIdx.y * 128;
    const long long bn = (long long)blockIdx.x * 128;

    const int ar = tid >> 3;               // 0..31
    const int ac = (tid & 7) * 4;          // 0..28

    float acc[2][8][4];
    #pragma unroll
    for (int i = 0; i < 2; i++)
        #pragma unroll
        for (int j = 0; j < 8; j++)
            #pragma unroll
            for (int q_ = 0; q_ < 4; q_++) acc[i][j][q_] = 0.f;

    const int nit = K / 32;

    // stage fill via cp.async (raw copies; data pre-rounded to tf32)
    auto fill = [&](int st, int k0) {
        float* as = smem + st * 2 * STG_FLOATS;
        float* bs = as + STG_FLOATS;
        #pragma unroll
        for (int i = 0; i < 4; i++) {
            int r = ar + i * 32;
            cp16(&as[r * AS + ac], A + (bm + r) * K + k0 + ac);
        }
        #pragma unroll
        for (int i = 0; i < 4; i++) {
            int r = ar + i * 32;
            cp16(&bs[r * AS + ac], B + (bn + r) * K + k0 + ac);
        }
    };

    fill(0, 0);
    cp_commit();

    for (int it = 0; it < nit; it++) {
        if (it + 1 < nit) {
            fill((it + 1) & 1, (it + 1) * 32);
            cp_commit();
            cp_wait<1>();
        } else {
            cp_wait<0>();
        }
        __syncthreads();

        const float* as = smem + (it & 1) * 2 * STG_FLOATS;
        const float* bs = as + STG_FLOATS;

        #pragma unroll
        for (int ks = 0; ks < 4; ks++) {
            const int kb = ks * 8;
            unsigned af[2][4];
            #pragma unroll
            for (int mt = 0; mt < 2; mt++) {
                int m = warpM + mt * 16;
                af[mt][0] = __float_as_uint(as[(m + g)     * AS + kb + tg]);
                af[mt][1] = __float_as_uint(as[(m + g + 8) * AS + kb + tg]);
                af[mt][2] = __float_as_uint(as[(m + g)     * AS + kb + tg + 4]);
                af[mt][3] = __float_as_uint(as[(m + g + 8) * AS + kb + tg + 4]);
            }
            unsigned bf[8][2];
            #pragma unroll
            for (int nt = 0; nt < 8; nt++) {
                int n = warpN + nt * 8 + g;
                bf[nt][0] = __float_as_uint(bs[n * AS + kb + tg]);
                bf[nt][1] = __float_as_uint(bs[n * AS + kb + tg + 4]);
            }
            #pragma unroll
            for (int mt = 0; mt < 2; mt++)
                #pragma unroll
                for (int nt = 0; nt < 8; nt++)
                    mma_tf32(acc[mt][nt], af[mt], bf[nt]);
        }
        __syncthreads();
    }

    // ---- epilogue ----
    #pragma unroll
    for (int mt = 0; mt < 2; mt++) {
        #pragma unroll
        for (int nt = 0; nt < 8; nt++) {
            long long row0 = bm + warpM + mt * 16 + g;
            long long col  = bn + warpN + nt * 8 + tg * 2;
            float b0 = 0.f, b1 = 0.f;
            if (HAS_BIAS) { b0 = bias[col]; b1 = bias[col + 1]; }
            float o00 = acc[mt][nt][0] * alpha + b0;
            float o01 = acc[mt][nt][1] * alpha + b1;
            float o10 = acc[mt][nt][2] * alpha + b0;
            float o11 = acc[mt][nt][3] * alpha + b1;
            if (ROUND_OUT) {
                o00 = f2tf(o00); o01 = f2tf(o01); o10 = f2tf(o10); o11 = f2tf(o11);
            }
            *reinterpret_cast<float2*>(Cout + row0 * Ntot + col)       = make_float2(o00, o01);
            *reinterpret_cast<float2*>(Cout + (row0 + 8) * Ntot + col) = make_float2(o10, o11);
        }
    }
}

// ---------------- launch ----------------------------------------------------
extern "C" void kernel_launch(void* const* d_in, const int* in_sizes, int n_in,
                              void* d_out, int out_size) {
    const float* q    = (const float*)d_in[0];
    const float* k    = (const float*)d_in[1];
    const float* v    = (const float*)d_in[2];
    const float* ln_g = (const float*)d_in[3];
    const float* ln_b = (const float*)d_in[4];
    const float* Wq   = (const float*)d_in[5];
    const float* bq   = (const float*)d_in[6];
    const float* Wk   = (const float*)d_in[7];
    const float* bk   = (const float*)d_in[8];
    const float* Wv   = (const float*)d_in[9];
    const float* bv   = (const float*)d_in[10];
    const float* Wo   = (const float*)d_in[11];
    const float* bo   = (const float*)d_in[12];
    float* out = (float*)d_out;

    float *qn, *kn, *vn, *qp, *kp, *vp, *vpt, *attn, *x, *wqt, *wkt, *wvt, *wot;
    cudaGetSymbolAddress((void**)&qn, g_qn);
    cudaGetSymbolAddress((void**)&kn, g_kn);
    cudaGetSymbolAddress((void**)&vn, g_vn);
    cudaGetSymbolAddress((void**)&qp, g_qp);
    cudaGetSymbolAddress((void**)&kp, g_kp);
    cudaGetSymbolAddress((void**)&vp, g_vp);
    cudaGetSymbolAddress((void**)&vpt, g_vpt);
    cudaGetSymbolAddress((void**)&attn, g_attn);
    cudaGetSymbolAddress((void**)&x, g_x);
    cudaGetSymbolAddress((void**)&wqt, g_wqt);
    cudaGetSymbolAddress((void**)&wkt, g_wkt);
    cudaGetSymbolAddress((void**)&wvt, g_wvt);
    cudaGetSymbolAddress((void**)&wot, g_wot);

    cudaFuncSetAttribute(mma_gemm<true,  true >, cudaFuncAttributeMaxDynamicSharedMemorySize, PIPE_SMEM);
    cudaFuncSetAttribute(mma_gemm<true,  false>, cudaFuncAttributeMaxDynamicSharedMemorySize, PIPE_SMEM);
    cudaFuncSetAttribute(mma_gemm<false, true >, cudaFuncAttributeMaxDynamicSharedMemorySize, PIPE_SMEM);
    cudaFuncSetAttribute(mma_gemm<false, false>, cudaFuncAttributeMaxDynamicSharedMemorySize, PIPE_SMEM);

    // 0. transpose+round weights
    transpose_kernel<<<dim3(INNER / 32, CD / 32, 1), dim3(32, 8)>>>(Wq, wqt, CD, INNER, 0, 0);
    transpose_kernel<<<dim3(INNER / 32, CD / 32, 1), dim3(32, 8)>>>(Wk, wkt, CD, INNER, 0, 0);
    transpose_kernel<<<dim3(INNER / 32, CD / 32, 1), dim3(32, 8)>>>(Wv, wvt, CD, INNER, 0, 0);
    transpose_kernel<<<dim3(CD / 32, INNER / 32, 1), dim3(32, 8)>>>(Wo, wot, INNER, CD, 0, 0);

    // 1. LayerNorm q,k,v (tf32-rounded out)
    ln_kernel<<<dim3(ROWS, 3), 256>>>(q, k, v, ln_g, ln_b);

    // 2. Projections: A[8192,256] @ Wt[1024,256]^T + bias
    {
        dim3 grid(INNER / 128, ROWS / 128, 1);
        mma_gemm<true, true ><<<grid, 256, PIPE_SMEM>>>(qn, wqt, bq, qp, INNER, CD, 1.0f, 0, 0, 0);
        mma_gemm<true, true ><<<grid, 256, PIPE_SMEM>>>(kn, wkt, bk, kp, INNER, CD, 1.0f, 0, 0, 0);
        mma_gemm<true, false><<<grid, 256, PIPE_SMEM>>>(vn, wvt, bv, vp, INNER, CD, 1.0f, 0, 0, 0);
    }

    // 3. Scores: per batch qp[2048,1024] @ kp[2048,1024]^T * SCALE (raw fp32 out)
    {
        dim3 grid(ND / 128, ND / 128, BD);
        mma_gemm<false, false><<<grid, 256, PIPE_SMEM>>>(
            qp, kp, nullptr, attn, ND, INNER, ATT_SCALE,
            (long long)ND * INNER, (long long)ND * INNER, (long long)ND * ND);
    }

    // 4. Softmax rows (writes tf32-rounded attn)
    softmax_kernel<<<BD * ND, 256>>>();

    // 5. transpose+round vp -> vpt per batch: [2048,1024] -> [1024,2048]
    transpose_kernel<<<dim3(INNER / 32, ND / 32, BD), dim3(32, 8)>>>(
        vp, vpt, ND, INNER, (long long)ND * INNER, (long long)ND * INNER);

    // 6. AV: per batch attn[2048,2048] @ vpt[1024,2048]^T (rounded out)
    {
        dim3 grid(INNER / 128, ND / 128, BD);
        mma_gemm<false, true><<<grid, 256, PIPE_SMEM>>>(
            attn, vpt, nullptr, x, INNER, ND, 1.0f,
            (long long)ND * ND, (long long)ND * INNER, (long long)ND * INNER);
    }

    // 7. Output projection: x[8192,1024] @ wot[256,1024]^T + bias (fp32 out)
    {
        dim3 grid(CD / 128, ROWS / 128, 1);
        mma_gemm<true, false><<<grid, 256, PIPE_SMEM>>>(x, wot, bo, out, CD, INNER, 1.0f, 0, 0, 0);
    }
}

// round 8
// speedup vs baseline: 2.3644x; 1.5117x over previous
#include <cuda_runtime.h>
#include <cuda_fp16.h>
#include <math.h>
#include <stdint.h>

// Problem constants
#define BD 4
#define ND 2048
#define CD 256
#define INNER 1024
#define ROWS (BD*ND)          // 8192
#define EPS 1e-5f
#define ATT_SCALE 0.125f      // 64^-0.5

// ---------------- scratch (device globals; allocation-free rule) -------------
__device__ __half g_qn[ROWS*CD];
__device__ __half g_kn[ROWS*CD];
__device__ __half g_vn[ROWS*CD];
__device__ __half g_qp[ROWS*INNER];
__device__ __half g_kp[ROWS*INNER];
__device__ __half g_vp[ROWS*INNER];
__device__ __half g_vpt[ROWS*INNER];            // vp^T per batch [INNER, ND]
__device__ float  g_attn[(long long)BD*ND*ND];  // raw fp32 scores, 64 MB
__device__ __half g_attnh[(long long)BD*ND*ND]; // softmaxed probs, half, 32 MB
__device__ __half g_x[ROWS*INNER];
__device__ __half g_wqt[INNER*CD];              // Wq^T [1024,256]
__device__ __half g_wkt[INNER*CD];
__device__ __half g_wvt[INNER*CD];
__device__ __half g_wot[CD*INNER];              // Wo^T [256,1024]

// ---------------- helpers ----------------
__device__ __forceinline__ float warp_sum(float v) {
    #pragma unroll
    for (int o = 16; o; o >>= 1) v += __shfl_xor_sync(0xffffffffu, v, o);
    return v;
}
__device__ __forceinline__ float warp_max(float v) {
    #pragma unroll
    for (int o = 16; o; o >>= 1) v = fmaxf(v, __shfl_xor_sync(0xffffffffu, v, o));
    return v;
}
__device__ __forceinline__ float block_sum256(float v, float* shm) {
    v = warp_sum(v);
    int w = threadIdx.x >> 5;
    if ((threadIdx.x & 31) == 0) shm[w] = v;
    __syncthreads();
    if (threadIdx.x == 0) {
        float s = 0.f;
        #pragma unroll
        for (int i = 0; i < 8; i++) s += shm[i];
        shm[8] = s;
    }
    __syncthreads();
    float r = shm[8];
    __syncthreads();
    return r;
}
__device__ __forceinline__ float block_max256(float v, float* shm) {
    v = warp_max(v);
    int w = threadIdx.x >> 5;
    if ((threadIdx.x & 31) == 0) shm[w] = v;
    __syncthreads();
    if (threadIdx.x == 0) {
        float m = shm[0];
        #pragma unroll
        for (int i = 1; i < 8; i++) m = fmaxf(m, shm[i]);
        shm[8] = m;
    }
    __syncthreads();
    float r = shm[8];
    __syncthreads();
    return r;
}

// mma m16n8k16: f32 acc, f16 inputs
__device__ __forceinline__ void mma_f16(float* c, const unsigned* a, const unsigned* b) {
    asm volatile(
        "mma.sync.aligned.m16n8k16.row.col.f32.f16.f16.f32 "
        "{%0,%1,%2,%3}, {%4,%5,%6,%7}, {%8,%9}, {%0,%1,%2,%3};"
        : "+f"(c[0]), "+f"(c[1]), "+f"(c[2]), "+f"(c[3])
        : "r"(a[0]), "r"(a[1]), "r"(a[2]), "r"(a[3]), "r"(b[0]), "r"(b[1]));
}

__device__ __forceinline__ void cp16(void* smem_dst, const void* gmem_src) {
    unsigned s = (unsigned)__cvta_generic_to_shared(smem_dst);
    asm volatile("cp.async.cg.shared.global [%0], [%1], 16;" :: "r"(s), "l"(gmem_src));
}
__device__ __forceinline__ void cp_commit() {
    asm volatile("cp.async.commit_group;");
}
template<int NN>
__device__ __forceinline__ void cp_wait() {
    asm volatile("cp.async.wait_group %0;" :: "n"(NN));
}

// ---------------- LayerNorm (writes half) ------------------------------------
__global__ void ln_kernel(const float* __restrict__ q, const float* __restrict__ k,
                          const float* __restrict__ v, const float* __restrict__ g,
                          const float* __restrict__ b) {
    __shared__ float shm[9];
    const float* src;
    __half* dst;
    int which = blockIdx.y;
    long long off = (long long)blockIdx.x * CD;
    if (which == 0)      { src = q + off; dst = g_qn + off; }
    else if (which == 1) { src = k + off; dst = g_kn + off; }
    else                 { src = v + off; dst = g_vn + off; }
    int t = threadIdx.x;
    float x = src[t];
    float mean = block_sum256(x, shm) * (1.0f / CD);
    float d = x - mean;
    float var = block_sum256(d * d, shm) * (1.0f / CD);
    float inv = rsqrtf(var + EPS);
    dst[t] = __float2half_rn(d * inv * g[t] + b[t]);
}

// ---------------- transposes (dst is half) -----------------------------------
__global__ void transpose_f2h(const float* __restrict__ src, __half* __restrict__ dst,
                              int R, int C) {
    __shared__ float tile[32][33];
    int tx = threadIdx.x, ty = threadIdx.y;
    int c0 = blockIdx.x * 32, r0 = blockIdx.y * 32;
    #pragma unroll
    for (int j = 0; j < 4; j++)
        tile[ty + 8 * j][tx] = src[(long long)(r0 + ty + 8 * j) * C + c0 + tx];
    __syncthreads();
    #pragma unroll
    for (int j = 0; j < 4; j++)
        dst[(long long)(c0 + ty + 8 * j) * R + r0 + tx] = __float2half_rn(tile[tx][ty + 8 * j]);
}

__global__ void transpose_h2h(const __half* __restrict__ src, __half* __restrict__ dst,
                              int R, int C, long long sstride, long long dstride) {
    __shared__ __half tile[32][34];
    src += (long long)blockIdx.z * sstride;
    dst += (long long)blockIdx.z * dstride;
    int tx = threadIdx.x, ty = threadIdx.y;
    int c0 = blockIdx.x * 32, r0 = blockIdx.y * 32;
    #pragma unroll
    for (int j = 0; j < 4; j++)
        tile[ty + 8 * j][tx] = src[(long long)(r0 + ty + 8 * j) * C + c0 + tx];
    __syncthreads();
    #pragma unroll
    for (int j = 0; j < 4; j++)
        dst[(long long)(c0 + ty + 8 * j) * R + r0 + tx] = tile[tx][ty + 8 * j];
}

// ---------------- softmax: read fp32 scores, write half probs ----------------
__global__ void softmax_kernel() {
    __shared__ float shm[9];
    const float* row = g_attn + (long long)blockIdx.x * ND;
    __half* rowh = g_attnh + (long long)blockIdx.x * ND;
    int t = threadIdx.x;
    float vals[8];
    float m = -INFINITY;
    #pragma unroll
    for (int i = 0; i < 8; i++) {
        vals[i] = row[t + i * 256];
        m = fmaxf(m, vals[i]);
    }
    m = block_max256(m, shm);
    float s = 0.f;
    #pragma unroll
    for (int i = 0; i < 8; i++) {
        vals[i] = __expf(vals[i] - m);
        s += vals[i];
    }
    s = block_sum256(s, shm);
    float inv = 1.0f / s;
    #pragma unroll
    for (int i = 0; i < 8; i++) rowh[t + i * 256] = __float2half_rn(vals[i] * inv);
}

// ---------------- fp16 tensor-core GEMM (NT; 2-stage cp.async pipeline) ------
// C[M,Ntot] = alpha * A[M,K] @ B[Ntot,K]^T (+ bias). A,B half, K-major.
// Block tile 128x128x32, 8 warps (4Mx2N), warp tile 32x64, mma m16n8k16.
// Smem: rows of 32 halves, row stride HS=40 halves (conflict-free frag loads).
#define HS 40
#define STG_HALFS (128 * HS)     // 5120 halves per tile

template<bool HAS_BIAS, bool OUT_HALF>
__global__ __launch_bounds__(256, 2)
void mma_gemm(const __half* __restrict__ A, const __half* __restrict__ B,
              const float* __restrict__ bias, void* __restrict__ CoutV,
              int Ntot, int K, float alpha,
              long long strideA, long long strideB, long long strideC) {
    __shared__ __align__(16) __half smem[4 * STG_HALFS];  // As0|Bs0|As1|Bs1 = 40KB

    A += (long long)blockIdx.z * strideA;
    B += (long long)blockIdx.z * strideB;

    const int tid  = threadIdx.x;
    const int lane = tid & 31;
    const int w    = tid >> 5;
    const int g    = lane >> 2;
    const int tg   = lane & 3;
    const int warpM = (w >> 1) * 32;
    const int warpN = (w & 1) * 64;
    const long long bm = (long long)blockIdx.y * 128;
    const long long bn = (long long)blockIdx.x * 128;

    float acc[2][8][4];
    #pragma unroll
    for (int i = 0; i < 2; i++)
        #pragma unroll
        for (int j = 0; j < 8; j++)
            #pragma unroll
            for (int q_ = 0; q_ < 4; q_++) acc[i][j][q_] = 0.f;

    const int nit = K / 32;

    // fill one stage: two 128x32-half tiles, 2 cp16 per thread per tile
    auto fill = [&](int st, int k0) {
        __half* as = smem + st * 2 * STG_HALFS;
        __half* bs = as + STG_HALFS;
        #pragma unroll
        for (int i = 0; i < 2; i++) {
            int idx = i * 256 + tid;
            int r  = idx >> 2;
            int c8 = (idx & 3) * 8;
            cp16(&as[r * HS + c8], A + (bm + r) * K + k0 + c8);
        }
        #pragma unroll
        for (int i = 0; i < 2; i++) {
            int idx = i * 256 + tid;
            int r  = idx >> 2;
            int c8 = (idx & 3) * 8;
            cp16(&bs[r * HS + c8], B + (bn + r) * K + k0 + c8);
        }
    };

    fill(0, 0);
    cp_commit();

    for (int it = 0; it < nit; it++) {
        if (it + 1 < nit) {
            fill((it + 1) & 1, (it + 1) * 32);
            cp_commit();
            cp_wait<1>();
        } else {
            cp_wait<0>();
        }
        __syncthreads();

        const __half* as = smem + (it & 1) * 2 * STG_HALFS;
        const __half* bs = as + STG_HALFS;

        #pragma unroll
        for (int ks = 0; ks < 2; ks++) {           // two K=16 mma steps
            const int kb = ks * 16;
            unsigned af[2][4];
            #pragma unroll
            for (int mt = 0; mt < 2; mt++) {
                int m = warpM + mt * 16;
                af[mt][0] = *reinterpret_cast<const unsigned*>(&as[(m + g)     * HS + kb + 2 * tg]);
                af[mt][1] = *reinterpret_cast<const unsigned*>(&as[(m + g + 8) * HS + kb + 2 * tg]);
                af[mt][2] = *reinterpret_cast<const unsigned*>(&as[(m + g)     * HS + kb + 8 + 2 * tg]);
                af[mt][3] = *reinterpret_cast<const unsigned*>(&as[(m + g + 8) * HS + kb + 8 + 2 * tg]);
            }
            unsigned bf[8][2];
            #pragma unroll
            for (int nt = 0; nt < 8; nt++) {
                int n = warpN + nt * 8 + g;
                bf[nt][0] = *reinterpret_cast<const unsigned*>(&bs[n * HS + kb + 2 * tg]);
                bf[nt][1] = *reinterpret_cast<const unsigned*>(&bs[n * HS + kb + 8 + 2 * tg]);
            }
            #pragma unroll
            for (int mt = 0; mt < 2; mt++)
                #pragma unroll
                for (int nt = 0; nt < 8; nt++)
                    mma_f16(acc[mt][nt], af[mt], bf[nt]);
        }
        __syncthreads();
    }

    // ---- epilogue ----
    #pragma unroll
    for (int mt = 0; mt < 2; mt++) {
        #pragma unroll
        for (int nt = 0; nt < 8; nt++) {
            long long row0 = bm + warpM + mt * 16 + g;
            long long col  = bn + warpN + nt * 8 + tg * 2;
            float b0 = 0.f, b1 = 0.f;
            if (HAS_BIAS) { b0 = bias[col]; b1 = bias[col + 1]; }
            float o00 = acc[mt][nt][0] * alpha + b0;
            float o01 = acc[mt][nt][1] * alpha + b1;
            float o10 = acc[mt][nt][2] * alpha + b0;
            float o11 = acc[mt][nt][3] * alpha + b1;
            if (OUT_HALF) {
                __half* Cout = (__half*)CoutV + (long long)blockIdx.z * strideC;
                *reinterpret_cast<__half2*>(Cout + row0 * Ntot + col) =
                    __floats2half2_rn(o00, o01);
                *reinterpret_cast<__half2*>(Cout + (row0 + 8) * Ntot + col) =
                    __floats2half2_rn(o10, o11);
            } else {
                float* Cout = (float*)CoutV + (long long)blockIdx.z * strideC;
                *reinterpret_cast<float2*>(Cout + row0 * Ntot + col)       = make_float2(o00, o01);
                *reinterpret_cast<float2*>(Cout + (row0 + 8) * Ntot + col) = make_float2(o10, o11);
            }
        }
    }
}

// ---------------- launch ----------------------------------------------------
extern "C" void kernel_launch(void* const* d_in, const int* in_sizes, int n_in,
                              void* d_out, int out_size) {
    const float* q    = (const float*)d_in[0];
    const float* k    = (const float*)d_in[1];
    const float* v    = (const float*)d_in[2];
    const float* ln_g = (const float*)d_in[3];
    const float* ln_b = (const float*)d_in[4];
    const float* Wq   = (const float*)d_in[5];
    const float* bq   = (const float*)d_in[6];
    const float* Wk   = (const float*)d_in[7];
    const float* bk   = (const float*)d_in[8];
    const float* Wv   = (const float*)d_in[9];
    const float* bv   = (const float*)d_in[10];
    const float* Wo   = (const float*)d_in[11];
    const float* bo   = (const float*)d_in[12];
    float* out = (float*)d_out;

    __half *qn, *kn, *vn, *qp, *kp, *vp, *vpt, *attnh, *x, *wqt, *wkt, *wvt, *wot;
    float *attn;
    cudaGetSymbolAddress((void**)&qn, g_qn);
    cudaGetSymbolAddress((void**)&kn, g_kn);
    cudaGetSymbolAddress((void**)&vn, g_vn);
    cudaGetSymbolAddress((void**)&qp, g_qp);
    cudaGetSymbolAddress((void**)&kp, g_kp);
    cudaGetSymbolAddress((void**)&vp, g_vp);
    cudaGetSymbolAddress((void**)&vpt, g_vpt);
    cudaGetSymbolAddress((void**)&attn, g_attn);
    cudaGetSymbolAddress((void**)&attnh, g_attnh);
    cudaGetSymbolAddress((void**)&x, g_x);
    cudaGetSymbolAddress((void**)&wqt, g_wqt);
    cudaGetSymbolAddress((void**)&wkt, g_wkt);
    cudaGetSymbolAddress((void**)&wvt, g_wvt);
    cudaGetSymbolAddress((void**)&wot, g_wot);

    // 0. transpose weights to [N,K] half
    transpose_f2h<<<dim3(INNER / 32, CD / 32), dim3(32, 8)>>>(Wq, wqt, CD, INNER);
    transpose_f2h<<<dim3(INNER / 32, CD / 32), dim3(32, 8)>>>(Wk, wkt, CD, INNER);
    transpose_f2h<<<dim3(INNER / 32, CD / 32), dim3(32, 8)>>>(Wv, wvt, CD, INNER);
    transpose_f2h<<<dim3(CD / 32, INNER / 32), dim3(32, 8)>>>(Wo, wot, INNER, CD);

    // 1. LayerNorm q,k,v (half out)
    ln_kernel<<<dim3(ROWS, 3), 256>>>(q, k, v, ln_g, ln_b);

    // 2. Projections: A[8192,256] @ Wt[1024,256]^T + bias -> half
    {
        dim3 grid(INNER / 128, ROWS / 128, 1);
        mma_gemm<true, true><<<grid, 256>>>(qn, wqt, bq, qp, INNER, CD, 1.0f, 0, 0, 0);
        mma_gemm<true, true><<<grid, 256>>>(kn, wkt, bk, kp, INNER, CD, 1.0f, 0, 0, 0);
        mma_gemm<true, true><<<grid, 256>>>(vn, wvt, bv, vp, INNER, CD, 1.0f, 0, 0, 0);
    }

    // 3. Scores: per batch qp[2048,1024] @ kp[2048,1024]^T * SCALE -> fp32
    {
        dim3 grid(ND / 128, ND / 128, BD);
        mma_gemm<false, false><<<grid, 256>>>(
            qp, kp, nullptr, attn, ND, INNER, ATT_SCALE,
            (long long)ND * INNER, (long long)ND * INNER, (long long)ND * ND);
    }

    // 4. Softmax rows (fp32 in, half out)
    softmax_kernel<<<BD * ND, 256>>>();

    // 5. transpose vp -> vpt per batch: [2048,1024] -> [1024,2048]
    transpose_h2h<<<dim3(INNER / 32, ND / 32, BD), dim3(32, 8)>>>(
        vp, vpt, ND, INNER, (long long)ND * INNER, (long long)ND * INNER);

    // 6. AV: per batch attnh[2048,2048] @ vpt[1024,2048]^T -> half
    {
        dim3 grid(INNER / 128, ND / 128, BD);
        mma_gemm<false, true><<<grid, 256>>>(
            attnh, vpt, nullptr, x, INNER, ND, 1.0f,
            (long long)ND * ND, (long long)ND * INNER, (long long)ND * INNER);
    }

    // 7. Output projection: x[8192,1024] @ wot[256,1024]^T + bias -> fp32 out
    {
        dim3 grid(CD / 128, ROWS / 128, 1);
        mma_gemm<true, false><<<grid, 256>>>(x, wot, bo, out, CD, INNER, 1.0f, 0, 0, 0);
    }
}

// round 9
// speedup vs baseline: 2.6770x; 1.1322x over previous
#include <cuda_runtime.h>
#include <cuda_fp16.h>
#include <math.h>
#include <stdint.h>

// Problem constants
#define BD 4
#define ND 2048
#define CD 256
#define INNER 1024
#define ROWS (BD*ND)          // 8192
#define EPS 1e-5f
#define ATT_SCALE 0.125f      // 64^-0.5

// ---------------- scratch (device globals; allocation-free rule) -------------
__device__ __half g_qn[ROWS*CD];
__device__ __half g_kn[ROWS*CD];
__device__ __half g_vn[ROWS*CD];
__device__ __half g_qp[ROWS*INNER];
__device__ __half g_kp[ROWS*INNER];
__device__ __half g_vp[ROWS*INNER];
__device__ __half g_vpt[ROWS*INNER];            // vp^T per batch [INNER, ND]
__device__ float  g_attn[(long long)BD*ND*ND];  // raw fp32 scores, 64 MB
__device__ __half g_attnh[(long long)BD*ND*ND]; // softmaxed probs, half, 32 MB
__device__ __half g_x[ROWS*INNER];
__device__ __half g_wqt[INNER*CD];              // Wq^T [1024,256]
__device__ __half g_wkt[INNER*CD];
__device__ __half g_wvt[INNER*CD];
__device__ __half g_wot[CD*INNER];              // Wo^T [256,1024]

// ---------------- helpers ----------------
__device__ __forceinline__ float warp_sum(float v) {
    #pragma unroll
    for (int o = 16; o; o >>= 1) v += __shfl_xor_sync(0xffffffffu, v, o);
    return v;
}
__device__ __forceinline__ float warp_max(float v) {
    #pragma unroll
    for (int o = 16; o; o >>= 1) v = fmaxf(v, __shfl_xor_sync(0xffffffffu, v, o));
    return v;
}
__device__ __forceinline__ float block_sum256(float v, float* shm) {
    v = warp_sum(v);
    int w = threadIdx.x >> 5;
    if ((threadIdx.x & 31) == 0) shm[w] = v;
    __syncthreads();
    if (threadIdx.x == 0) {
        float s = 0.f;
        #pragma unroll
        for (int i = 0; i < 8; i++) s += shm[i];
        shm[8] = s;
    }
    __syncthreads();
    float r = shm[8];
    __syncthreads();
    return r;
}
__device__ __forceinline__ float block_max256(float v, float* shm) {
    v = warp_max(v);
    int w = threadIdx.x >> 5;
    if ((threadIdx.x & 31) == 0) shm[w] = v;
    __syncthreads();
    if (threadIdx.x == 0) {
        float m = shm[0];
        #pragma unroll
        for (int i = 1; i < 8; i++) m = fmaxf(m, shm[i]);
        shm[8] = m;
    }
    __syncthreads();
    float r = shm[8];
    __syncthreads();
    return r;
}

// mma m16n8k16: f32 acc, f16 inputs
__device__ __forceinline__ void mma_f16(float* c, const unsigned* a, const unsigned* b) {
    asm volatile(
        "mma.sync.aligned.m16n8k16.row.col.f32.f16.f16.f32 "
        "{%0,%1,%2,%3}, {%4,%5,%6,%7}, {%8,%9}, {%0,%1,%2,%3};"
        : "+f"(c[0]), "+f"(c[1]), "+f"(c[2]), "+f"(c[3])
        : "r"(a[0]), "r"(a[1]), "r"(a[2]), "r"(a[3]), "r"(b[0]), "r"(b[1]));
}

__device__ __forceinline__ void cp16(void* smem_dst, const void* gmem_src) {
    unsigned s = (unsigned)__cvta_generic_to_shared(smem_dst);
    asm volatile("cp.async.cg.shared.global [%0], [%1], 16;" :: "r"(s), "l"(gmem_src));
}
__device__ __forceinline__ void cp_commit() {
    asm volatile("cp.async.commit_group;");
}
template<int NN>
__device__ __forceinline__ void cp_wait() {
    asm volatile("cp.async.wait_group %0;" :: "n"(NN));
}

// ---------------- LayerNorm (writes half) ------------------------------------
__global__ void ln_kernel(const float* __restrict__ q, const float* __restrict__ k,
                          const float* __restrict__ v, const float* __restrict__ g,
                          const float* __restrict__ b) {
    __shared__ float shm[9];
    const float* src;
    __half* dst;
    int which = blockIdx.y;
    long long off = (long long)blockIdx.x * CD;
    if (which == 0)      { src = q + off; dst = g_qn + off; }
    else if (which == 1) { src = k + off; dst = g_kn + off; }
    else                 { src = v + off; dst = g_vn + off; }
    int t = threadIdx.x;
    float x = src[t];
    float mean = block_sum256(x, shm) * (1.0f / CD);
    float d = x - mean;
    float var = block_sum256(d * d, shm) * (1.0f / CD);
    float inv = rsqrtf(var + EPS);
    dst[t] = __float2half_rn(d * inv * g[t] + b[t]);
}

// ---------------- transposes -------------------------------------------------
__global__ void transpose_f2h(const float* __restrict__ src, __half* __restrict__ dst,
                              int R, int C) {
    __shared__ float tile[32][33];
    int tx = threadIdx.x, ty = threadIdx.y;
    int c0 = blockIdx.x * 32, r0 = blockIdx.y * 32;
    #pragma unroll
    for (int j = 0; j < 4; j++)
        tile[ty + 8 * j][tx] = src[(long long)(r0 + ty + 8 * j) * C + c0 + tx];
    __syncthreads();
    #pragma unroll
    for (int j = 0; j < 4; j++)
        dst[(long long)(c0 + ty + 8 * j) * R + r0 + tx] = __float2half_rn(tile[tx][ty + 8 * j]);
}

__global__ void transpose_h2h(const __half* __restrict__ src, __half* __restrict__ dst,
                              int R, int C, long long sstride, long long dstride) {
    __shared__ __half tile[32][34];
    src += (long long)blockIdx.z * sstride;
    dst += (long long)blockIdx.z * dstride;
    int tx = threadIdx.x, ty = threadIdx.y;
    int c0 = blockIdx.x * 32, r0 = blockIdx.y * 32;
    #pragma unroll
    for (int j = 0; j < 4; j++)
        tile[ty + 8 * j][tx] = src[(long long)(r0 + ty + 8 * j) * C + c0 + tx];
    __syncthreads();
    #pragma unroll
    for (int j = 0; j < 4; j++)
        dst[(long long)(c0 + ty + 8 * j) * R + r0 + tx] = tile[tx][ty + 8 * j];
}

// ---------------- softmax: read fp32 scores, write half probs ----------------
__global__ void softmax_kernel() {
    __shared__ float shm[9];
    const float* row = g_attn + (long long)blockIdx.x * ND;
    __half* rowh = g_attnh + (long long)blockIdx.x * ND;
    int t = threadIdx.x;
    float vals[8];
    float m = -INFINITY;
    #pragma unroll
    for (int i = 0; i < 8; i++) {
        vals[i] = row[t + i * 256];
        m = fmaxf(m, vals[i]);
    }
    m = block_max256(m, shm);
    float s = 0.f;
    #pragma unroll
    for (int i = 0; i < 8; i++) {
        vals[i] = __expf(vals[i] - m);
        s += vals[i];
    }
    s = block_sum256(s, shm);
    float inv = 1.0f / s;
    #pragma unroll
    for (int i = 0; i < 8; i++) rowh[t + i * 256] = __float2half_rn(vals[i] * inv);
}

// ---------------- fp16 tensor-core GEMM (NT; 2-stage BK=64 pipeline) ---------
// C[M,Ntot] = alpha * A[M,K] @ B[Ntot,K]^T (+ bias). A,B half, K-major.
// Block tile 128x128x64, 8 warps (4Mx2N), warp tile 32x64, mma m16n8k16.
// Smem rows of 64 halves, stride HS=72 (fragment bank = 4r+tg, conflict-free).
#define HS 72
#define STG_HALFS (128 * HS)                 // 9216 halves per tile
#define PIPE_SMEM (4 * STG_HALFS * 2)        // 2 stages x (A+B) = 73728 bytes

template<bool HAS_BIAS, bool OUT_HALF>
__global__ __launch_bounds__(256, 2)
void mma_gemm(const __half* __restrict__ A, const __half* __restrict__ B,
              const float* __restrict__ bias, void* __restrict__ CoutV,
              int Ntot, int K, float alpha,
              long long strideA, long long strideB, long long strideC) {
    extern __shared__ __align__(16) __half smem[];   // As0|Bs0|As1|Bs1

    A += (long long)blockIdx.z * strideA;
    B += (long long)blockIdx.z * strideB;

    const int tid  = threadIdx.x;
    const int lane = tid & 31;
    const int w    = tid >> 5;
    const int g    = lane >> 2;
    const int tg   = lane & 3;
    const int warpM = (w >> 1) * 32;
    const int warpN = (w & 1) * 64;
    const long long bm = (long long)blockIdx.y * 128;
    const long long bn = (long long)blockIdx.x * 128;

    float acc[2][8][4];
    #pragma unroll
    for (int i = 0; i < 2; i++)
        #pragma unroll
        for (int j = 0; j < 8; j++)
            #pragma unroll
            for (int q_ = 0; q_ < 4; q_++) acc[i][j][q_] = 0.f;

    const int nit = K / 64;

    // fill one BK=64 stage: 4 cp16 per thread per tile
    auto fill = [&](int st, int k0) {
        __half* as = smem + st * 2 * STG_HALFS;
        __half* bs = as + STG_HALFS;
        #pragma unroll
        for (int i = 0; i < 4; i++) {
            int idx = i * 256 + tid;
            int r  = idx >> 3;
            int c8 = (idx & 7) * 8;
            cp16(&as[r * HS + c8], A + (bm + r) * K + k0 + c8);
        }
        #pragma unroll
        for (int i = 0; i < 4; i++) {
            int idx = i * 256 + tid;
            int r  = idx >> 3;
            int c8 = (idx & 7) * 8;
            cp16(&bs[r * HS + c8], B + (bn + r) * K + k0 + c8);
        }
    };

    fill(0, 0);
    cp_commit();

    for (int it = 0; it < nit; it++) {
        if (it + 1 < nit) {
            fill((it + 1) & 1, (it + 1) * 64);
            cp_commit();
            cp_wait<1>();
        } else {
            cp_wait<0>();
        }
        __syncthreads();

        const __half* as = smem + (it & 1) * 2 * STG_HALFS;
        const __half* bs = as + STG_HALFS;

        #pragma unroll
        for (int ks = 0; ks < 4; ks++) {           // four K=16 mma steps
            const int kb = ks * 16;
            unsigned af[2][4];
            #pragma unroll
            for (int mt = 0; mt < 2; mt++) {
                int m = warpM + mt * 16;
                af[mt][0] = *reinterpret_cast<const unsigned*>(&as[(m + g)     * HS + kb + 2 * tg]);
                af[mt][1] = *reinterpret_cast<const unsigned*>(&as[(m + g + 8) * HS + kb + 2 * tg]);
                af[mt][2] = *reinterpret_cast<const unsigned*>(&as[(m + g)     * HS + kb + 8 + 2 * tg]);
                af[mt][3] = *reinterpret_cast<const unsigned*>(&as[(m + g + 8) * HS + kb + 8 + 2 * tg]);
            }
            unsigned bf[8][2];
            #pragma unroll
            for (int nt = 0; nt < 8; nt++) {
                int n = warpN + nt * 8 + g;
                bf[nt][0] = *reinterpret_cast<const unsigned*>(&bs[n * HS + kb + 2 * tg]);
                bf[nt][1] = *reinterpret_cast<const unsigned*>(&bs[n * HS + kb + 8 + 2 * tg]);
            }
            #pragma unroll
            for (int mt = 0; mt < 2; mt++)
                #pragma unroll
                for (int nt = 0; nt < 8; nt++)
                    mma_f16(acc[mt][nt], af[mt], bf[nt]);
        }
        __syncthreads();
    }

    // ---- epilogue ----
    #pragma unroll
    for (int mt = 0; mt < 2; mt++) {
        #pragma unroll
        for (int nt = 0; nt < 8; nt++) {
            long long row0 = bm + warpM + mt * 16 + g;
            long long col  = bn + warpN + nt * 8 + tg * 2;
            float b0 = 0.f, b1 = 0.f;
            if (HAS_BIAS) { b0 = bias[col]; b1 = bias[col + 1]; }
            float o00 = acc[mt][nt][0] * alpha + b0;
            float o01 = acc[mt][nt][1] * alpha + b1;
            float o10 = acc[mt][nt][2] * alpha + b0;
            float o11 = acc[mt][nt][3] * alpha + b1;
            if (OUT_HALF) {
                __half* Cout = (__half*)CoutV + (long long)blockIdx.z * strideC;
                *reinterpret_cast<__half2*>(Cout + row0 * Ntot + col) =
                    __floats2half2_rn(o00, o01);
                *reinterpret_cast<__half2*>(Cout + (row0 + 8) * Ntot + col) =
                    __floats2half2_rn(o10, o11);
            } else {
                float* Cout = (float*)CoutV + (long long)blockIdx.z * strideC;
                *reinterpret_cast<float2*>(Cout + row0 * Ntot + col)       = make_float2(o00, o01);
                *reinterpret_cast<float2*>(Cout + (row0 + 8) * Ntot + col) = make_float2(o10, o11);
            }
        }
    }
}

// ---------------- launch ----------------------------------------------------
extern "C" void kernel_launch(void* const* d_in, const int* in_sizes, int n_in,
                              void* d_out, int out_size) {
    const float* q    = (const float*)d_in[0];
    const float* k    = (const float*)d_in[1];
    const float* v    = (const float*)d_in[2];
    const float* ln_g = (const float*)d_in[3];
    const float* ln_b = (const float*)d_in[4];
    const float* Wq   = (const float*)d_in[5];
    const float* bq   = (const float*)d_in[6];
    const float* Wk   = (const float*)d_in[7];
    const float* bk   = (const float*)d_in[8];
    const float* Wv   = (const float*)d_in[9];
    const float* bv   = (const float*)d_in[10];
    const float* Wo   = (const float*)d_in[11];
    const float* bo   = (const float*)d_in[12];
    float* out = (float*)d_out;

    __half *qn, *kn, *vn, *qp, *kp, *vp, *vpt, *attnh, *x, *wqt, *wkt, *wvt, *wot;
    float *attn;
    cudaGetSymbolAddress((void**)&qn, g_qn);
    cudaGetSymbolAddress((void**)&kn, g_kn);
    cudaGetSymbolAddress((void**)&vn, g_vn);
    cudaGetSymbolAddress((void**)&qp, g_qp);
    cudaGetSymbolAddress((void**)&kp, g_kp);
    cudaGetSymbolAddress((void**)&vp, g_vp);
    cudaGetSymbolAddress((void**)&vpt, g_vpt);
    cudaGetSymbolAddress((void**)&attn, g_attn);
    cudaGetSymbolAddress((void**)&attnh, g_attnh);
    cudaGetSymbolAddress((void**)&x, g_x);
    cudaGetSymbolAddress((void**)&wqt, g_wqt);
    cudaGetSymbolAddress((void**)&wkt, g_wkt);
    cudaGetSymbolAddress((void**)&wvt, g_wvt);
    cudaGetSymbolAddress((void**)&wot, g_wot);

    cudaFuncSetAttribute(mma_gemm<true,  true >, cudaFuncAttributeMaxDynamicSharedMemorySize, PIPE_SMEM);
    cudaFuncSetAttribute(mma_gemm<false, false>, cudaFuncAttributeMaxDynamicSharedMemorySize, PIPE_SMEM);
    cudaFuncSetAttribute(mma_gemm<false, true >, cudaFuncAttributeMaxDynamicSharedMemorySize, PIPE_SMEM);
    cudaFuncSetAttribute(mma_gemm<true,  false>, cudaFuncAttributeMaxDynamicSharedMemorySize, PIPE_SMEM);

    // 0. transpose weights to [N,K] half
    transpose_f2h<<<dim3(INNER / 32, CD / 32), dim3(32, 8)>>>(Wq, wqt, CD, INNER);
    transpose_f2h<<<dim3(INNER / 32, CD / 32), dim3(32, 8)>>>(Wk, wkt, CD, INNER);
    transpose_f2h<<<dim3(INNER / 32, CD / 32), dim3(32, 8)>>>(Wv, wvt, CD, INNER);
    transpose_f2h<<<dim3(CD / 32, INNER / 32), dim3(32, 8)>>>(Wo, wot, INNER, CD);

    // 1. LayerNorm q,k,v (half out)
    ln_kernel<<<dim3(ROWS, 3), 256>>>(q, k, v, ln_g, ln_b);

    // 2. Projections: A[8192,256] @ Wt[1024,256]^T + bias -> half
    {
        dim3 grid(INNER / 128, ROWS / 128, 1);
        mma_gemm<true, true><<<grid, 256, PIPE_SMEM>>>(qn, wqt, bq, qp, INNER, CD, 1.0f, 0, 0, 0);
        mma_gemm<true, true><<<grid, 256, PIPE_SMEM>>>(kn, wkt, bk, kp, INNER, CD, 1.0f, 0, 0, 0);
        mma_gemm<true, true><<<grid, 256, PIPE_SMEM>>>(vn, wvt, bv, vp, INNER, CD, 1.0f, 0, 0, 0);
    }

    // 3. Scores: per batch qp[2048,1024] @ kp[2048,1024]^T * SCALE -> fp32
    {
        dim3 grid(ND / 128, ND / 128, BD);
        mma_gemm<false, false><<<grid, 256, PIPE_SMEM>>>(
            qp, kp, nullptr, attn, ND, INNER, ATT_SCALE,
            (long long)ND * INNER, (long long)ND * INNER, (long long)ND * ND);
    }

    // 4. Softmax rows (fp32 in, half out)
    softmax_kernel<<<BD * ND, 256>>>();

    // 5. transpose vp -> vpt per batch: [2048,1024] -> [1024,2048]
    transpose_h2h<<<dim3(INNER / 32, ND / 32, BD), dim3(32, 8)>>>(
        vp, vpt, ND, INNER, (long long)ND * INNER, (long long)ND * INNER);

    // 6. AV: per batch attnh[2048,2048] @ vpt[1024,2048]^T -> half
    {
        dim3 grid(INNER / 128, ND / 128, BD);
        mma_gemm<false, true><<<grid, 256, PIPE_SMEM>>>(
            attnh, vpt, nullptr, x, INNER, ND, 1.0f,
            (long long)ND * ND, (long long)ND * INNER, (long long)ND * INNER);
    }

    // 7. Output projection: x[8192,1024] @ wot[256,1024]^T + bias -> fp32 out
    {
        dim3 grid(CD / 128, ROWS / 128, 1);
        mma_gemm<true, false><<<grid, 256, PIPE_SMEM>>>(x, wot, bo, out, CD, INNER, 1.0f, 0, 0, 0);
    }
}

// round 10
// speedup vs baseline: 2.8257x; 1.0555x over previous
#include <cuda_runtime.h>
#include <cuda_fp16.h>
#include <math.h>
#include <stdint.h>

// Problem constants
#define BD 4
#define ND 2048
#define CD 256
#define INNER 1024
#define ROWS (BD*ND)          // 8192
#define EPS 1e-5f
#define ATT_SCALE 0.125f      // 64^-0.5

// ---------------- scratch (device globals; allocation-free rule) -------------
__device__ __half g_qn[ROWS*CD];
__device__ __half g_kn[ROWS*CD];
__device__ __half g_vn[ROWS*CD];
__device__ __half g_qp[ROWS*INNER];
__device__ __half g_kp[ROWS*INNER];
__device__ __half g_vp[ROWS*INNER];
__device__ __half g_vpt[ROWS*INNER];            // vp^T per batch [INNER, ND]
__device__ float  g_attn[(long long)BD*ND*ND];  // raw fp32 scores, 64 MB
__device__ __half g_attnh[(long long)BD*ND*ND]; // softmaxed probs, half, 32 MB
__device__ __half g_x[ROWS*INNER];
__device__ __half g_wqt[INNER*CD];              // Wq^T [1024,256]
__device__ __half g_wkt[INNER*CD];
__device__ __half g_wvt[INNER*CD];
__device__ __half g_wot[CD*INNER];              // Wo^T [256,1024]

// ---------------- helpers ----------------
__device__ __forceinline__ float warp_sum(float v) {
    #pragma unroll
    for (int o = 16; o; o >>= 1) v += __shfl_xor_sync(0xffffffffu, v, o);
    return v;
}
__device__ __forceinline__ float warp_max(float v) {
    #pragma unroll
    for (int o = 16; o; o >>= 1) v = fmaxf(v, __shfl_xor_sync(0xffffffffu, v, o));
    return v;
}
__device__ __forceinline__ float block_sum256(float v, float* shm) {
    v = warp_sum(v);
    int w = threadIdx.x >> 5;
    if ((threadIdx.x & 31) == 0) shm[w] = v;
    __syncthreads();
    if (threadIdx.x == 0) {
        float s = 0.f;
        #pragma unroll
        for (int i = 0; i < 8; i++) s += shm[i];
        shm[8] = s;
    }
    __syncthreads();
    float r = shm[8];
    __syncthreads();
    return r;
}
__device__ __forceinline__ float block_max256(float v, float* shm) {
    v = warp_max(v);
    int w = threadIdx.x >> 5;
    if ((threadIdx.x & 31) == 0) shm[w] = v;
    __syncthreads();
    if (threadIdx.x == 0) {
        float m = shm[0];
        #pragma unroll
        for (int i = 1; i < 8; i++) m = fmaxf(m, shm[i]);
        shm[8] = m;
    }
    __syncthreads();
    float r = shm[8];
    __syncthreads();
    return r;
}

// mma m16n8k16: f32 acc, f16 inputs
__device__ __forceinline__ void mma_f16(float* c, const unsigned* a, const unsigned* b) {
    asm volatile(
        "mma.sync.aligned.m16n8k16.row.col.f32.f16.f16.f32 "
        "{%0,%1,%2,%3}, {%4,%5,%6,%7}, {%8,%9}, {%0,%1,%2,%3};"
        : "+f"(c[0]), "+f"(c[1]), "+f"(c[2]), "+f"(c[3])
        : "r"(a[0]), "r"(a[1]), "r"(a[2]), "r"(a[3]), "r"(b[0]), "r"(b[1]));
}

__device__ __forceinline__ void ldsm_x4(unsigned& r0, unsigned& r1, unsigned& r2, unsigned& r3,
                                        unsigned addr) {
    asm volatile("ldmatrix.sync.aligned.m8n8.x4.shared.b16 {%0,%1,%2,%3}, [%4];"
                 : "=r"(r0), "=r"(r1), "=r"(r2), "=r"(r3) : "r"(addr));
}

__device__ __forceinline__ void cp16(void* smem_dst, const void* gmem_src) {
    unsigned s = (unsigned)__cvta_generic_to_shared(smem_dst);
    asm volatile("cp.async.cg.shared.global [%0], [%1], 16;" :: "r"(s), "l"(gmem_src));
}
__device__ __forceinline__ void cp_commit() {
    asm volatile("cp.async.commit_group;");
}
template<int NN>
__device__ __forceinline__ void cp_wait() {
    asm volatile("cp.async.wait_group %0;" :: "n"(NN));
}

// ---------------- LayerNorm (writes half) ------------------------------------
__global__ void ln_kernel(const float* __restrict__ q, const float* __restrict__ k,
                          const float* __restrict__ v, const float* __restrict__ g,
                          const float* __restrict__ b) {
    __shared__ float shm[9];
    const float* src;
    __half* dst;
    int which = blockIdx.y;
    long long off = (long long)blockIdx.x * CD;
    if (which == 0)      { src = q + off; dst = g_qn + off; }
    else if (which == 1) { src = k + off; dst = g_kn + off; }
    else                 { src = v + off; dst = g_vn + off; }
    int t = threadIdx.x;
    float x = src[t];
    float mean = block_sum256(x, shm) * (1.0f / CD);
    float d = x - mean;
    float var = block_sum256(d * d, shm) * (1.0f / CD);
    float inv = rsqrtf(var + EPS);
    dst[t] = __float2half_rn(d * inv * g[t] + b[t]);
}

// ---------------- transposes -------------------------------------------------
__global__ void transpose_f2h(const float* __restrict__ src, __half* __restrict__ dst,
                              int R, int C) {
    __shared__ float tile[32][33];
    int tx = threadIdx.x, ty = threadIdx.y;
    int c0 = blockIdx.x * 32, r0 = blockIdx.y * 32;
    #pragma unroll
    for (int j = 0; j < 4; j++)
        tile[ty + 8 * j][tx] = src[(long long)(r0 + ty + 8 * j) * C + c0 + tx];
    __syncthreads();
    #pragma unroll
    for (int j = 0; j < 4; j++)
        dst[(long long)(c0 + ty + 8 * j) * R + r0 + tx] = __float2half_rn(tile[tx][ty + 8 * j]);
}

__global__ void transpose_h2h(const __half* __restrict__ src, __half* __restrict__ dst,
                              int R, int C, long long sstride, long long dstride) {
    __shared__ __half tile[32][34];
    src += (long long)blockIdx.z * sstride;
    dst += (long long)blockIdx.z * dstride;
    int tx = threadIdx.x, ty = threadIdx.y;
    int c0 = blockIdx.x * 32, r0 = blockIdx.y * 32;
    #pragma unroll
    for (int j = 0; j < 4; j++)
        tile[ty + 8 * j][tx] = src[(long long)(r0 + ty + 8 * j) * C + c0 + tx];
    __syncthreads();
    #pragma unroll
    for (int j = 0; j < 4; j++)
        dst[(long long)(c0 + ty + 8 * j) * R + r0 + tx] = tile[tx][ty + 8 * j];
}

// ---------------- softmax: read fp32 scores, write half probs ----------------
__global__ void softmax_kernel() {
    __shared__ float shm[9];
    const float* row = g_attn + (long long)blockIdx.x * ND;
    __half* rowh = g_attnh + (long long)blockIdx.x * ND;
    int t = threadIdx.x;
    float vals[8];
    float m = -INFINITY;
    #pragma unroll
    for (int i = 0; i < 8; i++) {
        vals[i] = row[t + i * 256];
        m = fmaxf(m, vals[i]);
    }
    m = block_max256(m, shm);
    float s = 0.f;
    #pragma unroll
    for (int i = 0; i < 8; i++) {
        vals[i] = __expf(vals[i] - m);
        s += vals[i];
    }
    s = block_sum256(s, shm);
    float inv = 1.0f / s;
    #pragma unroll
    for (int i = 0; i < 8; i++) rowh[t + i * 256] = __float2half_rn(vals[i] * inv);
}

// ---------------- fp16 tensor-core GEMM (NT; BK=64 pipeline + ldmatrix) ------
// C[M,Ntot] = alpha * A[M,K] @ B[Ntot,K]^T (+ bias). A,B half, K-major.
// Block tile 128x128x64, 8 warps (4Mx2N), warp tile 32x64, mma m16n8k16.
// Smem rows of 64 halves, stride HS=72; ldmatrix row-phase spans all 32 banks.
#define HS 72
#define STG_HALFS (128 * HS)                 // 9216 halves per tile
#define PIPE_SMEM (4 * STG_HALFS * 2)        // 2 stages x (A+B) = 73728 bytes

template<bool HAS_BIAS, bool OUT_HALF>
__global__ __launch_bounds__(256, 2)
void mma_gemm(const __half* __restrict__ A, const __half* __restrict__ B,
              const float* __restrict__ bias, void* __restrict__ CoutV,
              int Ntot, int K, float alpha,
              long long strideA, long long strideB, long long strideC) {
    extern __shared__ __align__(16) __half smem[];   // As0|Bs0|As1|Bs1

    A += (long long)blockIdx.z * strideA;
    B += (long long)blockIdx.z * strideB;

    const int tid  = threadIdx.x;
    const int lane = tid & 31;
    const int w    = tid >> 5;
    const int g    = lane >> 2;
    const int tg   = lane & 3;
    const int warpM = (w >> 1) * 32;
    const int warpN = (w & 1) * 64;
    const long long bm = (long long)blockIdx.y * 128;
    const long long bn = (long long)blockIdx.x * 128;

    // ldmatrix per-lane byte offsets (within a tile)
    const int quad = lane >> 3;          // 0..3
    const int r8   = lane & 7;           // 0..7
    // A x4 (mt block): mat0 m0-7/k0-7, mat1 m8-15/k0-7, mat2 m0-7/k8-15, mat3 m8-15/k8-15
    const unsigned a_off0 = ((warpM + (quad & 1) * 8 + r8) * HS + (quad >> 1) * 8) * 2u;
    const unsigned a_off1 = a_off0 + 16u * HS * 2u;
    // B x4 (nt pair j): mat0 nt=2j/k0-7, mat1 nt=2j/k8-15, mat2 nt=2j+1/k0-7, mat3 nt=2j+1/k8-15
    unsigned b_off[4];
    #pragma unroll
    for (int j = 0; j < 4; j++)
        b_off[j] = ((warpN + (2 * j + (quad >> 1)) * 8 + r8) * HS + (quad & 1) * 8) * 2u;

    const unsigned smem_u = (unsigned)__cvta_generic_to_shared(smem);

    float acc[2][8][4];
    #pragma unroll
    for (int i = 0; i < 2; i++)
        #pragma unroll
        for (int j = 0; j < 8; j++)
            #pragma unroll
            for (int q_ = 0; q_ < 4; q_++) acc[i][j][q_] = 0.f;

    const int nit = K / 64;

    // fill one BK=64 stage: 4 cp16 per thread per tile
    auto fill = [&](int st, int k0) {
        __half* as = smem + st * 2 * STG_HALFS;
        __half* bs = as + STG_HALFS;
        #pragma unroll
        for (int i = 0; i < 4; i++) {
            int idx = i * 256 + tid;
            int r  = idx >> 3;
            int c8 = (idx & 7) * 8;
            cp16(&as[r * HS + c8], A + (bm + r) * K + k0 + c8);
        }
        #pragma unroll
        for (int i = 0; i < 4; i++) {
            int idx = i * 256 + tid;
            int r  = idx >> 3;
            int c8 = (idx & 7) * 8;
            cp16(&bs[r * HS + c8], B + (bn + r) * K + k0 + c8);
        }
    };

    fill(0, 0);
    cp_commit();

    for (int it = 0; it < nit; it++) {
        if (it + 1 < nit) {
            fill((it + 1) & 1, (it + 1) * 64);
            cp_commit();
            cp_wait<1>();
        } else {
            cp_wait<0>();
        }
        __syncthreads();

        const unsigned as_u = smem_u + (it & 1) * (2u * STG_HALFS * 2u);
        const unsigned bs_u = as_u + STG_HALFS * 2u;

        #pragma unroll
        for (int ks = 0; ks < 4; ks++) {           // four K=16 mma steps
            const unsigned kbB = ks * 16u * 2u;    // k offset in bytes
            unsigned af[2][4];
            ldsm_x4(af[0][0], af[0][1], af[0][2], af[0][3], as_u + a_off0 + kbB);
            ldsm_x4(af[1][0], af[1][1], af[1][2], af[1][3], as_u + a_off1 + kbB);
            unsigned bf[8][2];
            #pragma unroll
            for (int j = 0; j < 4; j++)
                ldsm_x4(bf[2 * j][0], bf[2 * j][1], bf[2 * j + 1][0], bf[2 * j + 1][1],
                        bs_u + b_off[j] + kbB);
            #pragma unroll
            for (int mt = 0; mt < 2; mt++)
                #pragma unroll
                for (int nt = 0; nt < 8; nt++)
                    mma_f16(acc[mt][nt], af[mt], bf[nt]);
        }
        __syncthreads();
    }

    // ---- epilogue ----
    #pragma unroll
    for (int mt = 0; mt < 2; mt++) {
        #pragma unroll
        for (int nt = 0; nt < 8; nt++) {
            long long row0 = bm + warpM + mt * 16 + g;
            long long col  = bn + warpN + nt * 8 + tg * 2;
            float b0 = 0.f, b1 = 0.f;
            if (HAS_BIAS) { b0 = bias[col]; b1 = bias[col + 1]; }
            float o00 = acc[mt][nt][0] * alpha + b0;
            float o01 = acc[mt][nt][1] * alpha + b1;
            float o10 = acc[mt][nt][2] * alpha + b0;
            float o11 = acc[mt][nt][3] * alpha + b1;
            if (OUT_HALF) {
                __half* Cout = (__half*)CoutV + (long long)blockIdx.z * strideC;
                *reinterpret_cast<__half2*>(Cout + row0 * Ntot + col) =
                    __floats2half2_rn(o00, o01);
                *reinterpret_cast<__half2*>(Cout + (row0 + 8) * Ntot + col) =
                    __floats2half2_rn(o10, o11);
            } else {
                float* Cout = (float*)CoutV + (long long)blockIdx.z * strideC;
                *reinterpret_cast<float2*>(Cout + row0 * Ntot + col)       = make_float2(o00, o01);
                *reinterpret_cast<float2*>(Cout + (row0 + 8) * Ntot + col) = make_float2(o10, o11);
            }
        }
    }
}

// ---------------- launch ----------------------------------------------------
extern "C" void kernel_launch(void* const* d_in, const int* in_sizes, int n_in,
                              void* d_out, int out_size) {
    const float* q    = (const float*)d_in[0];
    const float* k    = (const float*)d_in[1];
    const float* v    = (const float*)d_in[2];
    const float* ln_g = (const float*)d_in[3];
    const float* ln_b = (const float*)d_in[4];
    const float* Wq   = (const float*)d_in[5];
    const float* bq   = (const float*)d_in[6];
    const float* Wk   = (const float*)d_in[7];
    const float* bk   = (const float*)d_in[8];
    const float* Wv   = (const float*)d_in[9];
    const float* bv   = (const float*)d_in[10];
    const float* Wo   = (const float*)d_in[11];
    const float* bo   = (const float*)d_in[12];
    float* out = (float*)d_out;

    __half *qn, *kn, *vn, *qp, *kp, *vp, *vpt, *attnh, *x, *wqt, *wkt, *wvt, *wot;
    float *attn;
    cudaGetSymbolAddress((void**)&qn, g_qn);
    cudaGetSymbolAddress((void**)&kn, g_kn);
    cudaGetSymbolAddress((void**)&vn, g_vn);
    cudaGetSymbolAddress((void**)&qp, g_qp);
    cudaGetSymbolAddress((void**)&kp, g_kp);
    cudaGetSymbolAddress((void**)&vp, g_vp);
    cudaGetSymbolAddress((void**)&vpt, g_vpt);
    cudaGetSymbolAddress((void**)&attn, g_attn);
    cudaGetSymbolAddress((void**)&attnh, g_attnh);
    cudaGetSymbolAddress((void**)&x, g_x);
    cudaGetSymbolAddress((void**)&wqt, g_wqt);
    cudaGetSymbolAddress((void**)&wkt, g_wkt);
    cudaGetSymbolAddress((void**)&wvt, g_wvt);
    cudaGetSymbolAddress((void**)&wot, g_wot);

    cudaFuncSetAttribute(mma_gemm<true,  true >, cudaFuncAttributeMaxDynamicSharedMemorySize, PIPE_SMEM);
    cudaFuncSetAttribute(mma_gemm<false, false>, cudaFuncAttributeMaxDynamicSharedMemorySize, PIPE_SMEM);
    cudaFuncSetAttribute(mma_gemm<false, true >, cudaFuncAttributeMaxDynamicSharedMemorySize, PIPE_SMEM);
    cudaFuncSetAttribute(mma_gemm<true,  false>, cudaFuncAttributeMaxDynamicSharedMemorySize, PIPE_SMEM);

    // 0. transpose weights to [N,K] half
    transpose_f2h<<<dim3(INNER / 32, CD / 32), dim3(32, 8)>>>(Wq, wqt, CD, INNER);
    transpose_f2h<<<dim3(INNER / 32, CD / 32), dim3(32, 8)>>>(Wk, wkt, CD, INNER);
    transpose_f2h<<<dim3(INNER / 32, CD / 32), dim3(32, 8)>>>(Wv, wvt, CD, INNER);
    transpose_f2h<<<dim3(CD / 32, INNER / 32), dim3(32, 8)>>>(Wo, wot, INNER, CD);

    // 1. LayerNorm q,k,v (half out)
    ln_kernel<<<dim3(ROWS, 3), 256>>>(q, k, v, ln_g, ln_b);

    // 2. Projections: A[8192,256] @ Wt[1024,256]^T + bias -> half
    {
        dim3 grid(INNER / 128, ROWS / 128, 1);
        mma_gemm<true, true><<<grid, 256, PIPE_SMEM>>>(qn, wqt, bq, qp, INNER, CD, 1.0f, 0, 0, 0);
        mma_gemm<true, true><<<grid, 256, PIPE_SMEM>>>(kn, wkt, bk, kp, INNER, CD, 1.0f, 0, 0, 0);
        mma_gemm<true, true><<<grid, 256, PIPE_SMEM>>>(vn, wvt, bv, vp, INNER, CD, 1.0f, 0, 0, 0);
    }

    // 3. Scores: per batch qp[2048,1024] @ kp[2048,1024]^T * SCALE -> fp32
    {
        dim3 grid(ND / 128, ND / 128, BD);
        mma_gemm<false, false><<<grid, 256, PIPE_SMEM>>>(
            qp, kp, nullptr, attn, ND, INNER, ATT_SCALE,
            (long long)ND * INNER, (long long)ND * INNER, (long long)ND * ND);
    }

    // 4. Softmax rows (fp32 in, half out)
    softmax_kernel<<<BD * ND, 256>>>();

    // 5. transpose vp -> vpt per batch: [2048,1024] -> [1024,2048]
    transpose_h2h<<<dim3(INNER / 32, ND / 32, BD), dim3(32, 8)>>>(
        vp, vpt, ND, INNER, (long long)ND * INNER, (long long)ND * INNER);

    // 6. AV: per batch attnh[2048,2048] @ vpt[1024,2048]^T -> half
    {
        dim3 grid(INNER / 128, ND / 128, BD);
        mma_gemm<false, true><<<grid, 256, PIPE_SMEM>>>(
            attnh, vpt, nullptr, x, INNER, ND, 1.0f,
            (long long)ND * ND, (long long)ND * INNER, (long long)ND * INNER);
    }

    // 7. Output projection: x[8192,1024] @ wot[256,1024]^T + bias -> fp32 out
    {
        dim3 grid(CD / 128, ROWS / 128, 1);
        mma_gemm<true, false><<<grid, 256, PIPE_SMEM>>>(x, wot, bo, out, CD, INNER, 1.0f, 0, 0, 0);
    }
}

// round 11
// speedup vs baseline: 2.9436x; 1.0417x over previous
#include <cuda_runtime.h>
#include <cuda_fp16.h>
#include <math.h>
#include <stdint.h>

// Problem constants
#define BD 4
#define ND 2048
#define CD 256
#define INNER 1024
#define ROWS (BD*ND)          // 8192
#define EPS 1e-5f
#define ATT_SCALE 0.125f      // 64^-0.5

// ---------------- scratch (device globals; allocation-free rule) -------------
__device__ __half g_qn[ROWS*CD];
__device__ __half g_kn[ROWS*CD];
__device__ __half g_vn[ROWS*CD];
__device__ __half g_qp[ROWS*INNER];
__device__ __half g_kp[ROWS*INNER];
__device__ __half g_vpt[ROWS*INNER];            // vp^T per batch [INNER, ND]
__device__ float  g_attn[(long long)BD*ND*ND];  // raw fp32 scores, 64 MB
__device__ __half g_attnh[(long long)BD*ND*ND]; // softmaxed probs, half, 32 MB
__device__ __half g_x[ROWS*INNER];
__device__ __half g_wt[3][INNER*CD];            // Wq^T, Wk^T, Wv^T [1024,256]
__device__ __half g_wot[CD*INNER];              // Wo^T [256,1024]

// ---------------- helpers ----------------
__device__ __forceinline__ float warp_sum(float v) {
    #pragma unroll
    for (int o = 16; o; o >>= 1) v += __shfl_xor_sync(0xffffffffu, v, o);
    return v;
}
__device__ __forceinline__ float warp_max(float v) {
    #pragma unroll
    for (int o = 16; o; o >>= 1) v = fmaxf(v, __shfl_xor_sync(0xffffffffu, v, o));
    return v;
}
__device__ __forceinline__ float block_sum256(float v, float* shm) {
    v = warp_sum(v);
    int w = threadIdx.x >> 5;
    if ((threadIdx.x & 31) == 0) shm[w] = v;
    __syncthreads();
    if (threadIdx.x == 0) {
        float s = 0.f;
        #pragma unroll
        for (int i = 0; i < 8; i++) s += shm[i];
        shm[8] = s;
    }
    __syncthreads();
    float r = shm[8];
    __syncthreads();
    return r;
}
__device__ __forceinline__ float block_max256(float v, float* shm) {
    v = warp_max(v);
    int w = threadIdx.x >> 5;
    if ((threadIdx.x & 31) == 0) shm[w] = v;
    __syncthreads();
    if (threadIdx.x == 0) {
        float m = shm[0];
        #pragma unroll
        for (int i = 1; i < 8; i++) m = fmaxf(m, shm[i]);
        shm[8] = m;
    }
    __syncthreads();
    float r = shm[8];
    __syncthreads();
    return r;
}

// mma m16n8k16: f32 acc, f16 inputs
__device__ __forceinline__ void mma_f16(float* c, const unsigned* a, const unsigned* b) {
    asm volatile(
        "mma.sync.aligned.m16n8k16.row.col.f32.f16.f16.f32 "
        "{%0,%1,%2,%3}, {%4,%5,%6,%7}, {%8,%9}, {%0,%1,%2,%3};"
        : "+f"(c[0]), "+f"(c[1]), "+f"(c[2]), "+f"(c[3])
        : "r"(a[0]), "r"(a[1]), "r"(a[2]), "r"(a[3]), "r"(b[0]), "r"(b[1]));
}

__device__ __forceinline__ void ldsm_x4(unsigned& r0, unsigned& r1, unsigned& r2, unsigned& r3,
                                        unsigned addr) {
    asm volatile("ldmatrix.sync.aligned.m8n8.x4.shared.b16 {%0,%1,%2,%3}, [%4];"
                 : "=r"(r0), "=r"(r1), "=r"(r2), "=r"(r3) : "r"(addr));
}

__device__ __forceinline__ void cp16(void* smem_dst, const void* gmem_src) {
    unsigned s = (unsigned)__cvta_generic_to_shared(smem_dst);
    asm volatile("cp.async.cg.shared.global [%0], [%1], 16;" :: "r"(s), "l"(gmem_src));
}
__device__ __forceinline__ void cp_commit() {
    asm volatile("cp.async.commit_group;");
}
template<int NN>
__device__ __forceinline__ void cp_wait() {
    asm volatile("cp.async.wait_group %0;" :: "n"(NN));
}

// ---------------- LayerNorm (writes half) ------------------------------------
__global__ void ln_kernel(const float* __restrict__ q, const float* __restrict__ k,
                          const float* __restrict__ v, const float* __restrict__ g,
                          const float* __restrict__ b) {
    __shared__ float shm[9];
    const float* src;
    __half* dst;
    int which = blockIdx.y;
    long long off = (long long)blockIdx.x * CD;
    if (which == 0)      { src = q + off; dst = g_qn + off; }
    else if (which == 1) { src = k + off; dst = g_kn + off; }
    else                 { src = v + off; dst = g_vn + off; }
    int t = threadIdx.x;
    float x = src[t];
    float mean = block_sum256(x, shm) * (1.0f / CD);
    float d = x - mean;
    float var = block_sum256(d * d, shm) * (1.0f / CD);
    float inv = rsqrtf(var + EPS);
    dst[t] = __float2half_rn(d * inv * g[t] + b[t]);
}

// ---------------- transposes -------------------------------------------------
// z-batched QKV weight transpose: [256,1024] -> [1024,256] half, z selects src
__global__ void transpose_qkv_w(const float* __restrict__ s0, const float* __restrict__ s1,
                                const float* __restrict__ s2) {
    __shared__ float tile[32][33];
    const float* src = (blockIdx.z == 0) ? s0 : (blockIdx.z == 1) ? s1 : s2;
    __half* dst = g_wt[blockIdx.z];
    int tx = threadIdx.x, ty = threadIdx.y;
    int c0 = blockIdx.x * 32, r0 = blockIdx.y * 32;
    #pragma unroll
    for (int j = 0; j < 4; j++)
        tile[ty + 8 * j][tx] = src[(long long)(r0 + ty + 8 * j) * INNER + c0 + tx];
    __syncthreads();
    #pragma unroll
    for (int j = 0; j < 4; j++)
        dst[(long long)(c0 + ty + 8 * j) * CD + r0 + tx] = __float2half_rn(tile[tx][ty + 8 * j]);
}

__global__ void transpose_f2h(const float* __restrict__ src, __half* __restrict__ dst,
                              int R, int C) {
    __shared__ float tile[32][33];
    int tx = threadIdx.x, ty = threadIdx.y;
    int c0 = blockIdx.x * 32, r0 = blockIdx.y * 32;
    #pragma unroll
    for (int j = 0; j < 4; j++)
        tile[ty + 8 * j][tx] = src[(long long)(r0 + ty + 8 * j) * C + c0 + tx];
    __syncthreads();
    #pragma unroll
    for (int j = 0; j < 4; j++)
        dst[(long long)(c0 + ty + 8 * j) * R + r0 + tx] = __float2half_rn(tile[tx][ty + 8 * j]);
}

// ---------------- softmax: read fp32 scores, write half probs ----------------
__global__ void softmax_kernel() {
    __shared__ float shm[9];
    const float* row = g_attn + (long long)blockIdx.x * ND;
    __half* rowh = g_attnh + (long long)blockIdx.x * ND;
    int t = threadIdx.x;
    float vals[8];
    float m = -INFINITY;
    #pragma unroll
    for (int i = 0; i < 8; i++) {
        vals[i] = row[t + i * 256];
        m = fmaxf(m, vals[i]);
    }
    m = block_max256(m, shm);
    float s = 0.f;
    #pragma unroll
    for (int i = 0; i < 8; i++) {
        vals[i] = __expf(vals[i] - m);
        s += vals[i];
    }
    s = block_sum256(s, shm);
    float inv = 1.0f / s;
    #pragma unroll
    for (int i = 0; i < 8; i++) rowh[t + i * 256] = __float2half_rn(vals[i] * inv);
}

// ---------------- fp16 tensor-core GEMM (NT; BK=64 pipeline + ldmatrix) ------
// C[M,Ntot] = alpha * A[M,K] @ B[Ntot,K]^T (+ bias). A,B half, K-major.
// BIAS_MODE: 0 = none, 1 = per-column bias, 2 = per-row bias.
// Block tile 128x128x64, 8 warps (4Mx2N), warp tile 32x64, mma m16n8k16.
#define HS 72
#define STG_HALFS (128 * HS)                 // 9216 halves per tile
#define PIPE_SMEM (4 * STG_HALFS * 2)        // 2 stages x (A+B) = 73728 bytes

template<int BIAS_MODE, bool OUT_HALF>
__global__ __launch_bounds__(256, 2)
void mma_gemm(const __half* __restrict__ A, const __half* __restrict__ B,
              const float* __restrict__ bias, void* __restrict__ CoutV,
              int Ntot, int K, float alpha,
              long long strideA, long long strideB, long long strideC) {
    extern __shared__ __align__(16) __half smem[];   // As0|Bs0|As1|Bs1

    A += (long long)blockIdx.z * strideA;
    B += (long long)blockIdx.z * strideB;

    const int tid  = threadIdx.x;
    const int lane = tid & 31;
    const int w    = tid >> 5;
    const int g    = lane >> 2;
    const int tg   = lane & 3;
    const int warpM = (w >> 1) * 32;
    const int warpN = (w & 1) * 64;
    const long long bm = (long long)blockIdx.y * 128;
    const long long bn = (long long)blockIdx.x * 128;

    // ldmatrix per-lane byte offsets (within a tile)
    const int quad = lane >> 3;          // 0..3
    const int r8   = lane & 7;           // 0..7
    const unsigned a_off0 = ((warpM + (quad & 1) * 8 + r8) * HS + (quad >> 1) * 8) * 2u;
    const unsigned a_off1 = a_off0 + 16u * HS * 2u;
    unsigned b_off[4];
    #pragma unroll
    for (int j = 0; j < 4; j++)
        b_off[j] = ((warpN + (2 * j + (quad >> 1)) * 8 + r8) * HS + (quad & 1) * 8) * 2u;

    const unsigned smem_u = (unsigned)__cvta_generic_to_shared(smem);

    float acc[2][8][4];
    #pragma unroll
    for (int i = 0; i < 2; i++)
        #pragma unroll
        for (int j = 0; j < 8; j++)
            #pragma unroll
            for (int q_ = 0; q_ < 4; q_++) acc[i][j][q_] = 0.f;

    const int nit = K / 64;

    // fill one BK=64 stage: 4 cp16 per thread per tile
    auto fill = [&](int st, int k0) {
        __half* as = smem + st * 2 * STG_HALFS;
        __half* bs = as + STG_HALFS;
        #pragma unroll
        for (int i = 0; i < 4; i++) {
            int idx = i * 256 + tid;
            int r  = idx >> 3;
            int c8 = (idx & 7) * 8;
            cp16(&as[r * HS + c8], A + (bm + r) * K + k0 + c8);
        }
        #pragma unroll
        for (int i = 0; i < 4; i++) {
            int idx = i * 256 + tid;
            int r  = idx >> 3;
            int c8 = (idx & 7) * 8;
            cp16(&bs[r * HS + c8], B + (bn + r) * K + k0 + c8);
        }
    };

    fill(0, 0);
    cp_commit();

    for (int it = 0; it < nit; it++) {
        if (it + 1 < nit) {
            fill((it + 1) & 1, (it + 1) * 64);
            cp_commit();
            cp_wait<1>();
        } else {
            cp_wait<0>();
        }
        __syncthreads();

        const unsigned as_u = smem_u + (it & 1) * (2u * STG_HALFS * 2u);
        const unsigned bs_u = as_u + STG_HALFS * 2u;

        #pragma unroll
        for (int ks = 0; ks < 4; ks++) {           // four K=16 mma steps
            const unsigned kbB = ks * 16u * 2u;    // k offset in bytes
            unsigned af[2][4];
            ldsm_x4(af[0][0], af[0][1], af[0][2], af[0][3], as_u + a_off0 + kbB);
            ldsm_x4(af[1][0], af[1][1], af[1][2], af[1][3], as_u + a_off1 + kbB);
            unsigned bf[8][2];
            #pragma unroll
            for (int j = 0; j < 4; j++)
                ldsm_x4(bf[2 * j][0], bf[2 * j][1], bf[2 * j + 1][0], bf[2 * j + 1][1],
                        bs_u + b_off[j] + kbB);
            #pragma unroll
            for (int mt = 0; mt < 2; mt++)
                #pragma unroll
                for (int nt = 0; nt < 8; nt++)
                    mma_f16(acc[mt][nt], af[mt], bf[nt]);
        }
        __syncthreads();
    }

    // ---- epilogue ----
    #pragma unroll
    for (int mt = 0; mt < 2; mt++) {
        #pragma unroll
        for (int nt = 0; nt < 8; nt++) {
            long long row0 = bm + warpM + mt * 16 + g;
            long long col  = bn + warpN + nt * 8 + tg * 2;
            float b00 = 0.f, b01 = 0.f, b10 = 0.f, b11 = 0.f;
            if (BIAS_MODE == 1) {                       // per-column
                b00 = b10 = bias[col];
                b01 = b11 = bias[col + 1];
            } else if (BIAS_MODE == 2) {                // per-row
                b00 = b01 = bias[row0];
                b10 = b11 = bias[row0 + 8];
            }
            float o00 = acc[mt][nt][0] * alpha + b00;
            float o01 = acc[mt][nt][1] * alpha + b01;
            float o10 = acc[mt][nt][2] * alpha + b10;
            float o11 = acc[mt][nt][3] * alpha + b11;
            if (OUT_HALF) {
                __half* Cout = (__half*)CoutV + (long long)blockIdx.z * strideC;
                *reinterpret_cast<__half2*>(Cout + row0 * Ntot + col) =
                    __floats2half2_rn(o00, o01);
                *reinterpret_cast<__half2*>(Cout + (row0 + 8) * Ntot + col) =
                    __floats2half2_rn(o10, o11);
            } else {
                float* Cout = (float*)CoutV + (long long)blockIdx.z * strideC;
                *reinterpret_cast<float2*>(Cout + row0 * Ntot + col)       = make_float2(o00, o01);
                *reinterpret_cast<float2*>(Cout + (row0 + 8) * Ntot + col) = make_float2(o10, o11);
            }
        }
    }
}

// ---------------- launch ----------------------------------------------------
extern "C" void kernel_launch(void* const* d_in, const int* in_sizes, int n_in,
                              void* d_out, int out_size) {
    const float* q    = (const float*)d_in[0];
    const float* k    = (const float*)d_in[1];
    const float* v    = (const float*)d_in[2];
    const float* ln_g = (const float*)d_in[3];
    const float* ln_b = (const float*)d_in[4];
    const float* Wq   = (const float*)d_in[5];
    const float* bq   = (const float*)d_in[6];
    const float* Wk   = (const float*)d_in[7];
    const float* bk   = (const float*)d_in[8];
    const float* Wv   = (const float*)d_in[9];
    const float* bv   = (const float*)d_in[10];
    const float* Wo   = (const float*)d_in[11];
    const float* bo   = (const float*)d_in[12];
    float* out = (float*)d_out;

    __half *qn, *kn, *vn, *qp, *kp, *vpt, *attnh, *x, *wt, *wot;
    float *attn;
    cudaGetSymbolAddress((void**)&qn, g_qn);
    cudaGetSymbolAddress((void**)&kn, g_kn);
    cudaGetSymbolAddress((void**)&vn, g_vn);
    cudaGetSymbolAddress((void**)&qp, g_qp);
    cudaGetSymbolAddress((void**)&kp, g_kp);
    cudaGetSymbolAddress((void**)&vpt, g_vpt);
    cudaGetSymbolAddress((void**)&attn, g_attn);
    cudaGetSymbolAddress((void**)&attnh, g_attnh);
    cudaGetSymbolAddress((void**)&x, g_x);
    cudaGetSymbolAddress((void**)&wt, g_wt);
    cudaGetSymbolAddress((void**)&wot, g_wot);

    __half* wqt = wt;
    __half* wkt = wt + (long long)INNER * CD;
    __half* wvt = wt + 2LL * INNER * CD;

    cudaFuncSetAttribute(mma_gemm<1, true >, cudaFuncAttributeMaxDynamicSharedMemorySize, PIPE_SMEM);
    cudaFuncSetAttribute(mma_gemm<2, true >, cudaFuncAttributeMaxDynamicSharedMemorySize, PIPE_SMEM);
    cudaFuncSetAttribute(mma_gemm<0, false>, cudaFuncAttributeMaxDynamicSharedMemorySize, PIPE_SMEM);
    cudaFuncSetAttribute(mma_gemm<0, true >, cudaFuncAttributeMaxDynamicSharedMemorySize, PIPE_SMEM);
    cudaFuncSetAttribute(mma_gemm<1, false>, cudaFuncAttributeMaxDynamicSharedMemorySize, PIPE_SMEM);

    // 0. transpose weights to [N,K] half (QKV batched z=3; Wo separate)
    transpose_qkv_w<<<dim3(INNER / 32, CD / 32, 3), dim3(32, 8)>>>(Wq, Wk, Wv);
    transpose_f2h<<<dim3(CD / 32, INNER / 32), dim3(32, 8)>>>(Wo, wot, INNER, CD);

    // 1. LayerNorm q,k,v (half out)
    ln_kernel<<<dim3(ROWS, 3), 256>>>(q, k, v, ln_g, ln_b);

    // 2. Q/K projections: LNx[8192,256] @ Wt[1024,256]^T + col-bias -> half
    {
        dim3 grid(INNER / 128, ROWS / 128, 1);
        mma_gemm<1, true><<<grid, 256, PIPE_SMEM>>>(qn, wqt, bq, qp, INNER, CD, 1.0f, 0, 0, 0);
        mma_gemm<1, true><<<grid, 256, PIPE_SMEM>>>(kn, wkt, bk, kp, INNER, CD, 1.0f, 0, 0, 0);
    }

    // 2b. V projection TRANSPOSED directly: vpt[b] = Wv^T @ vn[b]^T + row-bias
    //     C[M=1024, N=2048] = wvt[1024,256] @ vn_b[2048,256]^T + bv[row]
    {
        dim3 grid(ND / 128, INNER / 128, BD);
        mma_gemm<2, true><<<grid, 256, PIPE_SMEM>>>(
            wvt, vn, bv, vpt, ND, CD, 1.0f,
            0, (long long)ND * CD, (long long)INNER * ND);
    }

    // 3. Scores: per batch qp[2048,1024] @ kp[2048,1024]^T * SCALE -> fp32
    {
        dim3 grid(ND / 128, ND / 128, BD);
        mma_gemm<0, false><<<grid, 256, PIPE_SMEM>>>(
            qp, kp, nullptr, attn, ND, INNER, ATT_SCALE,
            (long long)ND * INNER, (long long)ND * INNER, (long long)ND * ND);
    }

    // 4. Softmax rows (fp32 in, half out)
    softmax_kernel<<<BD * ND, 256>>>();

    // 5. AV: per batch attnh[2048,2048] @ vpt[1024,2048]^T -> half
    {
        dim3 grid(INNER / 128, ND / 128, BD);
        mma_gemm<0, true><<<grid, 256, PIPE_SMEM>>>(
            attnh, vpt, nullptr, x, INNER, ND, 1.0f,
            (long long)ND * ND, (long long)INNER * ND, (long long)ND * INNER);
    }

    // 6. Output projection: x[8192,1024] @ wot[256,1024]^T + bias -> fp32 out
    {
        dim3 grid(CD / 128, ROWS / 128, 1);
        mma_gemm<1, false><<<grid, 256, PIPE_SMEM>>>(x, wot, bo, out, CD, INNER, 1.0f, 0, 0, 0);
    }
}

// round 12
// speedup vs baseline: 2.9795x; 1.0122x over previous
#include <cuda_runtime.h>
#include <cuda_fp16.h>
#include <math.h>
#include <stdint.h>

// Problem constants
#define BD 4
#define ND 2048
#define CD 256
#define INNER 1024
#define ROWS (BD*ND)          // 8192
#define EPS 1e-5f
#define ATT_SCALE 0.125f      // 64^-0.5

// ---------------- scratch (device globals; allocation-free rule) -------------
__device__ __half g_qn[ROWS*CD];
__device__ __half g_kn[ROWS*CD];
__device__ __half g_vn[ROWS*CD];
__device__ __half g_qp[ROWS*INNER];
__device__ __half g_kp[ROWS*INNER];
__device__ __half g_vpt[ROWS*INNER];            // vp^T per batch [INNER, ND]
__device__ float  g_attn[(long long)BD*ND*ND];  // raw fp32 scores, 64 MB
__device__ __half g_attnh[(long long)BD*ND*ND]; // softmaxed probs, half, 32 MB
__device__ __half g_x[ROWS*INNER];
__device__ __half g_wt[3][INNER*CD];            // Wq^T, Wk^T, Wv^T [1024,256]
__device__ __half g_wot[CD*INNER];              // Wo^T [256,1024]

// ---------------- helpers ----------------
__device__ __forceinline__ float warp_sum(float v) {
    #pragma unroll
    for (int o = 16; o; o >>= 1) v += __shfl_xor_sync(0xffffffffu, v, o);
    return v;
}
__device__ __forceinline__ float warp_max(float v) {
    #pragma unroll
    for (int o = 16; o; o >>= 1) v = fmaxf(v, __shfl_xor_sync(0xffffffffu, v, o));
    return v;
}
__device__ __forceinline__ float block_sum256(float v, float* shm) {
    v = warp_sum(v);
    int w = threadIdx.x >> 5;
    if ((threadIdx.x & 31) == 0) shm[w] = v;
    __syncthreads();
    if (threadIdx.x == 0) {
        float s = 0.f;
        #pragma unroll
        for (int i = 0; i < 8; i++) s += shm[i];
        shm[8] = s;
    }
    __syncthreads();
    float r = shm[8];
    __syncthreads();
    return r;
}
__device__ __forceinline__ float block_max256(float v, float* shm) {
    v = warp_max(v);
    int w = threadIdx.x >> 5;
    if ((threadIdx.x & 31) == 0) shm[w] = v;
    __syncthreads();
    if (threadIdx.x == 0) {
        float m = shm[0];
        #pragma unroll
        for (int i = 1; i < 8; i++) m = fmaxf(m, shm[i]);
        shm[8] = m;
    }
    __syncthreads();
    float r = shm[8];
    __syncthreads();
    return r;
}

// mma m16n8k16: f32 acc, f16 inputs
__device__ __forceinline__ void mma_f16(float* c, const unsigned* a, const unsigned* b) {
    asm volatile(
        "mma.sync.aligned.m16n8k16.row.col.f32.f16.f16.f32 "
        "{%0,%1,%2,%3}, {%4,%5,%6,%7}, {%8,%9}, {%0,%1,%2,%3};"
        : "+f"(c[0]), "+f"(c[1]), "+f"(c[2]), "+f"(c[3])
        : "r"(a[0]), "r"(a[1]), "r"(a[2]), "r"(a[3]), "r"(b[0]), "r"(b[1]));
}

__device__ __forceinline__ void ldsm_x4(unsigned& r0, unsigned& r1, unsigned& r2, unsigned& r3,
                                        unsigned addr) {
    asm volatile("ldmatrix.sync.aligned.m8n8.x4.shared.b16 {%0,%1,%2,%3}, [%4];"
                 : "=r"(r0), "=r"(r1), "=r"(r2), "=r"(r3) : "r"(addr));
}

__device__ __forceinline__ void cp16(void* smem_dst, const void* gmem_src) {
    unsigned s = (unsigned)__cvta_generic_to_shared(smem_dst);
    asm volatile("cp.async.cg.shared.global [%0], [%1], 16;" :: "r"(s), "l"(gmem_src));
}
__device__ __forceinline__ void cp_commit() {
    asm volatile("cp.async.commit_group;");
}
template<int NN>
__device__ __forceinline__ void cp_wait() {
    asm volatile("cp.async.wait_group %0;" :: "n"(NN));
}

// ---------------- LayerNorm (writes half) ------------------------------------
__global__ void ln_kernel(const float* __restrict__ q, const float* __restrict__ k,
                          const float* __restrict__ v, const float* __restrict__ g,
                          const float* __restrict__ b) {
    __shared__ float shm[9];
    const float* src;
    __half* dst;
    int which = blockIdx.y;
    long long off = (long long)blockIdx.x * CD;
    if (which == 0)      { src = q + off; dst = g_qn + off; }
    else if (which == 1) { src = k + off; dst = g_kn + off; }
    else                 { src = v + off; dst = g_vn + off; }
    int t = threadIdx.x;
    float x = src[t];
    float mean = block_sum256(x, shm) * (1.0f / CD);
    float d = x - mean;
    float var = block_sum256(d * d, shm) * (1.0f / CD);
    float inv = rsqrtf(var + EPS);
    dst[t] = __float2half_rn(d * inv * g[t] + b[t]);
}

// ---------------- transposes -------------------------------------------------
// z-batched QKV weight transpose: [256,1024] -> [1024,256] half, z selects src
__global__ void transpose_qkv_w(const float* __restrict__ s0, const float* __restrict__ s1,
                                const float* __restrict__ s2) {
    __shared__ float tile[32][33];
    const float* src = (blockIdx.z == 0) ? s0 : (blockIdx.z == 1) ? s1 : s2;
    __half* dst = g_wt[blockIdx.z];
    int tx = threadIdx.x, ty = threadIdx.y;
    int c0 = blockIdx.x * 32, r0 = blockIdx.y * 32;
    #pragma unroll
    for (int j = 0; j < 4; j++)
        tile[ty + 8 * j][tx] = src[(long long)(r0 + ty + 8 * j) * INNER + c0 + tx];
    __syncthreads();
    #pragma unroll
    for (int j = 0; j < 4; j++)
        dst[(long long)(c0 + ty + 8 * j) * CD + r0 + tx] = __float2half_rn(tile[tx][ty + 8 * j]);
}

__global__ void transpose_f2h(const float* __restrict__ src, __half* __restrict__ dst,
                              int R, int C) {
    __shared__ float tile[32][33];
    int tx = threadIdx.x, ty = threadIdx.y;
    int c0 = blockIdx.x * 32, r0 = blockIdx.y * 32;
    #pragma unroll
    for (int j = 0; j < 4; j++)
        tile[ty + 8 * j][tx] = src[(long long)(r0 + ty + 8 * j) * C + c0 + tx];
    __syncthreads();
    #pragma unroll
    for (int j = 0; j < 4; j++)
        dst[(long long)(c0 + ty + 8 * j) * R + r0 + tx] = __float2half_rn(tile[tx][ty + 8 * j]);
}

// ---------------- softmax: read fp32 scores, write half probs ----------------
__global__ void softmax_kernel() {
    __shared__ float shm[9];
    const float* row = g_attn + (long long)blockIdx.x * ND;
    __half* rowh = g_attnh + (long long)blockIdx.x * ND;
    int t = threadIdx.x;
    float vals[8];
    float m = -INFINITY;
    #pragma unroll
    for (int i = 0; i < 8; i++) {
        vals[i] = row[t + i * 256];
        m = fmaxf(m, vals[i]);
    }
    m = block_max256(m, shm);
    float s = 0.f;
    #pragma unroll
    for (int i = 0; i < 8; i++) {
        vals[i] = __expf(vals[i] - m);
        s += vals[i];
    }
    s = block_sum256(s, shm);
    float inv = 1.0f / s;
    #pragma unroll
    for (int i = 0; i < 8; i++) rowh[t + i * 256] = __float2half_rn(vals[i] * inv);
}

// ---------------- fp16 tensor-core GEMM (NT; 3-stage single-sync pipeline) ---
// C[M,Ntot] = alpha * A[M,K] @ B[Ntot,K]^T (+ bias). A,B half, K-major.
// BIAS_MODE: 0 = none, 1 = per-column bias, 2 = per-row bias.
// Block tile 128x128x64, 8 warps (4Mx2N), warp tile 32x64, mma m16n8k16.
// 3 smem stages; exactly ONE __syncthreads per K-iteration.
#define HS 72
#define STG_HALFS (128 * HS)                 // 9216 halves per operand tile
#define STG_BYTES (2u * STG_HALFS * 2u)      // A+B stage bytes = 36864
#define PIPE_SMEM (3 * (int)STG_BYTES)       // 110592 bytes

template<int BIAS_MODE, bool OUT_HALF>
__global__ __launch_bounds__(256, 2)
void mma_gemm(const __half* __restrict__ A, const __half* __restrict__ B,
              const float* __restrict__ bias, void* __restrict__ CoutV,
              int Ntot, int K, float alpha,
              long long strideA, long long strideB, long long strideC) {
    extern __shared__ __align__(16) __half smem[];   // 3 x (As|Bs)

    A += (long long)blockIdx.z * strideA;
    B += (long long)blockIdx.z * strideB;

    const int tid  = threadIdx.x;
    const int lane = tid & 31;
    const int w    = tid >> 5;
    const int g    = lane >> 2;
    const int tg   = lane & 3;
    const int warpM = (w >> 1) * 32;
    const int warpN = (w & 1) * 64;
    const long long bm = (long long)blockIdx.y * 128;
    const long long bn = (long long)blockIdx.x * 128;

    // ldmatrix per-lane byte offsets (within a tile)
    const int quad = lane >> 3;          // 0..3
    const int r8   = lane & 7;           // 0..7
    const unsigned a_off0 = ((warpM + (quad & 1) * 8 + r8) * HS + (quad >> 1) * 8) * 2u;
    const unsigned a_off1 = a_off0 + 16u * HS * 2u;
    unsigned b_off[4];
    #pragma unroll
    for (int j = 0; j < 4; j++)
        b_off[j] = ((warpN + (2 * j + (quad >> 1)) * 8 + r8) * HS + (quad & 1) * 8) * 2u;

    const unsigned smem_u = (unsigned)__cvta_generic_to_shared(smem);

    float acc[2][8][4];
    #pragma unroll
    for (int i = 0; i < 2; i++)
        #pragma unroll
        for (int j = 0; j < 8; j++)
            #pragma unroll
            for (int q_ = 0; q_ < 4; q_++) acc[i][j][q_] = 0.f;

    const int nit = K / 64;

    // fill one BK=64 stage: 4 cp16 per thread per tile
    auto fill = [&](int st, int k0) {
        __half* as = smem + st * 2 * STG_HALFS;
        __half* bs = as + STG_HALFS;
        #pragma unroll
        for (int i = 0; i < 4; i++) {
            int idx = i * 256 + tid;
            int r  = idx >> 3;
            int c8 = (idx & 7) * 8;
            cp16(&as[r * HS + c8], A + (bm + r) * K + k0 + c8);
        }
        #pragma unroll
        for (int i = 0; i < 4; i++) {
            int idx = i * 256 + tid;
            int r  = idx >> 3;
            int c8 = (idx & 7) * 8;
            cp16(&bs[r * HS + c8], B + (bn + r) * K + k0 + c8);
        }
    };

    // prologue: prefill stages 0 and 1 (nit >= 4 for all our GEMMs)
    fill(0, 0);
    cp_commit();
    fill(1, 64);
    cp_commit();

    for (int it = 0; it < nit; it++) {
        // stage `it` must be complete; one newer fill may remain in flight
        if (it == nit - 1) cp_wait<0>(); else cp_wait<1>();
        __syncthreads();   // data-ready + all warps done with stage (it+2)%3's old use
        if (it + 2 < nit) {
            fill((it + 2) % 3, (it + 2) * 64);
            cp_commit();
        }

        const unsigned as_u = smem_u + (unsigned)(it % 3) * STG_BYTES;
        const unsigned bs_u = as_u + STG_HALFS * 2u;

        #pragma unroll
        for (int ks = 0; ks < 4; ks++) {           // four K=16 mma steps
            const unsigned kbB = ks * 16u * 2u;    // k offset in bytes
            unsigned af[2][4];
            ldsm_x4(af[0][0], af[0][1], af[0][2], af[0][3], as_u + a_off0 + kbB);
            ldsm_x4(af[1][0], af[1][1], af[1][2], af[1][3], as_u + a_off1 + kbB);
            unsigned bf[8][2];
            #pragma unroll
            for (int j = 0; j < 4; j++)
                ldsm_x4(bf[2 * j][0], bf[2 * j][1], bf[2 * j + 1][0], bf[2 * j + 1][1],
                        bs_u + b_off[j] + kbB);
            #pragma unroll
            for (int mt = 0; mt < 2; mt++)
                #pragma unroll
                for (int nt = 0; nt < 8; nt++)
                    mma_f16(acc[mt][nt], af[mt], bf[nt]);
        }
    }

    // ---- epilogue ----
    #pragma unroll
    for (int mt = 0; mt < 2; mt++) {
        #pragma unroll
        for (int nt = 0; nt < 8; nt++) {
            long long row0 = bm + warpM + mt * 16 + g;
            long long col  = bn + warpN + nt * 8 + tg * 2;
            float b00 = 0.f, b01 = 0.f, b10 = 0.f, b11 = 0.f;
            if (BIAS_MODE == 1) {                       // per-column
                b00 = b10 = bias[col];
                b01 = b11 = bias[col + 1];
            } else if (BIAS_MODE == 2) {                // per-row
                b00 = b01 = bias[row0];
                b10 = b11 = bias[row0 + 8];
            }
            float o00 = acc[mt][nt][0] * alpha + b00;
            float o01 = acc[mt][nt][1] * alpha + b01;
            float o10 = acc[mt][nt][2] * alpha + b10;
            float o11 = acc[mt][nt][3] * alpha + b11;
            if (OUT_HALF) {
                __half* Cout = (__half*)CoutV + (long long)blockIdx.z * strideC;
                *reinterpret_cast<__half2*>(Cout + row0 * Ntot + col) =
                    __floats2half2_rn(o00, o01);
                *reinterpret_cast<__half2*>(Cout + (row0 + 8) * Ntot + col) =
                    __floats2half2_rn(o10, o11);
            } else {
                float* Cout = (float*)CoutV + (long long)blockIdx.z * strideC;
                *reinterpret_cast<float2*>(Cout + row0 * Ntot + col)       = make_float2(o00, o01);
                *reinterpret_cast<float2*>(Cout + (row0 + 8) * Ntot + col) = make_float2(o10, o11);
            }
        }
    }
}

// ---------------- launch ----------------------------------------------------
extern "C" void kernel_launch(void* const* d_in, const int* in_sizes, int n_in,
                              void* d_out, int out_size) {
    const float* q    = (const float*)d_in[0];
    const float* k    = (const float*)d_in[1];
    const float* v    = (const float*)d_in[2];
    const float* ln_g = (const float*)d_in[3];
    const float* ln_b = (const float*)d_in[4];
    const float* Wq   = (const float*)d_in[5];
    const float* bq   = (const float*)d_in[6];
    const float* Wk   = (const float*)d_in[7];
    const float* bk   = (const float*)d_in[8];
    const float* Wv   = (const float*)d_in[9];
    const float* bv   = (const float*)d_in[10];
    const float* Wo   = (const float*)d_in[11];
    const float* bo   = (const float*)d_in[12];
    float* out = (float*)d_out;

    __half *qn, *kn, *vn, *qp, *kp, *vpt, *attnh, *x, *wt, *wot;
    float *attn;
    cudaGetSymbolAddress((void**)&qn, g_qn);
    cudaGetSymbolAddress((void**)&kn, g_kn);
    cudaGetSymbolAddress((void**)&vn, g_vn);
    cudaGetSymbolAddress((void**)&qp, g_qp);
    cudaGetSymbolAddress((void**)&kp, g_kp);
    cudaGetSymbolAddress((void**)&vpt, g_vpt);
    cudaGetSymbolAddress((void**)&attn, g_attn);
    cudaGetSymbolAddress((void**)&attnh, g_attnh);
    cudaGetSymbolAddress((void**)&x, g_x);
    cudaGetSymbolAddress((void**)&wt, g_wt);
    cudaGetSymbolAddress((void**)&wot, g_wot);

    __half* wqt = wt;
    __half* wkt = wt + (long long)INNER * CD;
    __half* wvt = wt + 2LL * INNER * CD;

    cudaFuncSetAttribute(mma_gemm<1, true >, cudaFuncAttributeMaxDynamicSharedMemorySize, PIPE_SMEM);
    cudaFuncSetAttribute(mma_gemm<2, true >, cudaFuncAttributeMaxDynamicSharedMemorySize, PIPE_SMEM);
    cudaFuncSetAttribute(mma_gemm<0, false>, cudaFuncAttributeMaxDynamicSharedMemorySize, PIPE_SMEM);
    cudaFuncSetAttribute(mma_gemm<0, true >, cudaFuncAttributeMaxDynamicSharedMemorySize, PIPE_SMEM);
    cudaFuncSetAttribute(mma_gemm<1, false>, cudaFuncAttributeMaxDynamicSharedMemorySize, PIPE_SMEM);

    // 0. transpose weights to [N,K] half (QKV batched z=3; Wo separate)
    transpose_qkv_w<<<dim3(INNER / 32, CD / 32, 3), dim3(32, 8)>>>(Wq, Wk, Wv);
    transpose_f2h<<<dim3(CD / 32, INNER / 32), dim3(32, 8)>>>(Wo, wot, INNER, CD);

    // 1. LayerNorm q,k,v (half out)
    ln_kernel<<<dim3(ROWS, 3), 256>>>(q, k, v, ln_g, ln_b);

    // 2. Q/K projections: LNx[8192,256] @ Wt[1024,256]^T + col-bias -> half
    {
        dim3 grid(INNER / 128, ROWS / 128, 1);
        mma_gemm<1, true><<<grid, 256, PIPE_SMEM>>>(qn, wqt, bq, qp, INNER, CD, 1.0f, 0, 0, 0);
        mma_gemm<1, true><<<grid, 256, PIPE_SMEM>>>(kn, wkt, bk, kp, INNER, CD, 1.0f, 0, 0, 0);
    }

    // 2b. V projection TRANSPOSED directly: vpt[b] = Wv^T @ vn[b]^T + row-bias
    {
        dim3 grid(ND / 128, INNER / 128, BD);
        mma_gemm<2, true><<<grid, 256, PIPE_SMEM>>>(
            wvt, vn, bv, vpt, ND, CD, 1.0f,
            0, (long long)ND * CD, (long long)INNER * ND);
    }

    // 3. Scores: per batch qp[2048,1024] @ kp[2048,1024]^T * SCALE -> fp32
    {
        dim3 grid(ND / 128, ND / 128, BD);
        mma_gemm<0, false><<<grid, 256, PIPE_SMEM>>>(
            qp, kp, nullptr, attn, ND, INNER, ATT_SCALE,
            (long long)ND * INNER, (long long)ND * INNER, (long long)ND * ND);
    }

    // 4. Softmax rows (fp32 in, half out)
    softmax_kernel<<<BD * ND, 256>>>();

    // 5. AV: per batch attnh[2048,2048] @ vpt[1024,2048]^T -> half
    {
        dim3 grid(INNER / 128, ND / 128, BD);
        mma_gemm<0, true><<<grid, 256, PIPE_SMEM>>>(
            attnh, vpt, nullptr, x, INNER, ND, 1.0f,
            (long long)ND * ND, (long long)INNER * ND, (long long)ND * INNER);
    }

    // 6. Output projection: x[8192,1024] @ wot[256,1024]^T + bias -> fp32 out
    {
        dim3 grid(CD / 128, ROWS / 128, 1);
        mma_gemm<1, false><<<grid, 256, PIPE_SMEM>>>(x, wot, bo, out, CD, INNER, 1.0f, 0, 0, 0);
    }
}

// round 14
// speedup vs baseline: 5.4666x; 1.8347x over previous
#include <cuda_runtime.h>
#include <cuda_fp16.h>
#include <math.h>
#include <stdint.h>

// Problem constants
#define BD 4
#define ND 2048
#define CD 256
#define INNER 1024
#define ROWS (BD*ND)          // 8192
#define EPS 1e-5f
#define ATT_SCALE 0.125f      // 64^-0.5

// ---------------- scratch (device globals; allocation-free rule) -------------
__device__ __half g_qn[ROWS*CD];
__device__ __half g_kn[ROWS*CD];
__device__ __half g_vn[ROWS*CD];
__device__ __half g_vnt[ROWS*CD];               // vn^T per batch [CD, ND]
__device__ __half g_t[ROWS*CD];                 // qn @ Wqk
__device__ __half g_y[ROWS*CD];                 // attn @ vn
__device__ float  g_attn[(long long)BD*ND*ND];  // raw fp32 scores, 64 MB
__device__ __half g_attnh[(long long)BD*ND*ND]; // softmaxed probs, half, 32 MB
__device__ __half g_wh[3][CD*INNER];            // Wq, Wk, Wv (half, untransposed)
__device__ __half g_wot[CD*INNER];              // Wo^T [256,1024]
__device__ __half g_wqkt[CD*CD];                // (Wq Wk^T)^T [256,256]
__device__ __half g_wvot[CD*CD];                // (Wv Wo)^T  [256,256]
__device__ float  g_r[CD];                      // Wk @ bq
__device__ float  g_rc[CD];                     // bv @ Wo + bo
__device__ float  g_wbias[ROWS];                // SCALE * (kn @ r), per key row

// ---------------- helpers ----------------
__device__ __forceinline__ float warp_sum(float v) {
    #pragma unroll
    for (int o = 16; o; o >>= 1) v += __shfl_xor_sync(0xffffffffu, v, o);
    return v;
}
__device__ __forceinline__ float warp_max(float v) {
    #pragma unroll
    for (int o = 16; o; o >>= 1) v = fmaxf(v, __shfl_xor_sync(0xffffffffu, v, o));
    return v;
}
__device__ __forceinline__ float block_sum256(float v, float* shm) {
    v = warp_sum(v);
    int w = threadIdx.x >> 5;
    if ((threadIdx.x & 31) == 0) shm[w] = v;
    __syncthreads();
    if (threadIdx.x == 0) {
        float s = 0.f;
        #pragma unroll
        for (int i = 0; i < 8; i++) s += shm[i];
        shm[8] = s;
    }
    __syncthreads();
    float r = shm[8];
    __syncthreads();
    return r;
}
__device__ __forceinline__ float block_max256(float v, float* shm) {
    v = warp_max(v);
    int w = threadIdx.x >> 5;
    if ((threadIdx.x & 31) == 0) shm[w] = v;
    __syncthreads();
    if (threadIdx.x == 0) {
        float m = shm[0];
        #pragma unroll
        for (int i = 1; i < 8; i++) m = fmaxf(m, shm[i]);
        shm[8] = m;
    }
    __syncthreads();
    float r = shm[8];
    __syncthreads();
    return r;
}

// mma m16n8k16: f32 acc, f16 inputs
__device__ __forceinline__ void mma_f16(float* c, const unsigned* a, const unsigned* b) {
    asm volatile(
        "mma.sync.aligned.m16n8k16.row.col.f32.f16.f16.f32 "
        "{%0,%1,%2,%3}, {%4,%5,%6,%7}, {%8,%9}, {%0,%1,%2,%3};"
        : "+f"(c[0]), "+f"(c[1]), "+f"(c[2]), "+f"(c[3])
        : "r"(a[0]), "r"(a[1]), "r"(a[2]), "r"(a[3]), "r"(b[0]), "r"(b[1]));
}

__device__ __forceinline__ void ldsm_x4(unsigned& r0, unsigned& r1, unsigned& r2, unsigned& r3,
                                        unsigned addr) {
    asm volatile("ldmatrix.sync.aligned.m8n8.x4.shared.b16 {%0,%1,%2,%3}, [%4];"
                 : "=r"(r0), "=r"(r1), "=r"(r2), "=r"(r3) : "r"(addr));
}

__device__ __forceinline__ void cp16(void* smem_dst, const void* gmem_src) {
    unsigned s = (unsigned)__cvta_generic_to_shared(smem_dst);
    asm volatile("cp.async.cg.shared.global [%0], [%1], 16;" :: "r"(s), "l"(gmem_src));
}
__device__ __forceinline__ void cp_commit() {
    asm volatile("cp.async.commit_group;");
}
template<int NN>
__device__ __forceinline__ void cp_wait() {
    asm volatile("cp.async.wait_group %0;" :: "n"(NN));
}

// ---------------- LayerNorm (writes half) ------------------------------------
__global__ void ln_kernel(const float* __restrict__ q, const float* __restrict__ k,
                          const float* __restrict__ v, const float* __restrict__ g,
                          const float* __restrict__ b) {
    __shared__ float shm[9];
    const float* src;
    __half* dst;
    int which = blockIdx.y;
    long long off = (long long)blockIdx.x * CD;
    if (which == 0)      { src = q + off; dst = g_qn + off; }
    else if (which == 1) { src = k + off; dst = g_kn + off; }
    else                 { src = v + off; dst = g_vn + off; }
    int t = threadIdx.x;
    float x = src[t];
    float mean = block_sum256(x, shm) * (1.0f / CD);
    float d = x - mean;
    float var = block_sum256(d * d, shm) * (1.0f / CD);
    float inv = rsqrtf(var + EPS);
    dst[t] = __float2half_rn(d * inv * g[t] + b[t]);
}

// ---------------- small prep kernels -----------------------------------------
// fp32 -> half copy of Wq/Wk/Wv (no transpose), z selects source
__global__ void f2h_copy3(const float* __restrict__ s0, const float* __restrict__ s1,
                          const float* __restrict__ s2) {
    const float* src = (blockIdx.y == 0) ? s0 : (blockIdx.y == 1) ? s1 : s2;
    __half* dst = g_wh[blockIdx.y];
    int i = blockIdx.x * 256 + threadIdx.x;
    if (i < CD * INNER) dst[i] = __float2half_rn(src[i]);
}

// Wo [1024,256] -> Wo^T [256,1024] half
__global__ void transpose_f2h(const float* __restrict__ src, __half* __restrict__ dst,
                              int R, int C) {
    __shared__ float tile[32][33];
    int tx = threadIdx.x, ty = threadIdx.y;
    int c0 = blockIdx.x * 32, r0 = blockIdx.y * 32;
    #pragma unroll
    for (int j = 0; j < 4; j++)
        tile[ty + 8 * j][tx] = src[(long long)(r0 + ty + 8 * j) * C + c0 + tx];
    __syncthreads();
    #pragma unroll
    for (int j = 0; j < 4; j++)
        dst[(long long)(c0 + ty + 8 * j) * R + r0 + tx] = __float2half_rn(tile[tx][ty + 8 * j]);
}

// vn [ND,CD] -> vn^T [CD,ND] half, per batch z
__global__ void transpose_h2h(const __half* __restrict__ src, __half* __restrict__ dst,
                              int R, int C, long long sstride, long long dstride) {
    __shared__ __half tile[32][34];
    src += (long long)blockIdx.z * sstride;
    dst += (long long)blockIdx.z * dstride;
    int tx = threadIdx.x, ty = threadIdx.y;
    int c0 = blockIdx.x * 32, r0 = blockIdx.y * 32;
    #pragma unroll
    for (int j = 0; j < 4; j++)
        tile[ty + 8 * j][tx] = src[(long long)(r0 + ty + 8 * j) * C + c0 + tx];
    __syncthreads();
    #pragma unroll
    for (int j = 0; j < 4; j++)
        dst[(long long)(c0 + ty + 8 * j) * R + r0 + tx] = tile[tx][ty + 8 * j];
}

// r[d] = sum_e Wk[d,e] * bq[e]   (Wk fp32 [256,1024])
__global__ void gemv_r(const float* __restrict__ Wk, const float* __restrict__ bq) {
    __shared__ float shm[9];
    int d = blockIdx.x;
    int t = threadIdx.x;
    float s = 0.f;
    #pragma unroll
    for (int i = 0; i < 4; i++) {
        int e = t + i * 256;
        s += Wk[(long long)d * INNER + e] * bq[e];
    }
    s = block_sum256(s, shm);
    if (t == 0) g_r[d] = s;
}

// rc[c] = sum_e bv[e] * Wo[e,c] + bo[c]   (Wo fp32 [1024,256])
__global__ void gemv_rc(const float* __restrict__ Wo, const float* __restrict__ bv,
                        const float* __restrict__ bo) {
    __shared__ float shm[9];
    int c = blockIdx.x;
    int t = threadIdx.x;
    float s = 0.f;
    #pragma unroll
    for (int i = 0; i < 4; i++) {
        int e = t + i * 256;
        s += bv[e] * Wo[(long long)e * CD + c];
    }
    s = block_sum256(s, shm);
    if (t == 0) g_rc[c] = s + bo[c];
}

// wbias[j] = SCALE * sum_d kn[j,d] * r[d]
__global__ void wbias_kernel() {
    __shared__ float shm[9];
    long long j = blockIdx.x;
    int t = threadIdx.x;
    float s = __half2float(g_kn[j * CD + t]) * g_r[t];
    s = block_sum256(s, shm);
    if (t == 0) g_wbias[j] = ATT_SCALE * s;
}

// ---------------- softmax: read fp32 scores, write half probs ----------------
__global__ void softmax_kernel() {
    __shared__ float shm[9];
    const float* row = g_attn + (long long)blockIdx.x * ND;
    __half* rowh = g_attnh + (long long)blockIdx.x * ND;
    int t = threadIdx.x;
    float vals[8];
    float m = -INFINITY;
    #pragma unroll
    for (int i = 0; i < 8; i++) {
        vals[i] = row[t + i * 256];
        m = fmaxf(m, vals[i]);
    }
    m = block_max256(m, shm);
    float s = 0.f;
    #pragma unroll
    for (int i = 0; i < 8; i++) {
        vals[i] = __expf(vals[i] - m);
        s += vals[i];
    }
    s = block_sum256(s, shm);
    float inv = 1.0f / s;
    #pragma unroll
    for (int i = 0; i < 8; i++) rowh[t + i * 256] = __float2half_rn(vals[i] * inv);
}

// ---------------- fp16 tensor-core GEMM (NT; 3-stage single-sync pipeline) ---
// C[M,Ntot] = alpha * A[M,K] @ B[Ntot,K]^T (+ bias). A,B half, K-major.
// BIAS_MODE: 0 = none, 1 = per-column fp32 bias (offset z*strideBias).
#define HS 72
#define STG_HALFS (128 * HS)
#define STG_BYTES (2u * STG_HALFS * 2u)      // A+B stage bytes = 36864
#define PIPE_SMEM (3 * (int)STG_BYTES)       // 110592 bytes

template<int BIAS_MODE, bool OUT_HALF>
__global__ __launch_bounds__(256, 2)
void mma_gemm(const __half* __restrict__ A, const __half* __restrict__ B,
              const float* __restrict__ bias, void* __restrict__ CoutV,
              int Ntot, int K, float alpha,
              long long strideA, long long strideB, long long strideC,
              long long strideBias) {
    extern __shared__ __align__(16) __half smem[];   // 3 x (As|Bs)

    A += (long long)blockIdx.z * strideA;
    B += (long long)blockIdx.z * strideB;
    if (BIAS_MODE == 1) bias += (long long)blockIdx.z * strideBias;

    const int tid  = threadIdx.x;
    const int lane = tid & 31;
    const int w    = tid >> 5;
    const int g    = lane >> 2;
    const int tg   = lane & 3;
    const int warpM = (w >> 1) * 32;
    const int warpN = (w & 1) * 64;
    const long long bm = (long long)blockIdx.y * 128;
    const long long bn = (long long)blockIdx.x * 128;

    const int quad = lane >> 3;
    const int r8   = lane & 7;
    const unsigned a_off0 = ((warpM + (quad & 1) * 8 + r8) * HS + (quad >> 1) * 8) * 2u;
    const unsigned a_off1 = a_off0 + 16u * HS * 2u;
    unsigned b_off[4];
    #pragma unroll
    for (int j = 0; j < 4; j++)
        b_off[j] = ((warpN + (2 * j + (quad >> 1)) * 8 + r8) * HS + (quad & 1) * 8) * 2u;

    const unsigned smem_u = (unsigned)__cvta_generic_to_shared(smem);

    float acc[2][8][4];
    #pragma unroll
    for (int i = 0; i < 2; i++)
        #pragma unroll
        for (int j = 0; j < 8; j++)
            #pragma unroll
            for (int q_ = 0; q_ < 4; q_++) acc[i][j][q_] = 0.f;

    const int nit = K / 64;

    auto fill = [&](int st, int k0) {
        __half* as = smem + st * 2 * STG_HALFS;
        __half* bs = as + STG_HALFS;
        #pragma unroll
        for (int i = 0; i < 4; i++) {
            int idx = i * 256 + tid;
            int r  = idx >> 3;
            int c8 = (idx & 7) * 8;
            cp16(&as[r * HS + c8], A + (bm + r) * K + k0 + c8);
        }
        #pragma unroll
        for (int i = 0; i < 4; i++) {
            int idx = i * 256 + tid;
            int r  = idx >> 3;
            int c8 = (idx & 7) * 8;
            cp16(&bs[r * HS + c8], B + (bn + r) * K + k0 + c8);
        }
    };

    fill(0, 0);
    cp_commit();
    fill(1, 64);
    cp_commit();

    for (int it = 0; it < nit; it++) {
        if (it == nit - 1) cp_wait<0>(); else cp_wait<1>();
        __syncthreads();
        if (it + 2 < nit) {
            fill((it + 2) % 3, (it + 2) * 64);
            cp_commit();
        }

        const unsigned as_u = smem_u + (unsigned)(it % 3) * STG_BYTES;
        const unsigned bs_u = as_u + STG_HALFS * 2u;

        #pragma unroll
        for (int ks = 0; ks < 4; ks++) {
            const unsigned kbB = ks * 16u * 2u;
            unsigned af[2][4];
            ldsm_x4(af[0][0], af[0][1], af[0][2], af[0][3], as_u + a_off0 + kbB);
            ldsm_x4(af[1][0], af[1][1], af[1][2], af[1][3], as_u + a_off1 + kbB);
            unsigned bf[8][2];
            #pragma unroll
            for (int j = 0; j < 4; j++)
                ldsm_x4(bf[2 * j][0], bf[2 * j][1], bf[2 * j + 1][0], bf[2 * j + 1][1],
                        bs_u + b_off[j] + kbB);
            #pragma unroll
            for (int mt = 0; mt < 2; mt++)
                #pragma unroll
                for (int nt = 0; nt < 8; nt++)
                    mma_f16(acc[mt][nt], af[mt], bf[nt]);
        }
    }

    // ---- epilogue ----
    #pragma unroll
    for (int mt = 0; mt < 2; mt++) {
        #pragma unroll
        for (int nt = 0; nt < 8; nt++) {
            long long row0 = bm + warpM + mt * 16 + g;
            long long col  = bn + warpN + nt * 8 + tg * 2;
            float b0 = 0.f, b1 = 0.f;
            if (BIAS_MODE == 1) { b0 = bias[col]; b1 = bias[col + 1]; }
            float o00 = acc[mt][nt][0] * alpha + b0;
            float o01 = acc[mt][nt][1] * alpha + b1;
            float o10 = acc[mt][nt][2] * alpha + b0;
            float o11 = acc[mt][nt][3] * alpha + b1;
            if (OUT_HALF) {
                __half* Cout = (__half*)CoutV + (long long)blockIdx.z * strideC;
                *reinterpret_cast<__half2*>(Cout + row0 * Ntot + col) =
                    __floats2half2_rn(o00, o01);
                *reinterpret_cast<__half2*>(Cout + (row0 + 8) * Ntot + col) =
                    __floats2half2_rn(o10, o11);
            } else {
                float* Cout = (float*)CoutV + (long long)blockIdx.z * strideC;
                *reinterpret_cast<float2*>(Cout + row0 * Ntot + col)       = make_float2(o00, o01);
                *reinterpret_cast<float2*>(Cout + (row0 + 8) * Ntot + col) = make_float2(o10, o11);
            }
        }
    }
}

// ---------------- launch ----------------------------------------------------
extern "C" void kernel_launch(void* const* d_in, const int* in_sizes, int n_in,
                              void* d_out, int out_size) {
    const float* q    = (const float*)d_in[0];
    const float* k    = (const float*)d_in[1];
    const float* v    = (const float*)d_in[2];
    const float* ln_g = (const float*)d_in[3];
    const float* ln_b = (const float*)d_in[4];
    const float* Wq   = (const float*)d_in[5];
    const float* bq   = (const float*)d_in[6];
    const float* Wk   = (const float*)d_in[7];
    const float* bk   = (const float*)d_in[8];
    const float* Wv   = (const float*)d_in[9];
    const float* bv   = (const float*)d_in[10];
    const float* Wo   = (const float*)d_in[11];
    const float* bo   = (const float*)d_in[12];
    float* out = (float*)d_out;
    (void)bk;  // cancels under softmax (row-constant term)

    __half *qn, *kn, *vn, *vnt, *t, *y, *attnh, *wh, *wot, *wqkt, *wvot;
    float *attn, *rbias, *rcbias, *wbias;
    cudaGetSymbolAddress((void**)&qn, g_qn);
    cudaGetSymbolAddress((void**)&kn, g_kn);
    cudaGetSymbolAddress((void**)&vn, g_vn);
    cudaGetSymbolAddress((void**)&vnt, g_vnt);
    cudaGetSymbolAddress((void**)&t, g_t);
    cudaGetSymbolAddress((void**)&y, g_y);
    cudaGetSymbolAddress((void**)&attn, g_attn);
    cudaGetSymbolAddress((void**)&attnh, g_attnh);
    cudaGetSymbolAddress((void**)&wh, g_wh);
    cudaGetSymbolAddress((void**)&wot, g_wot);
    cudaGetSymbolAddress((void**)&wqkt, g_wqkt);
    cudaGetSymbolAddress((void**)&wvot, g_wvot);
    cudaGetSymbolAddress((void**)&rbias, g_r);
    cudaGetSymbolAddress((void**)&rcbias, g_rc);
    cudaGetSymbolAddress((void**)&wbias, g_wbias);

    __half* wqh = wh;
    __half* wkh = wh + (long long)CD * INNER;
    __half* wvh = wh + 2LL * CD * INNER;

    cudaFuncSetAttribute(mma_gemm<0, true >, cudaFuncAttributeMaxDynamicSharedMemorySize, PIPE_SMEM);
    cudaFuncSetAttribute(mma_gemm<0, false>, cudaFuncAttributeMaxDynamicSharedMemorySize, PIPE_SMEM);
    cudaFuncSetAttribute(mma_gemm<1, true >, cudaFuncAttributeMaxDynamicSharedMemorySize, PIPE_SMEM);
    cudaFuncSetAttribute(mma_gemm<1, false>, cudaFuncAttributeMaxDynamicSharedMemorySize, PIPE_SMEM);

    // 0. weight preps
    f2h_copy3<<<dim3((CD * INNER + 255) / 256, 3), 256>>>(Wq, Wk, Wv);
    transpose_f2h<<<dim3(CD / 32, INNER / 32), dim3(32, 8)>>>(Wo, wot, INNER, CD);
    gemv_r<<<CD, 256>>>(Wk, bq);
    gemv_rc<<<CD, 256>>>(Wo, bv, bo);

    // 1. LayerNorm q,k,v (half out)
    ln_kernel<<<dim3(ROWS, 3), 256>>>(q, k, v, ln_g, ln_b);

    // 2. Wqk^T = Wk @ Wq^T  [256,256] half;  Wvo^T = Wo^T @ Wv^T [256,256] half
    {
        dim3 grid(CD / 128, CD / 128, 1);
        mma_gemm<0, true><<<grid, 256, PIPE_SMEM>>>(wkh, wqh, nullptr, wqkt, CD, INNER, 1.0f, 0, 0, 0, 0);
        mma_gemm<0, true><<<grid, 256, PIPE_SMEM>>>(wot, wvh, nullptr, wvot, CD, INNER, 1.0f, 0, 0, 0, 0);
    }

    // 3. vn^T per batch [256,2048]; wbias[j] = SCALE*(kn[j]·(Wk bq))
    transpose_h2h<<<dim3(CD / 32, ND / 32, BD), dim3(32, 8)>>>(
        vn, vnt, ND, CD, (long long)ND * CD, (long long)CD * ND);
    wbias_kernel<<<ROWS, 256>>>();

    // 4. t = qn @ Wqk  [8192,256] half  (NT with B = Wqk^T)
    {
        dim3 grid(CD / 128, ROWS / 128, 1);
        mma_gemm<0, true><<<grid, 256, PIPE_SMEM>>>(qn, wqkt, nullptr, t, CD, CD, 1.0f, 0, 0, 0, 0);
    }

    // 5. scores = SCALE*(t @ kn^T) + wbias[col], per batch -> fp32
    {
        dim3 grid(ND / 128, ND / 128, BD);
        mma_gemm<1, false><<<grid, 256, PIPE_SMEM>>>(
            t, kn, wbias, attn, ND, CD, ATT_SCALE,
            (long long)ND * CD, (long long)ND * CD, (long long)ND * ND, ND);
    }

    // 6. softmax rows (fp32 in, half out)
    softmax_kernel<<<BD * ND, 256>>>();

    // 7. y = attnh @ vn per batch  [2048,256] half  (NT with B = vn^T)
    {
        dim3 grid(CD / 128, ND / 128, BD);
        mma_gemm<0, true><<<grid, 256, PIPE_SMEM>>>(
            attnh, vnt, nullptr, y, CD, ND, 1.0f,
            (long long)ND * ND, (long long)CD * ND, (long long)ND * CD, 0);
    }

    // 8. out = y @ Wvo + (bv Wo + bo)  -> fp32  (NT with B = Wvo^T)
    {
        dim3 grid(CD / 128, ROWS / 128, 1);
        mma_gemm<1, false><<<grid, 256, PIPE_SMEM>>>(
            y, wvot, rcbias, out, CD, CD, 1.0f, 0, 0, 0, 0);
    }
}

// round 16
// speedup vs baseline: 6.1659x; 1.1279x over previous
#include <cuda_runtime.h>
#include <cuda_fp16.h>
#include <math.h>
#include <stdint.h>

// Problem constants
#define BD 4
#define ND 2048
#define CD 256
#define INNER 1024
#define ROWS (BD*ND)          // 8192
#define EPS 1e-5f
#define ATT_SCALE 0.125f      // 64^-0.5
#define NSPLIT 2              // split-K factor for AV

// ---------------- scratch (device globals; allocation-free rule) -------------
__device__ __half g_qn[ROWS*CD];
__device__ __half g_kn[ROWS*CD];
__device__ __half g_vn[ROWS*CD];
__device__ __half g_vnt[ROWS*CD];               // vn^T per batch [CD, ND]
__device__ __half g_t[ROWS*CD];                 // qn @ Wqk
__device__ __half g_y[ROWS*CD];                 // attn @ vn (reduced)
__device__ float  g_ypart[(long long)NSPLIT*ROWS*CD];  // split-K partials, 16 MB
__device__ float  g_attn[(long long)BD*ND*ND];  // raw fp32 scores, 64 MB
__device__ __half g_attnh[(long long)BD*ND*ND]; // softmaxed probs, half, 32 MB
__device__ __half g_wh4[4][CD*INNER];           // Wq, Wk, Wv, Wo^T (half)
__device__ __half g_wc[2][CD*CD];               // (WqWk^T)^T, (WvWo)^T
__device__ float  g_r[CD];                      // Wk @ bq
__device__ float  g_rc[CD];                     // bv @ Wo + bo
__device__ float  g_wbias[ROWS];                // SCALE * (kn @ r), per key row

// ---------------- helpers ----------------
__device__ __forceinline__ float warp_sum(float v) {
    #pragma unroll
    for (int o = 16; o; o >>= 1) v += __shfl_xor_sync(0xffffffffu, v, o);
    return v;
}
__device__ __forceinline__ float warp_max(float v) {
    #pragma unroll
    for (int o = 16; o; o >>= 1) v = fmaxf(v, __shfl_xor_sync(0xffffffffu, v, o));
    return v;
}
__device__ __forceinline__ float block_sum256(float v, float* shm) {
    v = warp_sum(v);
    int w = threadIdx.x >> 5;
    if ((threadIdx.x & 31) == 0) shm[w] = v;
    __syncthreads();
    if (threadIdx.x == 0) {
        float s = 0.f;
        #pragma unroll
        for (int i = 0; i < 8; i++) s += shm[i];
        shm[8] = s;
    }
    __syncthreads();
    float r = shm[8];
    __syncthreads();
    return r;
}
__device__ __forceinline__ float block_max256(float v, float* shm) {
    v = warp_max(v);
    int w = threadIdx.x >> 5;
    if ((threadIdx.x & 31) == 0) shm[w] = v;
    __syncthreads();
    if (threadIdx.x == 0) {
        float m = shm[0];
        #pragma unroll
        for (int i = 1; i < 8; i++) m = fmaxf(m, shm[i]);
        shm[8] = m;
    }
    __syncthreads();
    float r = shm[8];
    __syncthreads();
    return r;
}

// mma m16n8k16: f32 acc, f16 inputs
__device__ __forceinline__ void mma_f16(float* c, const unsigned* a, const unsigned* b) {
    asm volatile(
        "mma.sync.aligned.m16n8k16.row.col.f32.f16.f16.f32 "
        "{%0,%1,%2,%3}, {%4,%5,%6,%7}, {%8,%9}, {%0,%1,%2,%3};"
        : "+f"(c[0]), "+f"(c[1]), "+f"(c[2]), "+f"(c[3])
        : "r"(a[0]), "r"(a[1]), "r"(a[2]), "r"(a[3]), "r"(b[0]), "r"(b[1]));
}

__device__ __forceinline__ void ldsm_x4(unsigned& r0, unsigned& r1, unsigned& r2, unsigned& r3,
                                        unsigned addr) {
    asm volatile("ldmatrix.sync.aligned.m8n8.x4.shared.b16 {%0,%1,%2,%3}, [%4];"
                 : "=r"(r0), "=r"(r1), "=r"(r2), "=r"(r3) : "r"(addr));
}

__device__ __forceinline__ void cp16(void* smem_dst, const void* gmem_src) {
    unsigned s = (unsigned)__cvta_generic_to_shared(smem_dst);
    asm volatile("cp.async.cg.shared.global [%0], [%1], 16;" :: "r"(s), "l"(gmem_src));
}
__device__ __forceinline__ void cp_commit() {
    asm volatile("cp.async.commit_group;");
}
template<int NN>
__device__ __forceinline__ void cp_wait() {
    asm volatile("cp.async.wait_group %0;" :: "n"(NN));
}

// ---------------- LayerNorm (writes half; k-branch also computes wbias) ------
__global__ void ln_kernel(const float* __restrict__ q, const float* __restrict__ k,
                          const float* __restrict__ v, const float* __restrict__ g,
                          const float* __restrict__ b) {
    __shared__ float shm[9];
    const float* src;
    __half* dst;
    int which = blockIdx.y;
    long long off = (long long)blockIdx.x * CD;
    if (which == 0)      { src = q + off; dst = g_qn + off; }
    else if (which == 1) { src = k + off; dst = g_kn + off; }
    else                 { src = v + off; dst = g_vn + off; }
    int t = threadIdx.x;
    float x = src[t];
    float mean = block_sum256(x, shm) * (1.0f / CD);
    float d = x - mean;
    float var = block_sum256(d * d, shm) * (1.0f / CD);
    float inv = rsqrtf(var + EPS);
    __half val = __float2half_rn(d * inv * g[t] + b[t]);
    dst[t] = val;
    if (which == 1) {
        // wbias[row] = SCALE * kn(row) . r   (r precomputed before this launch)
        float s = __half2float(val) * g_r[t];
        s = block_sum256(s, shm);
        if (t == 0) g_wbias[blockIdx.x] = ATT_SCALE * s;
    }
}

// ---------------- small prep kernels -----------------------------------------
// fp32 -> half copy of Wq/Wk/Wv into g_wh4[0..2], y selects source
__global__ void f2h_copy3(const float* __restrict__ s0, const float* __restrict__ s1,
                          const float* __restrict__ s2) {
    const float* src = (blockIdx.y == 0) ? s0 : (blockIdx.y == 1) ? s1 : s2;
    __half* dst = g_wh4[blockIdx.y];
    int i = blockIdx.x * 256 + threadIdx.x;
    if (i < CD * INNER) dst[i] = __float2half_rn(src[i]);
}

// Wo [1024,256] -> Wo^T [256,1024] half into g_wh4[3]
__global__ void transpose_wo(const float* __restrict__ src) {
    __shared__ float tile[32][33];
    __half* dst = g_wh4[3];
    int tx = threadIdx.x, ty = threadIdx.y;
    int c0 = blockIdx.x * 32, r0 = blockIdx.y * 32;
    #pragma unroll
    for (int j = 0; j < 4; j++)
        tile[ty + 8 * j][tx] = src[(long long)(r0 + ty + 8 * j) * CD + c0 + tx];
    __syncthreads();
    #pragma unroll
    for (int j = 0; j < 4; j++)
        dst[(long long)(c0 + ty + 8 * j) * INNER + r0 + tx] = __float2half_rn(tile[tx][ty + 8 * j]);
}

// vn [ND,CD] -> vn^T [CD,ND] half, per batch z
__global__ void transpose_h2h(const __half* __restrict__ src, __half* __restrict__ dst,
                              int R, int C, long long sstride, long long dstride) {
    __shared__ __half tile[32][34];
    src += (long long)blockIdx.z * sstride;
    dst += (long long)blockIdx.z * dstride;
    int tx = threadIdx.x, ty = threadIdx.y;
    int c0 = blockIdx.x * 32, r0 = blockIdx.y * 32;
    #pragma unroll
    for (int j = 0; j < 4; j++)
        tile[ty + 8 * j][tx] = src[(long long)(r0 + ty + 8 * j) * C + c0 + tx];
    __syncthreads();
    #pragma unroll
    for (int j = 0; j < 4; j++)
        dst[(long long)(c0 + ty + 8 * j) * R + r0 + tx] = tile[tx][ty + 8 * j];
}

// merged GEMVs: y==0: r[d] = Wk[d,:]·bq ; y==1: rc[c] = bv·Wo[:,c] + bo[c]
__global__ void gemv2(const float* __restrict__ Wk, const float* __restrict__ bq,
                      const float* __restrict__ Wo, const float* __restrict__ bv,
                      const float* __restrict__ bo) {
    __shared__ float shm[9];
    int d = blockIdx.x;
    int t = threadIdx.x;
    float s = 0.f;
    if (blockIdx.y == 0) {
        #pragma unroll
        for (int i = 0; i < 4; i++) {
            int e = t + i * 256;
            s += Wk[(long long)d * INNER + e] * bq[e];
        }
        s = block_sum256(s, shm);
        if (t == 0) g_r[d] = s;
    } else {
        #pragma unroll
        for (int i = 0; i < 4; i++) {
            int e = t + i * 256;
            s += bv[e] * Wo[(long long)e * CD + d];
        }
        s = block_sum256(s, shm);
        if (t == 0) g_rc[d] = s + bo[d];
    }
}

// ---------------- softmax: read fp32 scores, write half probs ----------------
__global__ void softmax_kernel() {
    __shared__ float shm[9];
    const float* row = g_attn + (long long)blockIdx.x * ND;
    __half* rowh = g_attnh + (long long)blockIdx.x * ND;
    int t = threadIdx.x;
    float vals[8];
    float m = -INFINITY;
    #pragma unroll
    for (int i = 0; i < 8; i++) {
        vals[i] = row[t + i * 256];
        m = fmaxf(m, vals[i]);
    }
    m = block_max256(m, shm);
    float s = 0.f;
    #pragma unroll
    for (int i = 0; i < 8; i++) {
        vals[i] = __expf(vals[i] - m);
        s += vals[i];
    }
    s = block_sum256(s, shm);
    float inv = 1.0f / s;
    #pragma unroll
    for (int i = 0; i < 8; i++) rowh[t + i * 256] = __float2half_rn(vals[i] * inv);
}

// ---------------- split-K reduce: y = half(sum of NSPLIT fp32 partials) ------
__global__ void reduce_y() {
    const long long per_batch4 = (long long)ND * CD / 4;
    long long j = (long long)blockIdx.x * 256 + threadIdx.x;
    long long b = j / per_batch4, r = j % per_batch4;
    const float4* p = reinterpret_cast<const float4*>(g_ypart);
    float4 a = p[(b * NSPLIT + 0) * per_batch4 + r];
    float4 c = p[(b * NSPLIT + 1) * per_batch4 + r];
    __half2 h0 = __floats2half2_rn(a.x + c.x, a.y + c.y);
    __half2 h1 = __floats2half2_rn(a.z + c.z, a.w + c.w);
    reinterpret_cast<__half2*>(g_y)[j * 2]     = h0;
    reinterpret_cast<__half2*>(g_y)[j * 2 + 1] = h1;
}

// ---------------- fp16 tensor-core GEMM (NT; 3-stage single-sync pipeline) ---
// C[M,Ntot] = alpha * A[M,K]@B[N,K]^T (+bias). A,B half K-major with lds lda/ldb.
// BIAS_MODE: 0 = none, 1 = per-column fp32 bias (offset batch*strideBias).
// nsplit>1: blockIdx.z = batch*nsplit+split; A/B offset by split*K along K;
//           C indexed by blockIdx.z*strideC (per-split partial buffers).
#define HS 72
#define STG_HALFS (128 * HS)
#define STG_BYTES (2u * STG_HALFS * 2u)      // A+B stage bytes = 36864
#define PIPE_SMEM (3 * (int)STG_BYTES)       // 110592 bytes

template<int BIAS_MODE, bool OUT_HALF>
__global__ __launch_bounds__(256, 2)
void mma_gemm(const __half* __restrict__ A, const __half* __restrict__ B,
              const float* __restrict__ bias, void* __restrict__ CoutV,
              int Ntot, int K, int lda, int ldb, float alpha,
              long long strideA, long long strideB, long long strideC,
              long long strideBias, int nsplit) {
    extern __shared__ __align__(16) __half smem[];   // 3 x (As|Bs)

    const int zb = blockIdx.z / nsplit;
    const int zs = blockIdx.z % nsplit;
    A += (long long)zb * strideA + (long long)zs * K;
    B += (long long)zb * strideB + (long long)zs * K;
    if (BIAS_MODE == 1) bias += (long long)zb * strideBias;

    const int tid  = threadIdx.x;
    const int lane = tid & 31;
    const int w    = tid >> 5;
    const int g    = lane >> 2;
    const int tg   = lane & 3;
    const int warpM = (w >> 1) * 32;
    const int warpN = (w & 1) * 64;
    const long long bm = (long long)blockIdx.y * 128;
    const long long bn = (long long)blockIdx.x * 128;

    const int quad = lane >> 3;
    const int r8   = lane & 7;
    const unsigned a_off0 = ((warpM + (quad & 1) * 8 + r8) * HS + (quad >> 1) * 8) * 2u;
    const unsigned a_off1 = a_off0 + 16u * HS * 2u;
    unsigned b_off[4];
    #pragma unroll
    for (int j = 0; j < 4; j++)
        b_off[j] = ((warpN + (2 * j + (quad >> 1)) * 8 + r8) * HS + (quad & 1) * 8) * 2u;

    const unsigned smem_u = (unsigned)__cvta_generic_to_shared(smem);

    float acc[2][8][4];
    #pragma unroll
    for (int i = 0; i < 2; i++)
        #pragma unroll
        for (int j = 0; j < 8; j++)
            #pragma unroll
            for (int q_ = 0; q_ < 4; q_++) acc[i][j][q_] = 0.f;

    const int nit = K / 64;

    auto fill = [&](int st, int k0) {
        __half* as = smem + st * 2 * STG_HALFS;
        __half* bs = as + STG_HALFS;
        #pragma unroll
        for (int i = 0; i < 4; i++) {
            int idx = i * 256 + tid;
            int r  = idx >> 3;
            int c8 = (idx & 7) * 8;
            cp16(&as[r * HS + c8], A + (bm + r) * (long long)lda + k0 + c8);
        }
        #pragma unroll
        for (int i = 0; i < 4; i++) {
            int idx = i * 256 + tid;
            int r  = idx >> 3;
            int c8 = (idx & 7) * 8;
            cp16(&bs[r * HS + c8], B + (bn + r) * (long long)ldb + k0 + c8);
        }
    };

    fill(0, 0);
    cp_commit();
    fill(1, 64);
    cp_commit();

    for (int it = 0; it < nit; it++) {
        if (it == nit - 1) cp_wait<0>(); else cp_wait<1>();
        __syncthreads();
        if (it + 2 < nit) {
            fill((it + 2) % 3, (it + 2) * 64);
            cp_commit();
        }

        const unsigned as_u = smem_u + (unsigned)(it % 3) * STG_BYTES;
        const unsigned bs_u = as_u + STG_HALFS * 2u;

        #pragma unroll
        for (int ks = 0; ks < 4; ks++) {
            const unsigned kbB = ks * 16u * 2u;
            unsigned af[2][4];
            ldsm_x4(af[0][0], af[0][1], af[0][2], af[0][3], as_u + a_off0 + kbB);
            ldsm_x4(af[1][0], af[1][1], af[1][2], af[1][3], as_u + a_off1 + kbB);
            unsigned bf[8][2];
            #pragma unroll
            for (int j = 0; j < 4; j++)
                ldsm_x4(bf[2 * j][0], bf[2 * j][1], bf[2 * j + 1][0], bf[2 * j + 1][1],
                        bs_u + b_off[j] + kbB);
            #pragma unroll
            for (int mt = 0; mt < 2; mt++)
                #pragma unroll
                for (int nt = 0; nt < 8; nt++)
                    mma_f16(acc[mt][nt], af[mt], bf[nt]);
        }
    }

    // ---- epilogue ----
    #pragma unroll
    for (int mt = 0; mt < 2; mt++) {
        #pragma unroll
        for (int nt = 0; nt < 8; nt++) {
            long long row0 = bm + warpM + mt * 16 + g;
            long long col  = bn + warpN + nt * 8 + tg * 2;
            float b0 = 0.f, b1 = 0.f;
            if (BIAS_MODE == 1) { b0 = bias[col]; b1 = bias[col + 1]; }
            float o00 = acc[mt][nt][0] * alpha + b0;
            float o01 = acc[mt][nt][1] * alpha + b1;
            float o10 = acc[mt][nt][2] * alpha + b0;
            float o11 = acc[mt][nt][3] * alpha + b1;
            if (OUT_HALF) {
                __half* Cout = (__half*)CoutV + (long long)blockIdx.z * strideC;
                *reinterpret_cast<__half2*>(Cout + row0 * Ntot + col) =
                    __floats2half2_rn(o00, o01);
                *reinterpret_cast<__half2*>(Cout + (row0 + 8) * Ntot + col) =
                    __floats2half2_rn(o10, o11);
            } else {
                float* Cout = (float*)CoutV + (long long)blockIdx.z * strideC;
                *reinterpret_cast<float2*>(Cout + row0 * Ntot + col)       = make_float2(o00, o01);
                *reinterpret_cast<float2*>(Cout + (row0 + 8) * Ntot + col) = make_float2(o10, o11);
            }
        }
    }
}

// ---------------- launch ----------------------------------------------------
extern "C" void kernel_launch(void* const* d_in, const int* in_sizes, int n_in,
                              void* d_out, int out_size) {
    const float* q    = (const float*)d_in[0];
    const float* k    = (const float*)d_in[1];
    const float* v    = (const float*)d_in[2];
    const float* ln_g = (const float*)d_in[3];
    const float* ln_b = (const float*)d_in[4];
    const float* Wq   = (const float*)d_in[5];
    const float* bq   = (const float*)d_in[6];
    const float* Wk   = (const float*)d_in[7];
    const float* bk   = (const float*)d_in[8];
    const float* Wv   = (const float*)d_in[9];
    const float* bv   = (const float*)d_in[10];
    const float* Wo   = (const float*)d_in[11];
    const float* bo   = (const float*)d_in[12];
    float* out = (float*)d_out;
    (void)bk;  // cancels under softmax (row-constant term)

    __half *qn, *kn, *vn, *vnt, *t, *y, *attnh, *wh4, *wc;
    float *attn, *ypart, *rcbias, *wbias;
    cudaGetSymbolAddress((void**)&qn, g_qn);
    cudaGetSymbolAddress((void**)&kn, g_kn);
    cudaGetSymbolAddress((void**)&vn, g_vn);
    cudaGetSymbolAddress((void**)&vnt, g_vnt);
    cudaGetSymbolAddress((void**)&t, g_t);
    cudaGetSymbolAddress((void**)&y, g_y);
    cudaGetSymbolAddress((void**)&attn, g_attn);
    cudaGetSymbolAddress((void**)&attnh, g_attnh);
    cudaGetSymbolAddress((void**)&wh4, g_wh4);
    cudaGetSymbolAddress((void**)&wc, g_wc);
    cudaGetSymbolAddress((void**)&ypart, g_ypart);
    cudaGetSymbolAddress((void**)&rcbias, g_rc);
    cudaGetSymbolAddress((void**)&wbias, g_wbias);

    __half* wkh  = wh4 + 1LL * CD * INNER;   // g_wh4[1]
    __half* wqh  = wh4;                      // g_wh4[0]
    __half* wqkt = wc;                       // g_wc[0]
    __half* wvot = wc + (long long)CD * CD;  // g_wc[1]

    cudaFuncSetAttribute(mma_gemm<0, true >, cudaFuncAttributeMaxDynamicSharedMemorySize, PIPE_SMEM);
    cudaFuncSetAttribute(mma_gemm<0, false>, cudaFuncAttributeMaxDynamicSharedMemorySize, PIPE_SMEM);
    cudaFuncSetAttribute(mma_gemm<1, false>, cudaFuncAttributeMaxDynamicSharedMemorySize, PIPE_SMEM);

    // 0. weight preps: halves + Wo^T + merged GEMVs
    f2h_copy3<<<dim3((CD * INNER + 255) / 256, 3), 256>>>(Wq, Wk, Wv);
    transpose_wo<<<dim3(CD / 32, INNER / 32), dim3(32, 8)>>>(Wo);
    gemv2<<<dim3(CD, 2), 256>>>(Wk, bq, Wo, bv, bo);

    // 1. LayerNorm q,k,v (half out); k-branch also writes wbias (needs g_r)
    ln_kernel<<<dim3(ROWS, 3), 256>>>(q, k, v, ln_g, ln_b);

    // 2. Both weight products in one z=2 launch:
    //    z=0: wqkt = Wk @ Wq^T ; z=1: wvot = Wo^T @ Wv^T
    //    A: wh4[1](+2 slots)=wh4[3]; B: wh4[0](+2 slots)=wh4[2]
    {
        dim3 grid(CD / 128, CD / 128, 2);
        mma_gemm<0, true><<<grid, 256, PIPE_SMEM>>>(
            wkh, wqh, nullptr, wqkt, CD, INNER, INNER, INNER, 1.0f,
            2LL * CD * INNER, 2LL * CD * INNER, (long long)CD * CD, 0, 1);
    }

    // 3. vn^T per batch [256,2048]
    transpose_h2h<<<dim3(CD / 32, ND / 32, BD), dim3(32, 8)>>>(
        vn, vnt, ND, CD, (long long)ND * CD, (long long)CD * ND);

    // 4. t = qn @ Wqk  [8192,256] half
    {
        dim3 grid(CD / 128, ROWS / 128, 1);
        mma_gemm<0, true><<<grid, 256, PIPE_SMEM>>>(
            qn, wqkt, nullptr, t, CD, CD, CD, CD, 1.0f, 0, 0, 0, 0, 1);
    }

    // 5. scores = SCALE*(t @ kn^T) + wbias[col], per batch -> fp32
    {
        dim3 grid(ND / 128, ND / 128, BD);
        mma_gemm<1, false><<<grid, 256, PIPE_SMEM>>>(
            t, kn, wbias, attn, ND, CD, CD, CD, ATT_SCALE,
            (long long)ND * CD, (long long)ND * CD, (long long)ND * ND, ND, 1);
    }

    // 6. softmax rows (fp32 in, half out)
    softmax_kernel<<<BD * ND, 256>>>();

    // 7. AV split-K=2: partials[b*2+s] = attnh[b][:, sK:(s+1)K] @ vnt[b][:, sK:(s+1)K]^T
    {
        dim3 grid(CD / 128, ND / 128, BD * NSPLIT);
        mma_gemm<0, false><<<grid, 256, PIPE_SMEM>>>(
            attnh, vnt, nullptr, ypart, CD, ND / NSPLIT, ND, ND, 1.0f,
            (long long)ND * ND, (long long)CD * ND, (long long)ND * CD, 0, NSPLIT);
    }
    // 7b. reduce partials -> y (half)
    reduce_y<<<ROWS * CD / 4 / 256, 256>>>();

    // 8. out = y @ Wvo + (bv Wo + bo)  -> fp32
    {
        dim3 grid(CD / 128, ROWS / 128, 1);
        mma_gemm<1, false><<<grid, 256, PIPE_SMEM>>>(
            y, wvot, rcbias, out, CD, CD, CD, CD, 1.0f, 0, 0, 0, 0, 1);
    }
}

// round 17
// speedup vs baseline: 7.0704x; 1.1467x over previous
#include <cuda_runtime.h>
#include <cuda_fp16.h>
#include <math.h>
#include <stdint.h>

// Problem constants
#define BD 4
#define ND 2048
#define CD 256
#define INNER 1024
#define ROWS (BD*ND)          // 8192
#define EPS 1e-5f
#define ATT_SCALE 0.125f      // 64^-0.5
#define NSPLIT 2              // split-K factor for AV

// ---------------- scratch (device globals; allocation-free rule) -------------
__device__ __half g_qn[ROWS*CD];
__device__ __half g_kn[ROWS*CD];
__device__ __half g_vn[ROWS*CD];
__device__ __half g_vnt[ROWS*CD];               // vn^T per batch [CD, ND]
__device__ __half g_t[ROWS*CD];                 // qn @ Wqk
__device__ __half g_y[ROWS*CD];                 // attn @ vn (reduced)
__device__ float  g_ypart[(long long)NSPLIT*ROWS*CD];  // split-K partials, 16 MB
__device__ float  g_attn[(long long)BD*ND*ND];  // raw fp32 scores, 64 MB
__device__ __half g_attnh[(long long)BD*ND*ND]; // softmaxed probs, half, 32 MB
__device__ __half g_wh4[4][CD*INNER];           // Wq, Wk, Wv, Wo^T (half)
__device__ __half g_wc[2][CD*CD];               // (WqWk^T)^T, (WvWo)^T
__device__ float  g_r[CD];                      // Wk @ bq
__device__ float  g_rc[CD];                     // bv @ Wo + bo
__device__ float  g_wbias[ROWS];                // SCALE * (kn @ r), per key row

// ---------------- helpers ----------------
__device__ __forceinline__ float warp_sum(float v) {
    #pragma unroll
    for (int o = 16; o; o >>= 1) v += __shfl_xor_sync(0xffffffffu, v, o);
    return v;
}
__device__ __forceinline__ float warp_max(float v) {
    #pragma unroll
    for (int o = 16; o; o >>= 1) v = fmaxf(v, __shfl_xor_sync(0xffffffffu, v, o));
    return v;
}
__device__ __forceinline__ float block_sum256(float v, float* shm) {
    v = warp_sum(v);
    int w = threadIdx.x >> 5;
    if ((threadIdx.x & 31) == 0) shm[w] = v;
    __syncthreads();
    if (threadIdx.x == 0) {
        float s = 0.f;
        #pragma unroll
        for (int i = 0; i < 8; i++) s += shm[i];
        shm[8] = s;
    }
    __syncthreads();
    float r = shm[8];
    __syncthreads();
    return r;
}
__device__ __forceinline__ float block_max256(float v, float* shm) {
    v = warp_max(v);
    int w = threadIdx.x >> 5;
    if ((threadIdx.x & 31) == 0) shm[w] = v;
    __syncthreads();
    if (threadIdx.x == 0) {
        float m = shm[0];
        #pragma unroll
        for (int i = 1; i < 8; i++) m = fmaxf(m, shm[i]);
        shm[8] = m;
    }
    __syncthreads();
    float r = shm[8];
    __syncthreads();
    return r;
}

// mma m16n8k16: f32 acc, f16 inputs
__device__ __forceinline__ void mma_f16(float* c, const unsigned* a, const unsigned* b) {
    asm volatile(
        "mma.sync.aligned.m16n8k16.row.col.f32.f16.f16.f32 "
        "{%0,%1,%2,%3}, {%4,%5,%6,%7}, {%8,%9}, {%0,%1,%2,%3};"
        : "+f"(c[0]), "+f"(c[1]), "+f"(c[2]), "+f"(c[3])
        : "r"(a[0]), "r"(a[1]), "r"(a[2]), "r"(a[3]), "r"(b[0]), "r"(b[1]));
}

__device__ __forceinline__ void ldsm_x4(unsigned& r0, unsigned& r1, unsigned& r2, unsigned& r3,
                                        unsigned addr) {
    asm volatile("ldmatrix.sync.aligned.m8n8.x4.shared.b16 {%0,%1,%2,%3}, [%4];"
                 : "=r"(r0), "=r"(r1), "=r"(r2), "=r"(r3) : "r"(addr));
}

__device__ __forceinline__ void cp16(void* smem_dst, const void* gmem_src) {
    unsigned s = (unsigned)__cvta_generic_to_shared(smem_dst);
    asm volatile("cp.async.cg.shared.global [%0], [%1], 16;" :: "r"(s), "l"(gmem_src));
}
__device__ __forceinline__ void cp_commit() {
    asm volatile("cp.async.commit_group;");
}
template<int NN>
__device__ __forceinline__ void cp_wait() {
    asm volatile("cp.async.wait_group %0;" :: "n"(NN));
}

// ---------------- LayerNorm: warp-per-row, shuffle-only reductions -----------
// block = 8 warps = 8 rows; blockIdx.y selects tensor (0=q,1=k,2=v).
// Each lane: 8 elements (2 float4 loads), packed 16B half store.
// k-branch (y==1) also computes wbias[row] = SCALE * (kn_row . g_r).
__global__ void ln_kernel(const float* __restrict__ q, const float* __restrict__ k,
                          const float* __restrict__ v, const float* __restrict__ g,
                          const float* __restrict__ b) {
    const int lane = threadIdx.x & 31;
    const int wid  = threadIdx.x >> 5;
    const long long row = (long long)blockIdx.x * 8 + wid;
    const int which = blockIdx.y;
    const float* src;
    __half* dst;
    if (which == 0)      { src = q; dst = g_qn; }
    else if (which == 1) { src = k; dst = g_kn; }
    else                 { src = v; dst = g_vn; }
    src += row * CD;
    dst += row * CD;

    const int e0 = lane * 8;
    float4 x0 = *reinterpret_cast<const float4*>(src + e0);
    float4 x1 = *reinterpret_cast<const float4*>(src + e0 + 4);

    float s = x0.x + x0.y + x0.z + x0.w + x1.x + x1.y + x1.z + x1.w;
    float mean = warp_sum(s) * (1.0f / CD);

    float d0x = x0.x - mean, d0y = x0.y - mean, d0z = x0.z - mean, d0w = x0.w - mean;
    float d1x = x1.x - mean, d1y = x1.y - mean, d1z = x1.z - mean, d1w = x1.w - mean;
    float vs = d0x * d0x + d0y * d0y + d0z * d0z + d0w * d0w
             + d1x * d1x + d1y * d1y + d1z * d1z + d1w * d1w;
    float var = warp_sum(vs) * (1.0f / CD);
    float inv = rsqrtf(var + EPS);

    float4 gg0 = *reinterpret_cast<const float4*>(g + e0);
    float4 gg1 = *reinterpret_cast<const float4*>(g + e0 + 4);
    float4 bb0 = *reinterpret_cast<const float4*>(b + e0);
    float4 bb1 = *reinterpret_cast<const float4*>(b + e0 + 4);

    float o0 = d0x * inv * gg0.x + bb0.x;
    float o1 = d0y * inv * gg0.y + bb0.y;
    float o2 = d0z * inv * gg0.z + bb0.z;
    float o3 = d0w * inv * gg0.w + bb0.w;
    float o4 = d1x * inv * gg1.x + bb1.x;
    float o5 = d1y * inv * gg1.y + bb1.y;
    float o6 = d1z * inv * gg1.z + bb1.z;
    float o7 = d1w * inv * gg1.w + bb1.w;

    __half2 h[4];
    h[0] = __floats2half2_rn(o0, o1);
    h[1] = __floats2half2_rn(o2, o3);
    h[2] = __floats2half2_rn(o4, o5);
    h[3] = __floats2half2_rn(o6, o7);
    *reinterpret_cast<uint4*>(dst + e0) = *reinterpret_cast<const uint4*>(h);

    if (which == 1) {
        // wbias uses the half-rounded kn values (matches score-GEMM input)
        float4 r0 = *reinterpret_cast<const float4*>(g_r + e0);
        float4 r1 = *reinterpret_cast<const float4*>(g_r + e0 + 4);
        float ws = __half2float(__low2half(h[0]))  * r0.x
                 + __half2float(__high2half(h[0])) * r0.y
                 + __half2float(__low2half(h[1]))  * r0.z
                 + __half2float(__high2half(h[1])) * r0.w
                 + __half2float(__low2half(h[2]))  * r1.x
                 + __half2float(__high2half(h[2])) * r1.y
                 + __half2float(__low2half(h[3]))  * r1.z
                 + __half2float(__high2half(h[3])) * r1.w;
        ws = warp_sum(ws);
        if (lane == 0) g_wbias[row] = ATT_SCALE * ws;
    }
}

// ---------------- small prep kernels -----------------------------------------
// fp32 -> half copy of Wq/Wk/Wv into g_wh4[0..2], y selects source
__global__ void f2h_copy3(const float* __restrict__ s0, const float* __restrict__ s1,
                          const float* __restrict__ s2) {
    const float* src = (blockIdx.y == 0) ? s0 : (blockIdx.y == 1) ? s1 : s2;
    __half* dst = g_wh4[blockIdx.y];
    int i = blockIdx.x * 256 + threadIdx.x;
    if (i < CD * INNER) dst[i] = __float2half_rn(src[i]);
}

// Wo [1024,256] -> Wo^T [256,1024] half into g_wh4[3]
__global__ void transpose_wo(const float* __restrict__ src) {
    __shared__ float tile[32][33];
    __half* dst = g_wh4[3];
    int tx = threadIdx.x, ty = threadIdx.y;
    int c0 = blockIdx.x * 32, r0 = blockIdx.y * 32;
    #pragma unroll
    for (int j = 0; j < 4; j++)
        tile[ty + 8 * j][tx] = src[(long long)(r0 + ty + 8 * j) * CD + c0 + tx];
    __syncthreads();
    #pragma unroll
    for (int j = 0; j < 4; j++)
        dst[(long long)(c0 + ty + 8 * j) * INNER + r0 + tx] = __float2half_rn(tile[tx][ty + 8 * j]);
}

// vn [ND,CD] -> vn^T [CD,ND] half, per batch z
__global__ void transpose_h2h(const __half* __restrict__ src, __half* __restrict__ dst,
                              int R, int C, long long sstride, long long dstride) {
    __shared__ __half tile[32][34];
    src += (long long)blockIdx.z * sstride;
    dst += (long long)blockIdx.z * dstride;
    int tx = threadIdx.x, ty = threadIdx.y;
    int c0 = blockIdx.x * 32, r0 = blockIdx.y * 32;
    #pragma unroll
    for (int j = 0; j < 4; j++)
        tile[ty + 8 * j][tx] = src[(long long)(r0 + ty + 8 * j) * C + c0 + tx];
    __syncthreads();
    #pragma unroll
    for (int j = 0; j < 4; j++)
        dst[(long long)(c0 + ty + 8 * j) * R + r0 + tx] = tile[tx][ty + 8 * j];
}

// merged GEMVs: y==0: r[d] = Wk[d,:]·bq ; y==1: rc[c] = bv·Wo[:,c] + bo[c]
__global__ void gemv2(const float* __restrict__ Wk, const float* __restrict__ bq,
                      const float* __restrict__ Wo, const float* __restrict__ bv,
                      const float* __restrict__ bo) {
    __shared__ float shm[9];
    int d = blockIdx.x;
    int t = threadIdx.x;
    float s = 0.f;
    if (blockIdx.y == 0) {
        #pragma unroll
        for (int i = 0; i < 4; i++) {
            int e = t + i * 256;
            s += Wk[(long long)d * INNER + e] * bq[e];
        }
        s = block_sum256(s, shm);
        if (t == 0) g_r[d] = s;
    } else {
        #pragma unroll
        for (int i = 0; i < 4; i++) {
            int e = t + i * 256;
            s += bv[e] * Wo[(long long)e * CD + d];
        }
        s = block_sum256(s, shm);
        if (t == 0) g_rc[d] = s + bo[d];
    }
}

// ---------------- softmax: read fp32 scores, write half probs ----------------
__global__ void softmax_kernel() {
    __shared__ float shm[9];
    const float* row = g_attn + (long long)blockIdx.x * ND;
    __half* rowh = g_attnh + (long long)blockIdx.x * ND;
    int t = threadIdx.x;
    float vals[8];
    float m = -INFINITY;
    #pragma unroll
    for (int i = 0; i < 8; i++) {
        vals[i] = row[t + i * 256];
        m = fmaxf(m, vals[i]);
    }
    m = block_max256(m, shm);
    float s = 0.f;
    #pragma unroll
    for (int i = 0; i < 8; i++) {
        vals[i] = __expf(vals[i] - m);
        s += vals[i];
    }
    s = block_sum256(s, shm);
    float inv = 1.0f / s;
    #pragma unroll
    for (int i = 0; i < 8; i++) rowh[t + i * 256] = __float2half_rn(vals[i] * inv);
}

// ---------------- split-K reduce: y = half(sum of NSPLIT fp32 partials) ------
__global__ void reduce_y() {
    const long long per_batch4 = (long long)ND * CD / 4;
    long long j = (long long)blockIdx.x * 256 + threadIdx.x;
    long long b = j / per_batch4, r = j % per_batch4;
    const float4* p = reinterpret_cast<const float4*>(g_ypart);
    float4 a = p[(b * NSPLIT + 0) * per_batch4 + r];
    float4 c = p[(b * NSPLIT + 1) * per_batch4 + r];
    __half2 h0 = __floats2half2_rn(a.x + c.x, a.y + c.y);
    __half2 h1 = __floats2half2_rn(a.z + c.z, a.w + c.w);
    reinterpret_cast<__half2*>(g_y)[j * 2]     = h0;
    reinterpret_cast<__half2*>(g_y)[j * 2 + 1] = h1;
}

// ---------------- fp16 tensor-core GEMM (NT; 3-stage single-sync pipeline) ---
// C[M,Ntot] = alpha * A[M,K]@B[N,K]^T (+bias). A,B half K-major with lds lda/ldb.
// BIAS_MODE: 0 = none, 1 = per-column fp32 bias (offset batch*strideBias).
// nsplit>1: blockIdx.z = batch*nsplit+split; A/B offset by split*K along K;
//           C indexed by blockIdx.z*strideC (per-split partial buffers).
#define HS 72
#define STG_HALFS (128 * HS)
#define STG_BYTES (2u * STG_HALFS * 2u)      // A+B stage bytes = 36864
#define PIPE_SMEM (3 * (int)STG_BYTES)       // 110592 bytes

template<int BIAS_MODE, bool OUT_HALF>
__global__ __launch_bounds__(256, 2)
void mma_gemm(const __half* __restrict__ A, const __half* __restrict__ B,
              const float* __restrict__ bias, void* __restrict__ CoutV,
              int Ntot, int K, int lda, int ldb, float alpha,
              long long strideA, long long strideB, long long strideC,
              long long strideBias, int nsplit) {
    extern __shared__ __align__(16) __half smem[];   // 3 x (As|Bs)

    const int zb = blockIdx.z / nsplit;
    const int zs = blockIdx.z % nsplit;
    A += (long long)zb * strideA + (long long)zs * K;
    B += (long long)zb * strideB + (long long)zs * K;
    if (BIAS_MODE == 1) bias += (long long)zb * strideBias;

    const int tid  = threadIdx.x;
    const int lane = tid & 31;
    const int w    = tid >> 5;
    const int g    = lane >> 2;
    const int tg   = lane & 3;
    const int warpM = (w >> 1) * 32;
    const int warpN = (w & 1) * 64;
    const long long bm = (long long)blockIdx.y * 128;
    const long long bn = (long long)blockIdx.x * 128;

    const int quad = lane >> 3;
    const int r8   = lane & 7;
    const unsigned a_off0 = ((warpM + (quad & 1) * 8 + r8) * HS + (quad >> 1) * 8) * 2u;
    const unsigned a_off1 = a_off0 + 16u * HS * 2u;
    unsigned b_off[4];
    #pragma unroll
    for (int j = 0; j < 4; j++)
        b_off[j] = ((warpN + (2 * j + (quad >> 1)) * 8 + r8) * HS + (quad & 1) * 8) * 2u;

    const unsigned smem_u = (unsigned)__cvta_generic_to_shared(smem);

    float acc[2][8][4];
    #pragma unroll
    for (int i = 0; i < 2; i++)
        #pragma unroll
        for (int j = 0; j < 8; j++)
            #pragma unroll
            for (int q_ = 0; q_ < 4; q_++) acc[i][j][q_] = 0.f;

    const int nit = K / 64;

    auto fill = [&](int st, int k0) {
        __half* as = smem + st * 2 * STG_HALFS;
        __half* bs = as + STG_HALFS;
        #pragma unroll
        for (int i = 0; i < 4; i++) {
            int idx = i * 256 + tid;
            int r  = idx >> 3;
            int c8 = (idx & 7) * 8;
            cp16(&as[r * HS + c8], A + (bm + r) * (long long)lda + k0 + c8);
        }
        #pragma unroll
        for (int i = 0; i < 4; i++) {
            int idx = i * 256 + tid;
            int r  = idx >> 3;
            int c8 = (idx & 7) * 8;
            cp16(&bs[r * HS + c8], B + (bn + r) * (long long)ldb + k0 + c8);
        }
    };

    fill(0, 0);
    cp_commit();
    fill(1, 64);
    cp_commit();

    for (int it = 0; it < nit; it++) {
        if (it == nit - 1) cp_wait<0>(); else cp_wait<1>();
        __syncthreads();
        if (it + 2 < nit) {
            fill((it + 2) % 3, (it + 2) * 64);
            cp_commit();
        }

        const unsigned as_u = smem_u + (unsigned)(it % 3) * STG_BYTES;
        const unsigned bs_u = as_u + STG_HALFS * 2u;

        #pragma unroll
        for (int ks = 0; ks < 4; ks++) {
            const unsigned kbB = ks * 16u * 2u;
            unsigned af[2][4];
            ldsm_x4(af[0][0], af[0][1], af[0][2], af[0][3], as_u + a_off0 + kbB);
            ldsm_x4(af[1][0], af[1][1], af[1][2], af[1][3], as_u + a_off1 + kbB);
            unsigned bf[8][2];
            #pragma unroll
            for (int j = 0; j < 4; j++)
                ldsm_x4(bf[2 * j][0], bf[2 * j][1], bf[2 * j + 1][0], bf[2 * j + 1][1],
                        bs_u + b_off[j] + kbB);
            #pragma unroll
            for (int mt = 0; mt < 2; mt++)
                #pragma unroll
                for (int nt = 0; nt < 8; nt++)
                    mma_f16(acc[mt][nt], af[mt], bf[nt]);
        }
    }

    // ---- epilogue ----
    #pragma unroll
    for (int mt = 0; mt < 2; mt++) {
        #pragma unroll
        for (int nt = 0; nt < 8; nt++) {
            long long row0 = bm + warpM + mt * 16 + g;
            long long col  = bn + warpN + nt * 8 + tg * 2;
            float b0 = 0.f, b1 = 0.f;
            if (BIAS_MODE == 1) { b0 = bias[col]; b1 = bias[col + 1]; }
            float o00 = acc[mt][nt][0] * alpha + b0;
            float o01 = acc[mt][nt][1] * alpha + b1;
            float o10 = acc[mt][nt][2] * alpha + b0;
            float o11 = acc[mt][nt][3] * alpha + b1;
            if (OUT_HALF) {
                __half* Cout = (__half*)CoutV + (long long)blockIdx.z * strideC;
                *reinterpret_cast<__half2*>(Cout + row0 * Ntot + col) =
                    __floats2half2_rn(o00, o01);
                *reinterpret_cast<__half2*>(Cout + (row0 + 8) * Ntot + col) =
                    __floats2half2_rn(o10, o11);
            } else {
                float* Cout = (float*)CoutV + (long long)blockIdx.z * strideC;
                *reinterpret_cast<float2*>(Cout + row0 * Ntot + col)       = make_float2(o00, o01);
                *reinterpret_cast<float2*>(Cout + (row0 + 8) * Ntot + col) = make_float2(o10, o11);
            }
        }
    }
}

// ---------------- launch ----------------------------------------------------
extern "C" void kernel_launch(void* const* d_in, const int* in_sizes, int n_in,
                              void* d_out, int out_size) {
    const float* q    = (const float*)d_in[0];
    const float* k    = (const float*)d_in[1];
    const float* v    = (const float*)d_in[2];
    const float* ln_g = (const float*)d_in[3];
    const float* ln_b = (const float*)d_in[4];
    const float* Wq   = (const float*)d_in[5];
    const float* bq   = (const float*)d_in[6];
    const float* Wk   = (const float*)d_in[7];
    const float* bk   = (const float*)d_in[8];
    const float* Wv   = (const float*)d_in[9];
    const float* bv   = (const float*)d_in[10];
    const float* Wo   = (const float*)d_in[11];
    const float* bo   = (const float*)d_in[12];
    float* out = (float*)d_out;
    (void)bk;  // cancels under softmax (row-constant term)

    __half *qn, *kn, *vn, *vnt, *t, *y, *attnh, *wh4, *wc;
    float *attn, *ypart, *rcbias, *wbias;
    cudaGetSymbolAddress((void**)&qn, g_qn);
    cudaGetSymbolAddress((void**)&kn, g_kn);
    cudaGetSymbolAddress((void**)&vn, g_vn);
    cudaGetSymbolAddress((void**)&vnt, g_vnt);
    cudaGetSymbolAddress((void**)&t, g_t);
    cudaGetSymbolAddress((void**)&y, g_y);
    cudaGetSymbolAddress((void**)&attn, g_attn);
    cudaGetSymbolAddress((void**)&attnh, g_attnh);
    cudaGetSymbolAddress((void**)&wh4, g_wh4);
    cudaGetSymbolAddress((void**)&wc, g_wc);
    cudaGetSymbolAddress((void**)&ypart, g_ypart);
    cudaGetSymbolAddress((void**)&rcbias, g_rc);
    cudaGetSymbolAddress((void**)&wbias, g_wbias);

    __half* wkh  = wh4 + 1LL * CD * INNER;   // g_wh4[1]
    __half* wqh  = wh4;                      // g_wh4[0]
    __half* wqkt = wc;                       // g_wc[0]
    __half* wvot = wc + (long long)CD * CD;  // g_wc[1]

    cudaFuncSetAttribute(mma_gemm<0, true >, cudaFuncAttributeMaxDynamicSharedMemorySize, PIPE_SMEM);
    cudaFuncSetAttribute(mma_gemm<0, false>, cudaFuncAttributeMaxDynamicSharedMemorySize, PIPE_SMEM);
    cudaFuncSetAttribute(mma_gemm<1, false>, cudaFuncAttributeMaxDynamicSharedMemorySize, PIPE_SMEM);

    // 0. weight preps: halves + Wo^T + merged GEMVs
    f2h_copy3<<<dim3((CD * INNER + 255) / 256, 3), 256>>>(Wq, Wk, Wv);
    transpose_wo<<<dim3(CD / 32, INNER / 32), dim3(32, 8)>>>(Wo);
    gemv2<<<dim3(CD, 2), 256>>>(Wk, bq, Wo, bv, bo);

    // 1. LayerNorm q,k,v (warp-per-row; k-branch writes wbias, needs g_r)
    ln_kernel<<<dim3(ROWS / 8, 3), 256>>>(q, k, v, ln_g, ln_b);

    // 2. Both weight products in one z=2 launch:
    //    z=0: wqkt = Wk @ Wq^T ; z=1: wvot = Wo^T @ Wv^T
    {
        dim3 grid(CD / 128, CD / 128, 2);
        mma_gemm<0, true><<<grid, 256, PIPE_SMEM>>>(
            wkh, wqh, nullptr, wqkt, CD, INNER, INNER, INNER, 1.0f,
            2LL * CD * INNER, 2LL * CD * INNER, (long long)CD * CD, 0, 1);
    }

    // 3. vn^T per batch [256,2048]
    transpose_h2h<<<dim3(CD / 32, ND / 32, BD), dim3(32, 8)>>>(
        vn, vnt, ND, CD, (long long)ND * CD, (long long)CD * ND);

    // 4. t = qn @ Wqk  [8192,256] half
    {
        dim3 grid(CD / 128, ROWS / 128, 1);
        mma_gemm<0, true><<<grid, 256, PIPE_SMEM>>>(
            qn, wqkt, nullptr, t, CD, CD, CD, CD, 1.0f, 0, 0, 0, 0, 1);
    }

    // 5. scores = SCALE*(t @ kn^T) + wbias[col], per batch -> fp32
    {
        dim3 grid(ND / 128, ND / 128, BD);
        mma_gemm<1, false><<<grid, 256, PIPE_SMEM>>>(
            t, kn, wbias, attn, ND, CD, CD, CD, ATT_SCALE,
            (long long)ND * CD, (long long)ND * CD, (long long)ND * ND, ND, 1);
    }

    // 6. softmax rows (fp32 in, half out)
    softmax_kernel<<<BD * ND, 256>>>();

    // 7. AV split-K=2: partials[b*2+s] = attnh[b][:, sK:(s+1)K] @ vnt[b][:, sK:(s+1)K]^T
    {
        dim3 grid(CD / 128, ND / 128, BD * NSPLIT);
        mma_gemm<0, false><<<grid, 256, PIPE_SMEM>>>(
            attnh, vnt, nullptr, ypart, CD, ND / NSPLIT, ND, ND, 1.0f,
            (long long)ND * ND, (long long)CD * ND, (long long)ND * CD, 0, NSPLIT);
    }
    // 7b. reduce partials -> y (half)
    reduce_y<<<ROWS * CD / 4 / 256, 256>>>();

    // 8. out = y @ Wvo + (bv Wo + bo)  -> fp32
    {
        dim3 grid(CD / 128, ROWS / 128, 1);
        mma_gemm<1, false><<<grid, 256, PIPE_SMEM>>>(
            y, wvot, rcbias, out, CD, CD, CD, CD, 1.0f, 0, 0, 0, 0, 1);
    }
}